// round 2
// baseline (speedup 1.0000x reference)
#include <cuda_runtime.h>
#include <math.h>

#define BB 4
#define CC 256
#define CQ 64
#define NN 4096
#define BN_EPSF 1e-5f

static const size_t NN2 = (size_t)NN * NN;

// Scratch (device globals — no allocation allowed)
__device__ float g_qk[(size_t)BB * CQ * NN];        // 4 MB   qk[b,o,n]
__device__ float g_v[(size_t)BB * CC * NN];         // 16 MB  v[b,c,n] (later scaled by 1/colsum)
__device__ float g_attn[(size_t)BB * NN * NN];      // 268 MB exp(energy)[b,n,m]
__device__ float g_rowsum[BB * NN];                 // softmax denominators (over m)
__device__ float g_colsum[BB * NN];                 // L1 renorm denominators (over n)
__device__ float g_xmr[(size_t)BB * CC * NN];       // 16 MB  x - x_r

// ---------------------------------------------------------------------------
__global__ void k_init() {
    int i = blockIdx.x * blockDim.x + threadIdx.x;
    if (i < BB * NN) { g_rowsum[i] = 0.f; g_colsum[i] = 0.f; }
}

// ---------------------------------------------------------------------------
// out[b,o,n] = sum_c W[o,c] * x[b,c,n] + bias[o]
// 64x64 tile, BK=16, 256 threads, 4x4 microtile
__global__ void __launch_bounds__(256) k_conv(
        const float* __restrict__ W, const float* __restrict__ bias,
        const float* __restrict__ x, float* __restrict__ out, int O) {
    __shared__ float As[16][64];  // [k][o]
    __shared__ float Bs[16][64];  // [k][n]
    int b = blockIdx.z;
    int n0 = blockIdx.x * 64;
    int o0 = blockIdx.y * 64;
    const float* xb = x + (size_t)b * CC * NN;
    int t = threadIdx.x;
    int tx = t & 15, ty = t >> 4;
    float acc[4][4] = {};
    for (int c0 = 0; c0 < CC; c0 += 16) {
        {
            int o = t >> 2;
            int cq = (t & 3) << 2;
            float4 w4 = *reinterpret_cast<const float4*>(W + (o0 + o) * CC + c0 + cq);
            As[cq + 0][o] = w4.x; As[cq + 1][o] = w4.y;
            As[cq + 2][o] = w4.z; As[cq + 3][o] = w4.w;
            int c = t >> 4;
            int nq = (t & 15) << 2;
            *reinterpret_cast<float4*>(&Bs[c][nq]) =
                *reinterpret_cast<const float4*>(xb + (size_t)(c0 + c) * NN + n0 + nq);
        }
        __syncthreads();
        #pragma unroll
        for (int k = 0; k < 16; k++) {
            float a0 = As[k][ty * 4 + 0], a1 = As[k][ty * 4 + 1];
            float a2 = As[k][ty * 4 + 2], a3 = As[k][ty * 4 + 3];
            float b0 = Bs[k][tx * 4 + 0], b1 = Bs[k][tx * 4 + 1];
            float b2 = Bs[k][tx * 4 + 2], b3 = Bs[k][tx * 4 + 3];
            acc[0][0] += a0 * b0; acc[0][1] += a0 * b1; acc[0][2] += a0 * b2; acc[0][3] += a0 * b3;
            acc[1][0] += a1 * b0; acc[1][1] += a1 * b1; acc[1][2] += a1 * b2; acc[1][3] += a1 * b3;
            acc[2][0] += a2 * b0; acc[2][1] += a2 * b1; acc[2][2] += a2 * b2; acc[2][3] += a2 * b3;
            acc[3][0] += a3 * b0; acc[3][1] += a3 * b1; acc[3][2] += a3 * b2; acc[3][3] += a3 * b3;
        }
        __syncthreads();
    }
    #pragma unroll
    for (int i = 0; i < 4; i++) {
        int o = o0 + ty * 4 + i;
        float bv = bias ? bias[o] : 0.f;
        float4 r;
        r.x = acc[i][0] + bv; r.y = acc[i][1] + bv;
        r.z = acc[i][2] + bv; r.w = acc[i][3] + bv;
        *reinterpret_cast<float4*>(out + ((size_t)b * O + o) * NN + n0 + tx * 4) = r;
    }
}

// ---------------------------------------------------------------------------
// attn[b,n,m] = exp( sum_o qk[b,o,n]*qk[b,o,m] ), accumulate rowsum[b,n]
// 64x64 tile, full K=64 staged, 256 threads, 4x4 microtile
__global__ void __launch_bounds__(256) k_gram() {
    __shared__ float As[64][64];  // [o][n]
    __shared__ float Bs[64][64];  // [o][m]
    int b = blockIdx.z;
    int n0 = blockIdx.y * 64;
    int m0 = blockIdx.x * 64;
    const float* qk = g_qk + (size_t)b * CQ * NN;
    int t = threadIdx.x;
    int tx = t & 15, ty = t >> 4;
    #pragma unroll
    for (int r = 0; r < 4; r++) {
        int o = (t >> 4) + r * 16;
        int nq = (t & 15) << 2;
        *reinterpret_cast<float4*>(&As[o][nq]) =
            *reinterpret_cast<const float4*>(qk + (size_t)o * NN + n0 + nq);
        *reinterpret_cast<float4*>(&Bs[o][nq]) =
            *reinterpret_cast<const float4*>(qk + (size_t)o * NN + m0 + nq);
    }
    __syncthreads();
    float acc[4][4] = {};
    #pragma unroll 8
    for (int k = 0; k < 64; k++) {
        float a0 = As[k][ty * 4 + 0], a1 = As[k][ty * 4 + 1];
        float a2 = As[k][ty * 4 + 2], a3 = As[k][ty * 4 + 3];
        float b0 = Bs[k][tx * 4 + 0], b1 = Bs[k][tx * 4 + 1];
        float b2 = Bs[k][tx * 4 + 2], b3 = Bs[k][tx * 4 + 3];
        acc[0][0] += a0 * b0; acc[0][1] += a0 * b1; acc[0][2] += a0 * b2; acc[0][3] += a0 * b3;
        acc[1][0] += a1 * b0; acc[1][1] += a1 * b1; acc[1][2] += a1 * b2; acc[1][3] += a1 * b3;
        acc[2][0] += a2 * b0; acc[2][1] += a2 * b1; acc[2][2] += a2 * b2; acc[2][3] += a2 * b3;
        acc[3][0] += a3 * b0; acc[3][1] += a3 * b1; acc[3][2] += a3 * b2; acc[3][3] += a3 * b3;
    }
    float* arow = g_attn + (size_t)b * NN2;
    #pragma unroll
    for (int i = 0; i < 4; i++) {
        float4 w;
        w.x = __expf(acc[i][0]); w.y = __expf(acc[i][1]);
        w.z = __expf(acc[i][2]); w.w = __expf(acc[i][3]);
        int n = n0 + ty * 4 + i;
        *reinterpret_cast<float4*>(arow + (size_t)n * NN + m0 + tx * 4) = w;
        float s = w.x + w.y + w.z + w.w;
        // reduce across tx (16 consecutive lanes)
        #pragma unroll
        for (int off = 8; off > 0; off >>= 1)
            s += __shfl_down_sync(0xffffffffu, s, off, 16);
        if (tx == 0) atomicAdd(&g_rowsum[b * NN + n], s);
    }
}

// ---------------------------------------------------------------------------
// colsum[b,m] = sum_n attn[b,n,m] / rowsum[b,n]   (split over n-chunks, atomic)
__global__ void __launch_bounds__(256) k_colsum() {
    __shared__ float inv[256];
    int b = blockIdx.z;
    int m = blockIdx.x * 256 + threadIdx.x;
    int nbase = blockIdx.y * 256;
    inv[threadIdx.x] = 1.0f / g_rowsum[b * NN + nbase + threadIdx.x];
    __syncthreads();
    const float* ab = g_attn + (size_t)b * NN2;
    float s = 0.f;
    #pragma unroll 4
    for (int i = 0; i < 256; i++)
        s += ab[(size_t)(nbase + i) * NN + m] * inv[i];
    atomicAdd(&g_colsum[b * NN + m], s);
}

// ---------------------------------------------------------------------------
// v[b,c,m] /= (1e-9 + colsum[b,m])
__global__ void __launch_bounds__(256) k_scalev() {
    size_t i = (size_t)blockIdx.x * 256 + threadIdx.x;
    int m = (int)(i & (NN - 1));
    int b = (int)(i >> 20);   // CC*NN = 2^20
    g_v[i] = g_v[i] / (1e-9f + g_colsum[b * NN + m]);
}

// ---------------------------------------------------------------------------
// xmr[b,c,n] = x[b,c,n] - (1/rowsum[b,n]) * sum_m attn[b,n,m] * vs[b,c,m]
// 128x128 tile (c x n), BK=16, 256 threads, 8x8 microtile. 68.7 GFLOP.
__global__ void __launch_bounds__(256) k_xr(const float* __restrict__ x) {
    __shared__ float As[16][128];  // attn: [m][n]
    __shared__ float Bs[16][128];  // vs:   [m][c]
    int b = blockIdx.z;
    int n0 = blockIdx.x * 128;
    int c0 = blockIdx.y * 128;
    const float* ab = g_attn + (size_t)b * NN2;
    const float* vb = g_v + (size_t)b * CC * NN;
    int t = threadIdx.x;
    int tx = t & 15, ty = t >> 4;
    float acc[8][8] = {};
    for (int m0 = 0; m0 < NN; m0 += 16) {
        #pragma unroll
        for (int r = 0; r < 2; r++) {
            int idx = t * 2 + r;        // 0..511
            int n = idx >> 2;           // 0..127
            int mq = (idx & 3) << 2;    // 0,4,8,12
            float4 a4 = *reinterpret_cast<const float4*>(ab + (size_t)(n0 + n) * NN + m0 + mq);
            As[mq + 0][n] = a4.x; As[mq + 1][n] = a4.y;
            As[mq + 2][n] = a4.z; As[mq + 3][n] = a4.w;
            float4 v4 = *reinterpret_cast<const float4*>(vb + (size_t)(c0 + n) * NN + m0 + mq);
            Bs[mq + 0][n] = v4.x; Bs[mq + 1][n] = v4.y;
            Bs[mq + 2][n] = v4.z; Bs[mq + 3][n] = v4.w;
        }
        __syncthreads();
        #pragma unroll
        for (int k = 0; k < 16; k++) {
            float ra[8], rb[8];
            #pragma unroll
            for (int j = 0; j < 4; j++) {
                ra[j]     = As[k][tx * 4 + j];
                ra[j + 4] = As[k][64 + tx * 4 + j];
                rb[j]     = Bs[k][ty * 4 + j];
                rb[j + 4] = Bs[k][64 + ty * 4 + j];
            }
            #pragma unroll
            for (int i = 0; i < 8; i++)
                #pragma unroll
                for (int j = 0; j < 8; j++)
                    acc[i][j] += rb[i] * ra[j];
        }
        __syncthreads();
    }
    const float* xb = x + (size_t)b * CC * NN;
    float* ob = g_xmr + (size_t)b * CC * NN;
    float invr[8];
    #pragma unroll
    for (int j = 0; j < 8; j++) {
        int n = n0 + ((j < 4) ? (tx * 4 + j) : (64 + tx * 4 + j - 4));
        invr[j] = 1.0f / g_rowsum[b * NN + n];
    }
    #pragma unroll
    for (int i = 0; i < 8; i++) {
        int c = c0 + ((i < 4) ? (ty * 4 + i) : (64 + ty * 4 + i - 4));
        #pragma unroll
        for (int half = 0; half < 2; half++) {
            int n = n0 + half * 64 + tx * 4;
            size_t off = (size_t)c * NN + n;
            float4 xv = *reinterpret_cast<const float4*>(xb + off);
            float4 r;
            r.x = xv.x - acc[i][half * 4 + 0] * invr[half * 4 + 0];
            r.y = xv.y - acc[i][half * 4 + 1] * invr[half * 4 + 1];
            r.z = xv.z - acc[i][half * 4 + 2] * invr[half * 4 + 2];
            r.w = xv.w - acc[i][half * 4 + 3] * invr[half * 4 + 3];
            *reinterpret_cast<float4*>(ob + off) = r;
        }
    }
}

// ---------------------------------------------------------------------------
// t = wt * xmr + bt ; bn inference ; out = x + relu(bn)
__global__ void __launch_bounds__(256) k_final(
        const float* __restrict__ W, const float* __restrict__ bias,
        const float* __restrict__ x,
        const float* __restrict__ gamma, const float* __restrict__ beta,
        const float* __restrict__ mean,  const float* __restrict__ var,
        float* __restrict__ out) {
    __shared__ float As[16][64];
    __shared__ float Bs[16][64];
    int b = blockIdx.z;
    int n0 = blockIdx.x * 64;
    int o0 = blockIdx.y * 64;
    const float* ib = g_xmr + (size_t)b * CC * NN;
    int t = threadIdx.x;
    int tx = t & 15, ty = t >> 4;
    float acc[4][4] = {};
    for (int c0 = 0; c0 < CC; c0 += 16) {
        {
            int o = t >> 2;
            int cq = (t & 3) << 2;
            float4 w4 = *reinterpret_cast<const float4*>(W + (o0 + o) * CC + c0 + cq);
            As[cq + 0][o] = w4.x; As[cq + 1][o] = w4.y;
            As[cq + 2][o] = w4.z; As[cq + 3][o] = w4.w;
            int c = t >> 4;
            int nq = (t & 15) << 2;
            *reinterpret_cast<float4*>(&Bs[c][nq]) =
                *reinterpret_cast<const float4*>(ib + (size_t)(c0 + c) * NN + n0 + nq);
        }
        __syncthreads();
        #pragma unroll
        for (int k = 0; k < 16; k++) {
            float a0 = As[k][ty * 4 + 0], a1 = As[k][ty * 4 + 1];
            float a2 = As[k][ty * 4 + 2], a3 = As[k][ty * 4 + 3];
            float b0 = Bs[k][tx * 4 + 0], b1 = Bs[k][tx * 4 + 1];
            float b2 = Bs[k][tx * 4 + 2], b3 = Bs[k][tx * 4 + 3];
            acc[0][0] += a0 * b0; acc[0][1] += a0 * b1; acc[0][2] += a0 * b2; acc[0][3] += a0 * b3;
            acc[1][0] += a1 * b0; acc[1][1] += a1 * b1; acc[1][2] += a1 * b2; acc[1][3] += a1 * b3;
            acc[2][0] += a2 * b0; acc[2][1] += a2 * b1; acc[2][2] += a2 * b2; acc[2][3] += a2 * b3;
            acc[3][0] += a3 * b0; acc[3][1] += a3 * b1; acc[3][2] += a3 * b2; acc[3][3] += a3 * b3;
        }
        __syncthreads();
    }
    const float* xb = x + (size_t)b * CC * NN;
    #pragma unroll
    for (int i = 0; i < 4; i++) {
        int o = o0 + ty * 4 + i;
        float s  = gamma[o] * rsqrtf(var[o] + BN_EPSF);
        float sh = beta[o] - mean[o] * s;
        float bt = bias[o];
        size_t off = ((size_t)b * CC + o) * NN + n0 + tx * 4;
        float4 xv = *reinterpret_cast<const float4*>(xb + (size_t)o * NN + n0 + tx * 4);
        float4 r;
        r.x = xv.x + fmaxf((acc[i][0] + bt) * s + sh, 0.f);
        r.y = xv.y + fmaxf((acc[i][1] + bt) * s + sh, 0.f);
        r.z = xv.z + fmaxf((acc[i][2] + bt) * s + sh, 0.f);
        r.w = xv.w + fmaxf((acc[i][3] + bt) * s + sh, 0.f);
        *reinterpret_cast<float4*>(out + off) = r;
    }
}

// ---------------------------------------------------------------------------
extern "C" void kernel_launch(void* const* d_in, const int* in_sizes, int n_in,
                              void* d_out, int out_size) {
    const float* x     = (const float*)d_in[0];
    const float* wq    = (const float*)d_in[1];
    const float* wv    = (const float*)d_in[2];
    const float* bv    = (const float*)d_in[3];
    const float* wt    = (const float*)d_in[4];
    const float* bt    = (const float*)d_in[5];
    const float* gamma = (const float*)d_in[6];
    const float* beta  = (const float*)d_in[7];
    const float* rmean = (const float*)d_in[8];
    const float* rvar  = (const float*)d_in[9];
    float* out = (float*)d_out;

    float *qk_p = nullptr, *v_p = nullptr;
    cudaGetSymbolAddress((void**)&qk_p, g_qk);
    cudaGetSymbolAddress((void**)&v_p, g_v);

    k_init<<<(BB * NN + 255) / 256, 256>>>();
    // qk = wq * x   (q and k share this projection)
    k_conv<<<dim3(NN / 64, CQ / 64, BB), 256>>>(wq, nullptr, x, qk_p, CQ);
    // v = wv * x + bv
    k_conv<<<dim3(NN / 64, CC / 64, BB), 256>>>(wv, bv, x, v_p, CC);
    // exp(energy) + rowsums
    k_gram<<<dim3(NN / 64, NN / 64, BB), 256>>>();
    // colsums of normalized attn
    k_colsum<<<dim3(NN / 256, NN / 256, BB), 256>>>();
    // fold L1 renorm into v
    k_scalev<<<(BB * CC * NN) / 256, 256>>>();
    // x - x_r
    k_xr<<<dim3(NN / 128, CC / 128, BB), 256>>>(x);
    // wt conv + BN + relu + residual
    k_final<<<dim3(NN / 64, CC / 64, BB), 256>>>(wt, bt, x, gamma, beta, rmean, rvar, out);
}

// round 6
// speedup vs baseline: 1.8960x; 1.8960x over previous
#include <cuda_runtime.h>
#include <cuda_bf16.h>
#include <mma.h>
#include <cstdint>
#include <math.h>

using namespace nvcuda;

#define BB 4
#define CC 256
#define CQ 64
#define NN 4096
#define BN_EPSF 1e-5f

static const size_t NN2 = (size_t)NN * NN;

// Scratch (device globals — no allocation allowed)
__device__ __nv_bfloat16 g_qkh[(size_t)BB * NN * CQ];   // 2 MB  qk hi  [b][n][o]
__device__ __nv_bfloat16 g_qkl[(size_t)BB * NN * CQ];   // 2 MB  qk lo
__device__ float         g_v[(size_t)BB * CC * NN];     // 16 MB v[b,c,n]
__device__ __nv_bfloat16 g_vh[(size_t)BB * CC * NN];    // 8 MB  vs hi [b][c][m]
__device__ __nv_bfloat16 g_vl[(size_t)BB * CC * NN];    // 8 MB  vs lo
__device__ __nv_bfloat16 g_ah[(size_t)BB * NN * NN];    // 134 MB exp(energy) hi [b][n][m]
__device__ __nv_bfloat16 g_al[(size_t)BB * NN * NN];    // 134 MB exp(energy) lo
__device__ float         g_rowsum[BB * NN];
__device__ float         g_colsum[BB * NN];
__device__ float         g_xr[(size_t)BB * CC * NN];    // 16 MB raw x_r sums

// ===========================================================================
__device__ __forceinline__ uint32_t smem_u32(const void* p) {
    uint32_t a;
    asm("{ .reg .u64 t; cvta.to.shared.u64 t, %1; cvt.u32.u64 %0, t; }" : "=r"(a) : "l"(p));
    return a;
}
__device__ __forceinline__ void cp16(uint32_t dst, const void* src) {
    asm volatile("cp.async.cg.shared.global [%0], [%1], 16;" :: "r"(dst), "l"(src) : "memory");
}
__device__ __forceinline__ void cp_commit() {
    asm volatile("cp.async.commit_group;" ::: "memory");
}
template <int N> __device__ __forceinline__ void cp_wait() {
    asm volatile("cp.async.wait_group %0;" :: "n"(N) : "memory");
}

// ===========================================================================
__global__ void k_init() {
    int i = blockIdx.x * blockDim.x + threadIdx.x;
    if (i < BB * NN) { g_rowsum[i] = 0.f; g_colsum[i] = 0.f; }
}

// ---------------------------------------------------------------------------
// out[b,o,n] = sum_c W[o,c] * x[b,c,n] + bias[o]   (v projection, fp32 SIMT)
__global__ void __launch_bounds__(256) k_conv(
        const float* __restrict__ W, const float* __restrict__ bias,
        const float* __restrict__ x, float* __restrict__ out, int O) {
    __shared__ float As[16][64];
    __shared__ float Bs[16][64];
    int b = blockIdx.z;
    int n0 = blockIdx.x * 64;
    int o0 = blockIdx.y * 64;
    const float* xb = x + (size_t)b * CC * NN;
    int t = threadIdx.x;
    int tx = t & 15, ty = t >> 4;
    float acc[4][4] = {};
    for (int c0 = 0; c0 < CC; c0 += 16) {
        {
            int o = t >> 2;
            int cq = (t & 3) << 2;
            float4 w4 = *reinterpret_cast<const float4*>(W + (o0 + o) * CC + c0 + cq);
            As[cq + 0][o] = w4.x; As[cq + 1][o] = w4.y;
            As[cq + 2][o] = w4.z; As[cq + 3][o] = w4.w;
            int c = t >> 4;
            int nq = (t & 15) << 2;
            *reinterpret_cast<float4*>(&Bs[c][nq]) =
                *reinterpret_cast<const float4*>(xb + (size_t)(c0 + c) * NN + n0 + nq);
        }
        __syncthreads();
        #pragma unroll
        for (int k = 0; k < 16; k++) {
            float a0 = As[k][ty * 4 + 0], a1 = As[k][ty * 4 + 1];
            float a2 = As[k][ty * 4 + 2], a3 = As[k][ty * 4 + 3];
            float b0 = Bs[k][tx * 4 + 0], b1 = Bs[k][tx * 4 + 1];
            float b2 = Bs[k][tx * 4 + 2], b3 = Bs[k][tx * 4 + 3];
            acc[0][0] += a0 * b0; acc[0][1] += a0 * b1; acc[0][2] += a0 * b2; acc[0][3] += a0 * b3;
            acc[1][0] += a1 * b0; acc[1][1] += a1 * b1; acc[1][2] += a1 * b2; acc[1][3] += a1 * b3;
            acc[2][0] += a2 * b0; acc[2][1] += a2 * b1; acc[2][2] += a2 * b2; acc[2][3] += a2 * b3;
            acc[3][0] += a3 * b0; acc[3][1] += a3 * b1; acc[3][2] += a3 * b2; acc[3][3] += a3 * b3;
        }
        __syncthreads();
    }
    #pragma unroll
    for (int i = 0; i < 4; i++) {
        int o = o0 + ty * 4 + i;
        float bv = bias ? bias[o] : 0.f;
        float4 r;
        r.x = acc[i][0] + bv; r.y = acc[i][1] + bv;
        r.z = acc[i][2] + bv; r.w = acc[i][3] + bv;
        *reinterpret_cast<float4*>(out + ((size_t)b * O + o) * NN + n0 + tx * 4) = r;
    }
}

// ---------------------------------------------------------------------------
// qk projection, written TRANSPOSED [b][n][o] as bf16 hi + residual lo
__global__ void __launch_bounds__(256) k_convq(
        const float* __restrict__ W, const float* __restrict__ x) {
    __shared__ float As[16][64];
    __shared__ float Bs[16][64];
    int b = blockIdx.z;
    int n0 = blockIdx.x * 64;
    const float* xb = x + (size_t)b * CC * NN;
    int t = threadIdx.x;
    int tx = t & 15, ty = t >> 4;
    float acc[4][4] = {};
    for (int c0 = 0; c0 < CC; c0 += 16) {
        {
            int o = t >> 2;
            int cq = (t & 3) << 2;
            float4 w4 = *reinterpret_cast<const float4*>(W + o * CC + c0 + cq);
            As[cq + 0][o] = w4.x; As[cq + 1][o] = w4.y;
            As[cq + 2][o] = w4.z; As[cq + 3][o] = w4.w;
            int c = t >> 4;
            int nq = (t & 15) << 2;
            *reinterpret_cast<float4*>(&Bs[c][nq]) =
                *reinterpret_cast<const float4*>(xb + (size_t)(c0 + c) * NN + n0 + nq);
        }
        __syncthreads();
        #pragma unroll
        for (int k = 0; k < 16; k++) {
            float a0 = As[k][ty * 4 + 0], a1 = As[k][ty * 4 + 1];
            float a2 = As[k][ty * 4 + 2], a3 = As[k][ty * 4 + 3];
            float b0 = Bs[k][tx * 4 + 0], b1 = Bs[k][tx * 4 + 1];
            float b2 = Bs[k][tx * 4 + 2], b3 = Bs[k][tx * 4 + 3];
            acc[0][0] += a0 * b0; acc[0][1] += a0 * b1; acc[0][2] += a0 * b2; acc[0][3] += a0 * b3;
            acc[1][0] += a1 * b0; acc[1][1] += a1 * b1; acc[1][2] += a1 * b2; acc[1][3] += a1 * b3;
            acc[2][0] += a2 * b0; acc[2][1] += a2 * b1; acc[2][2] += a2 * b2; acc[2][3] += a2 * b3;
            acc[3][0] += a3 * b0; acc[3][1] += a3 * b1; acc[3][2] += a3 * b2; acc[3][3] += a3 * b3;
        }
        __syncthreads();
    }
    #pragma unroll
    for (int i = 0; i < 4; i++) {
        int o = ty * 4 + i;
        #pragma unroll
        for (int j = 0; j < 4; j++) {
            int n = n0 + tx * 4 + j;
            float v = acc[i][j];
            __nv_bfloat16 h = __float2bfloat16(v);
            size_t off = ((size_t)b * NN + n) * CQ + o;
            g_qkh[off] = h;
            g_qkl[off] = __float2bfloat16(v - __bfloat162float(h));
        }
    }
}

// ---------------------------------------------------------------------------
// Gram via wmma bf16 3-term split: attn = exp(qk[n]·qk[m]); hi/lo bf16 store + rowsum.
// CTA 128n x 256m, K=64. smem: operands (110.6KB) then reused for C staging (139.3KB).
#define GPITCH 72
#define GRAM_SMEM 139264
__global__ void __launch_bounds__(256) k_gram_wmma() {
    extern __shared__ __align__(16) char smem[];
    int t = threadIdx.x, w = t >> 5, l = t & 31;
    int m0 = blockIdx.x * 256;
    int n0 = blockIdx.y * 128;
    int b = blockIdx.z;

    __nv_bfloat16* sAh = reinterpret_cast<__nv_bfloat16*>(smem);
    __nv_bfloat16* sAl = reinterpret_cast<__nv_bfloat16*>(smem + 18432);
    __nv_bfloat16* sBh = reinterpret_cast<__nv_bfloat16*>(smem + 36864);
    __nv_bfloat16* sBl = reinterpret_cast<__nv_bfloat16*>(smem + 73728);

    const __nv_bfloat16* qh = g_qkh + (size_t)b * NN * CQ;
    const __nv_bfloat16* ql = g_qkl + (size_t)b * NN * CQ;

    // Stage operands: 768 rows of 128B (8 x 16B chunks)
    #pragma unroll
    for (int i = 0; i < 24; i++) {
        int idx = i * 256 + t;
        int row = idx >> 3, q = idx & 7;
        const __nv_bfloat16* src;
        __nv_bfloat16* dst;
        if (row < 128)      { src = qh + (size_t)(n0 + row) * CQ;        dst = sAh + row * GPITCH; }
        else if (row < 256) { src = ql + (size_t)(n0 + row - 128) * CQ;  dst = sAl + (row - 128) * GPITCH; }
        else if (row < 512) { src = qh + (size_t)(m0 + row - 256) * CQ;  dst = sBh + (row - 256) * GPITCH; }
        else                { src = ql + (size_t)(m0 + row - 512) * CQ;  dst = sBl + (row - 512) * GPITCH; }
        *reinterpret_cast<float4*>(dst + q * 8) = *reinterpret_cast<const float4*>(src + q * 8);
    }
    __syncthreads();

    int wn = w >> 2;   // 0..1  (n half)
    int wm = w & 3;    // 0..3  (m quarter)

    wmma::fragment<wmma::accumulator, 16, 16, 16, float> acc[4][4];
    #pragma unroll
    for (int i = 0; i < 4; i++)
        #pragma unroll
        for (int j = 0; j < 4; j++) wmma::fill_fragment(acc[i][j], 0.0f);

    #pragma unroll
    for (int kk = 0; kk < 4; kk++) {
        wmma::fragment<wmma::matrix_a, 16, 16, 16, __nv_bfloat16, wmma::row_major> ah[4], al[4];
        #pragma unroll
        for (int i = 0; i < 4; i++) {
            wmma::load_matrix_sync(ah[i], sAh + (wn * 64 + i * 16) * GPITCH + kk * 16, GPITCH);
            wmma::load_matrix_sync(al[i], sAl + (wn * 64 + i * 16) * GPITCH + kk * 16, GPITCH);
        }
        #pragma unroll
        for (int j = 0; j < 4; j++) {
            wmma::fragment<wmma::matrix_b, 16, 16, 16, __nv_bfloat16, wmma::col_major> bh, bl;
            wmma::load_matrix_sync(bh, sBh + (wm * 64 + j * 16) * GPITCH + kk * 16, GPITCH);
            wmma::load_matrix_sync(bl, sBl + (wm * 64 + j * 16) * GPITCH + kk * 16, GPITCH);
            #pragma unroll
            for (int i = 0; i < 4; i++) {
                wmma::mma_sync(acc[i][j], ah[i], bh, acc[i][j]);
                wmma::mma_sync(acc[i][j], ah[i], bl, acc[i][j]);
                wmma::mma_sync(acc[i][j], al[i], bh, acc[i][j]);
            }
        }
    }
    __syncthreads();  // operands dead; reuse smem for C staging

    float* Cst = reinterpret_cast<float*>(smem) + w * 4352;  // 64 x 68
    #pragma unroll
    for (int i = 0; i < 4; i++)
        #pragma unroll
        for (int j = 0; j < 4; j++)
            wmma::store_matrix_sync(Cst + (i * 16) * 68 + j * 16, acc[i][j], 68, wmma::mem_row_major);
    __syncwarp();

    // exp + bf16 hi/lo store + rowsum
    __nv_bfloat16* oh = g_ah + (size_t)b * NN2;
    __nv_bfloat16* ol = g_al + (size_t)b * NN2;
    for (int r = 0; r < 64; r++) {
        int n = n0 + wn * 64 + r;
        float e0 = __expf(Cst[r * 68 + 2 * l + 0]);
        float e1 = __expf(Cst[r * 68 + 2 * l + 1]);
        __nv_bfloat16 h0 = __float2bfloat16(e0);
        __nv_bfloat16 h1 = __float2bfloat16(e1);
        __nv_bfloat162 hh; hh.x = h0; hh.y = h1;
        __nv_bfloat162 ll;
        ll.x = __float2bfloat16(e0 - __bfloat162float(h0));
        ll.y = __float2bfloat16(e1 - __bfloat162float(h1));
        size_t off = (size_t)n * NN + m0 + wm * 64 + 2 * l;
        *reinterpret_cast<__nv_bfloat162*>(oh + off) = hh;
        *reinterpret_cast<__nv_bfloat162*>(ol + off) = ll;
        float s = e0 + e1;
        #pragma unroll
        for (int o2 = 16; o2 > 0; o2 >>= 1) s += __shfl_down_sync(0xffffffffu, s, o2);
        if (l == 0) atomicAdd(&g_rowsum[b * NN + n], s);
    }
}

// ---------------------------------------------------------------------------
// colsum[b,m] = sum_n (attn_hi + attn_lo)[n,m] / rowsum[n]
__global__ void __launch_bounds__(256) k_colsum() {
    __shared__ float inv[256];
    int b = blockIdx.z;
    int m = blockIdx.x * 256 + threadIdx.x;
    int nbase = blockIdx.y * 256;
    inv[threadIdx.x] = 1.0f / g_rowsum[b * NN + nbase + threadIdx.x];
    __syncthreads();
    const __nv_bfloat16* ah = g_ah + (size_t)b * NN2;
    const __nv_bfloat16* al = g_al + (size_t)b * NN2;
    float s = 0.f;
    #pragma unroll 4
    for (int i = 0; i < 256; i++) {
        size_t off = (size_t)(nbase + i) * NN + m;
        s += (__bfloat162float(ah[off]) + __bfloat162float(al[off])) * inv[i];
    }
    atomicAdd(&g_colsum[b * NN + m], s);
}

// ---------------------------------------------------------------------------
// vs = v/(1e-9+colsum[m]) -> bf16 hi/lo
__global__ void __launch_bounds__(256) k_splitv() {
    size_t i = (size_t)blockIdx.x * 256 + threadIdx.x;
    int m = (int)(i & (NN - 1));
    int b = (int)(i >> 20);
    float vs = g_v[i] / (1e-9f + g_colsum[b * NN + m]);
    __nv_bfloat16 h = __float2bfloat16(vs);
    g_vh[i] = h;
    g_vl[i] = __float2bfloat16(vs - __bfloat162float(h));
}

// ---------------------------------------------------------------------------
// x_r raw sums via wmma bf16 3-term split.
// CTA 256c x 128n, BK=32, 2-stage cp.async. Stage: Vh|Vl(256x40) Ah|Al(128x40) = 61440 B.
#define XPITCH 40
#define XSTAGE 61440
#define XR_SMEM (2 * XSTAGE)
__global__ void __launch_bounds__(256) k_xr_wmma() {
    extern __shared__ __align__(16) char smem[];
    const uint32_t sb = smem_u32(smem);
    int t = threadIdx.x, w = t >> 5;
    int n0 = blockIdx.x * 128;
    int b = blockIdx.y;

    const __nv_bfloat16* vh = g_vh + (size_t)b * CC * NN;
    const __nv_bfloat16* vl = g_vl + (size_t)b * CC * NN;
    const __nv_bfloat16* ahp = g_ah + (size_t)b * NN2 + (size_t)n0 * NN;
    const __nv_bfloat16* alp = g_al + (size_t)b * NN2 + (size_t)n0 * NN;

    auto issue = [&](int kc) {
        uint32_t base = sb + (uint32_t)(kc & 1) * XSTAGE;
        int koff = kc * 32;
        #pragma unroll
        for (int i = 0; i < 12; i++) {
            int idx = i * 256 + t;
            int row = idx >> 2, q = idx & 3;
            if (row < 256)
                cp16(base + row * 80 + q * 16, vh + (size_t)row * NN + koff + q * 8);
            else if (row < 512)
                cp16(base + 20480 + (row - 256) * 80 + q * 16, vl + (size_t)(row - 256) * NN + koff + q * 8);
            else if (row < 640)
                cp16(base + 40960 + (row - 512) * 80 + q * 16, ahp + (size_t)(row - 512) * NN + koff + q * 8);
            else
                cp16(base + 51200 + (row - 640) * 80 + q * 16, alp + (size_t)(row - 640) * NN + koff + q * 8);
        }
        cp_commit();
    };

    int wc = w >> 1;   // 0..3  (c quarter)
    int wn = w & 1;    // 0..1  (n half)

    wmma::fragment<wmma::accumulator, 16, 16, 16, float> acc[4][4];
    #pragma unroll
    for (int i = 0; i < 4; i++)
        #pragma unroll
        for (int j = 0; j < 4; j++) wmma::fill_fragment(acc[i][j], 0.0f);

    issue(0); issue(1);

    for (int kc = 0; kc < 128; kc++) {
        if (kc < 127) cp_wait<1>(); else cp_wait<0>();
        __syncthreads();
        const char* stg = smem + (kc & 1) * XSTAGE;
        const __nv_bfloat16* sVh = reinterpret_cast<const __nv_bfloat16*>(stg);
        const __nv_bfloat16* sVl = reinterpret_cast<const __nv_bfloat16*>(stg + 20480);
        const __nv_bfloat16* sAh = reinterpret_cast<const __nv_bfloat16*>(stg + 40960);
        const __nv_bfloat16* sAl = reinterpret_cast<const __nv_bfloat16*>(stg + 51200);
        #pragma unroll
        for (int kk = 0; kk < 32; kk += 16) {
            wmma::fragment<wmma::matrix_a, 16, 16, 16, __nv_bfloat16, wmma::row_major> avh[4], avl[4];
            #pragma unroll
            for (int i = 0; i < 4; i++) {
                wmma::load_matrix_sync(avh[i], sVh + (wc * 64 + i * 16) * XPITCH + kk, XPITCH);
                wmma::load_matrix_sync(avl[i], sVl + (wc * 64 + i * 16) * XPITCH + kk, XPITCH);
            }
            #pragma unroll
            for (int j = 0; j < 4; j++) {
                wmma::fragment<wmma::matrix_b, 16, 16, 16, __nv_bfloat16, wmma::col_major> bh, bl;
                wmma::load_matrix_sync(bh, sAh + (wn * 64 + j * 16) * XPITCH + kk, XPITCH);
                wmma::load_matrix_sync(bl, sAl + (wn * 64 + j * 16) * XPITCH + kk, XPITCH);
                #pragma unroll
                for (int i = 0; i < 4; i++) {
                    wmma::mma_sync(acc[i][j], avh[i], bh, acc[i][j]);
                    wmma::mma_sync(acc[i][j], avh[i], bl, acc[i][j]);
                    wmma::mma_sync(acc[i][j], avl[i], bh, acc[i][j]);
                }
            }
        }
        __syncthreads();
        if (kc + 2 < 128) issue(kc + 2);
    }

    // Store raw sums (scaled by 1/rowsum later in k_final)
    #pragma unroll
    for (int i = 0; i < 4; i++)
        #pragma unroll
        for (int j = 0; j < 4; j++)
            wmma::store_matrix_sync(
                g_xr + ((size_t)b * CC + wc * 64 + i * 16) * NN + n0 + wn * 64 + j * 16,
                acc[i][j], NN, wmma::mem_row_major);
}

// ---------------------------------------------------------------------------
// t = wt * (x - xr_raw/rowsum) + bt ; BN inference ; out = x + relu(bn)
__global__ void __launch_bounds__(256) k_final(
        const float* __restrict__ W, const float* __restrict__ bias,
        const float* __restrict__ x,
        const float* __restrict__ gamma, const float* __restrict__ beta,
        const float* __restrict__ mean,  const float* __restrict__ var,
        float* __restrict__ out) {
    __shared__ float As[16][64];
    __shared__ float Bs[16][64];
    __shared__ float invs[64];
    int b = blockIdx.z;
    int n0 = blockIdx.x * 64;
    int o0 = blockIdx.y * 64;
    const float* xb = x + (size_t)b * CC * NN;
    int t = threadIdx.x;
    int tx = t & 15, ty = t >> 4;
    if (t < 64) invs[t] = 1.0f / g_rowsum[b * NN + n0 + t];
    __syncthreads();
    float acc[4][4] = {};
    for (int c0 = 0; c0 < CC; c0 += 16) {
        {
            int o = t >> 2;
            int cq = (t & 3) << 2;
            float4 w4 = *reinterpret_cast<const float4*>(W + (o0 + o) * CC + c0 + cq);
            As[cq + 0][o] = w4.x; As[cq + 1][o] = w4.y;
            As[cq + 2][o] = w4.z; As[cq + 3][o] = w4.w;
            int c = t >> 4;
            int nq = (t & 15) << 2;
            float4 xv = *reinterpret_cast<const float4*>(xb + (size_t)(c0 + c) * NN + n0 + nq);
            float4 rv = *reinterpret_cast<const float4*>(g_xr + ((size_t)b * CC + c0 + c) * NN + n0 + nq);
            Bs[c][nq + 0] = xv.x - rv.x * invs[nq + 0];
            Bs[c][nq + 1] = xv.y - rv.y * invs[nq + 1];
            Bs[c][nq + 2] = xv.z - rv.z * invs[nq + 2];
            Bs[c][nq + 3] = xv.w - rv.w * invs[nq + 3];
        }
        __syncthreads();
        #pragma unroll
        for (int k = 0; k < 16; k++) {
            float a0 = As[k][ty * 4 + 0], a1 = As[k][ty * 4 + 1];
            float a2 = As[k][ty * 4 + 2], a3 = As[k][ty * 4 + 3];
            float b0 = Bs[k][tx * 4 + 0], b1 = Bs[k][tx * 4 + 1];
            float b2 = Bs[k][tx * 4 + 2], b3 = Bs[k][tx * 4 + 3];
            acc[0][0] += a0 * b0; acc[0][1] += a0 * b1; acc[0][2] += a0 * b2; acc[0][3] += a0 * b3;
            acc[1][0] += a1 * b0; acc[1][1] += a1 * b1; acc[1][2] += a1 * b2; acc[1][3] += a1 * b3;
            acc[2][0] += a2 * b0; acc[2][1] += a2 * b1; acc[2][2] += a2 * b2; acc[2][3] += a2 * b3;
            acc[3][0] += a3 * b0; acc[3][1] += a3 * b1; acc[3][2] += a3 * b2; acc[3][3] += a3 * b3;
        }
        __syncthreads();
    }
    #pragma unroll
    for (int i = 0; i < 4; i++) {
        int o = o0 + ty * 4 + i;
        float s  = gamma[o] * rsqrtf(var[o] + BN_EPSF);
        float sh = beta[o] - mean[o] * s;
        float bt = bias[o];
        size_t off = ((size_t)b * CC + o) * NN + n0 + tx * 4;
        float4 xv = *reinterpret_cast<const float4*>(xb + (size_t)o * NN + n0 + tx * 4);
        float4 r;
        r.x = xv.x + fmaxf((acc[i][0] + bt) * s + sh, 0.f);
        r.y = xv.y + fmaxf((acc[i][1] + bt) * s + sh, 0.f);
        r.z = xv.z + fmaxf((acc[i][2] + bt) * s + sh, 0.f);
        r.w = xv.w + fmaxf((acc[i][3] + bt) * s + sh, 0.f);
        *reinterpret_cast<float4*>(out + off) = r;
    }
}

// ---------------------------------------------------------------------------
extern "C" void kernel_launch(void* const* d_in, const int* in_sizes, int n_in,
                              void* d_out, int out_size) {
    const float* x     = (const float*)d_in[0];
    const float* wq    = (const float*)d_in[1];
    const float* wv    = (const float*)d_in[2];
    const float* bv    = (const float*)d_in[3];
    const float* wt    = (const float*)d_in[4];
    const float* bt    = (const float*)d_in[5];
    const float* gamma = (const float*)d_in[6];
    const float* beta  = (const float*)d_in[7];
    const float* rmean = (const float*)d_in[8];
    const float* rvar  = (const float*)d_in[9];
    float* out = (float*)d_out;

    float* v_p = nullptr;
    cudaGetSymbolAddress((void**)&v_p, g_v);

    cudaFuncSetAttribute(k_gram_wmma, cudaFuncAttributeMaxDynamicSharedMemorySize, GRAM_SMEM);
    cudaFuncSetAttribute(k_xr_wmma,   cudaFuncAttributeMaxDynamicSharedMemorySize, XR_SMEM);

    k_init<<<(BB * NN + 255) / 256, 256>>>();
    // qk projection -> bf16 hi/lo, transposed [b][n][64]
    k_convq<<<dim3(NN / 64, 1, BB), 256>>>(wq, x);
    // v = wv * x + bv (fp32)
    k_conv<<<dim3(NN / 64, CC / 64, BB), 256>>>(wv, bv, x, v_p, CC);
    // exp(energy) via wmma bf16 split + rowsums
    k_gram_wmma<<<dim3(NN / 256, NN / 128, BB), 256, GRAM_SMEM>>>();
    // colsums of normalized attn
    k_colsum<<<dim3(NN / 256, NN / 256, BB), 256>>>();
    // fold L1 renorm into v, split to bf16 hi/lo
    k_splitv<<<(BB * CC * NN) / 256, 256>>>();
    // raw x_r sums via wmma bf16 split
    k_xr_wmma<<<dim3(NN / 128, BB), 256, XR_SMEM>>>();
    // wt conv (x - x_r fused) + BN + relu + residual
    k_final<<<dim3(NN / 64, CC / 64, BB), 256>>>(wt, bt, x, gamma, beta, rmean, rvar, out);
}

// round 8
// speedup vs baseline: 2.2035x; 1.1622x over previous
#include <cuda_runtime.h>
#include <cuda_bf16.h>
#include <cstdint>
#include <math.h>

#define BB 4
#define CC 256
#define CQ 64
#define NN 4096
#define BN_EPSF 1e-5f

static constexpr size_t NN2 = (size_t)NN * NN;

// Scratch (device globals — no allocation allowed)
__device__ __nv_bfloat16 g_qkh[(size_t)BB * NN * CQ];   // 2 MB  qk hi  [b][n][o]
__device__ __nv_bfloat16 g_qkl[(size_t)BB * NN * CQ];   // 2 MB  qk lo
__device__ float         g_v[(size_t)BB * CC * NN];     // 16 MB v[b,c,n]
__device__ __nv_bfloat16 g_vh[(size_t)BB * CC * NN];    // 8 MB  vs hi [b][c][m]
__device__ __nv_bfloat16 g_vl[(size_t)BB * CC * NN];    // 8 MB  vs lo
__device__ __nv_bfloat16 g_ah[(size_t)BB * NN * NN];    // 134 MB exp(energy) hi [b][n][m]
__device__ __nv_bfloat16 g_al[(size_t)BB * NN * NN];    // 134 MB exp(energy) lo
__device__ float         g_rowsum[BB * NN];
__device__ float         g_colsum[BB * NN];
__device__ float         g_xr[(size_t)BB * CC * NN];    // 16 MB raw x_r sums

// ===========================================================================
__device__ __forceinline__ uint32_t smem_u32(const void* p) {
    uint32_t a;
    asm("{ .reg .u64 t; cvta.to.shared.u64 t, %1; cvt.u32.u64 %0, t; }" : "=r"(a) : "l"(p));
    return a;
}
__device__ __forceinline__ void cp16(uint32_t dst, const void* src) {
    asm volatile("cp.async.cg.shared.global [%0], [%1], 16;" :: "r"(dst), "l"(src) : "memory");
}
__device__ __forceinline__ void cp_commit() {
    asm volatile("cp.async.commit_group;" ::: "memory");
}
template <int N> __device__ __forceinline__ void cp_wait() {
    asm volatile("cp.async.wait_group %0;" :: "n"(N) : "memory");
}
__device__ __forceinline__ void ldm4(uint32_t* r, uint32_t a) {
    asm volatile("ldmatrix.sync.aligned.m8n8.x4.shared.b16 {%0,%1,%2,%3}, [%4];"
        : "=r"(r[0]), "=r"(r[1]), "=r"(r[2]), "=r"(r[3]) : "r"(a));
}
__device__ __forceinline__ void mma16816(float* c, const uint32_t* a, uint32_t b0, uint32_t b1) {
    asm volatile("mma.sync.aligned.m16n8k16.row.col.f32.bf16.bf16.f32 "
        "{%0,%1,%2,%3}, {%4,%5,%6,%7}, {%8,%9}, {%0,%1,%2,%3};"
        : "+f"(c[0]), "+f"(c[1]), "+f"(c[2]), "+f"(c[3])
        : "r"(a[0]), "r"(a[1]), "r"(a[2]), "r"(a[3]), "r"(b0), "r"(b1));
}

// ===========================================================================
__global__ void k_init() {
    int i = blockIdx.x * blockDim.x + threadIdx.x;
    if (i < BB * NN) { g_rowsum[i] = 0.f; g_colsum[i] = 0.f; }
}

// ---------------------------------------------------------------------------
// out[b,o,n] = sum_c W[o,c] * x[b,c,n] + bias[o]   (v projection, fp32 SIMT)
__global__ void __launch_bounds__(256) k_conv(
        const float* __restrict__ W, const float* __restrict__ bias,
        const float* __restrict__ x, float* __restrict__ out, int O) {
    __shared__ float As[16][64];
    __shared__ float Bs[16][64];
    int b = blockIdx.z;
    int n0 = blockIdx.x * 64;
    int o0 = blockIdx.y * 64;
    const float* xb = x + (size_t)b * CC * NN;
    int t = threadIdx.x;
    int tx = t & 15, ty = t >> 4;
    float acc[4][4] = {};
    for (int c0 = 0; c0 < CC; c0 += 16) {
        {
            int o = t >> 2;
            int cq = (t & 3) << 2;
            float4 w4 = *reinterpret_cast<const float4*>(W + (o0 + o) * CC + c0 + cq);
            As[cq + 0][o] = w4.x; As[cq + 1][o] = w4.y;
            As[cq + 2][o] = w4.z; As[cq + 3][o] = w4.w;
            int c = t >> 4;
            int nq = (t & 15) << 2;
            *reinterpret_cast<float4*>(&Bs[c][nq]) =
                *reinterpret_cast<const float4*>(xb + (size_t)(c0 + c) * NN + n0 + nq);
        }
        __syncthreads();
        #pragma unroll
        for (int k = 0; k < 16; k++) {
            float a0 = As[k][ty * 4 + 0], a1 = As[k][ty * 4 + 1];
            float a2 = As[k][ty * 4 + 2], a3 = As[k][ty * 4 + 3];
            float b0 = Bs[k][tx * 4 + 0], b1 = Bs[k][tx * 4 + 1];
            float b2 = Bs[k][tx * 4 + 2], b3 = Bs[k][tx * 4 + 3];
            acc[0][0] += a0 * b0; acc[0][1] += a0 * b1; acc[0][2] += a0 * b2; acc[0][3] += a0 * b3;
            acc[1][0] += a1 * b0; acc[1][1] += a1 * b1; acc[1][2] += a1 * b2; acc[1][3] += a1 * b3;
            acc[2][0] += a2 * b0; acc[2][1] += a2 * b1; acc[2][2] += a2 * b2; acc[2][3] += a2 * b3;
            acc[3][0] += a3 * b0; acc[3][1] += a3 * b1; acc[3][2] += a3 * b2; acc[3][3] += a3 * b3;
        }
        __syncthreads();
    }
    #pragma unroll
    for (int i = 0; i < 4; i++) {
        int o = o0 + ty * 4 + i;
        float bv = bias ? bias[o] : 0.f;
        float4 r;
        r.x = acc[i][0] + bv; r.y = acc[i][1] + bv;
        r.z = acc[i][2] + bv; r.w = acc[i][3] + bv;
        *reinterpret_cast<float4*>(out + ((size_t)b * O + o) * NN + n0 + tx * 4) = r;
    }
}

// ---------------------------------------------------------------------------
// qk projection, written TRANSPOSED [b][n][o] as bf16 hi + residual lo
__global__ void __launch_bounds__(256) k_convq(
        const float* __restrict__ W, const float* __restrict__ x) {
    __shared__ float As[16][64];
    __shared__ float Bs[16][64];
    int b = blockIdx.z;
    int n0 = blockIdx.x * 64;
    const float* xb = x + (size_t)b * CC * NN;
    int t = threadIdx.x;
    int tx = t & 15, ty = t >> 4;
    float acc[4][4] = {};
    for (int c0 = 0; c0 < CC; c0 += 16) {
        {
            int o = t >> 2;
            int cq = (t & 3) << 2;
            float4 w4 = *reinterpret_cast<const float4*>(W + o * CC + c0 + cq);
            As[cq + 0][o] = w4.x; As[cq + 1][o] = w4.y;
            As[cq + 2][o] = w4.z; As[cq + 3][o] = w4.w;
            int c = t >> 4;
            int nq = (t & 15) << 2;
            *reinterpret_cast<float4*>(&Bs[c][nq]) =
                *reinterpret_cast<const float4*>(xb + (size_t)(c0 + c) * NN + n0 + nq);
        }
        __syncthreads();
        #pragma unroll
        for (int k = 0; k < 16; k++) {
            float a0 = As[k][ty * 4 + 0], a1 = As[k][ty * 4 + 1];
            float a2 = As[k][ty * 4 + 2], a3 = As[k][ty * 4 + 3];
            float b0 = Bs[k][tx * 4 + 0], b1 = Bs[k][tx * 4 + 1];
            float b2 = Bs[k][tx * 4 + 2], b3 = Bs[k][tx * 4 + 3];
            acc[0][0] += a0 * b0; acc[0][1] += a0 * b1; acc[0][2] += a0 * b2; acc[0][3] += a0 * b3;
            acc[1][0] += a1 * b0; acc[1][1] += a1 * b1; acc[1][2] += a1 * b2; acc[1][3] += a1 * b3;
            acc[2][0] += a2 * b0; acc[2][1] += a2 * b1; acc[2][2] += a2 * b2; acc[2][3] += a2 * b3;
            acc[3][0] += a3 * b0; acc[3][1] += a3 * b1; acc[3][2] += a3 * b2; acc[3][3] += a3 * b3;
        }
        __syncthreads();
    }
    #pragma unroll
    for (int i = 0; i < 4; i++) {
        int o = ty * 4 + i;
        #pragma unroll
        for (int j = 0; j < 4; j++) {
            int n = n0 + tx * 4 + j;
            float v = acc[i][j];
            __nv_bfloat16 h = __float2bfloat16(v);
            size_t off = ((size_t)b * NN + n) * CQ + o;
            g_qkh[off] = h;
            g_qkl[off] = __float2bfloat16(v - __bfloat162float(h));
        }
    }
}

// ---------------------------------------------------------------------------
// Gram via raw mma bf16 3-term split: attn = exp(qk[n]·qk[m]); hi/lo store + rowsum.
// CTA 128n x 128m, 8 warps (warp 64n x 32m), K=64, 2 CTAs/SM.
// smem: Ah[128][72] | Al | Bh | Bl, pitch 72 bf16 (144B, conflict-free ldmatrix)
#define GP 72
#define GRAM_SMEM (4 * 128 * GP * 2)   // 73728
__global__ void __launch_bounds__(256, 2) k_gram_mma() {
    extern __shared__ __align__(16) char smem[];
    const uint32_t sb = smem_u32(smem);
    int t = threadIdx.x, w = t >> 5, l = t & 31;
    int m0 = blockIdx.x * 128;
    int n0 = blockIdx.y * 128;
    int b = blockIdx.z;
    const __nv_bfloat16* qh = g_qkh + (size_t)b * NN * CQ;
    const __nv_bfloat16* ql = g_qkl + (size_t)b * NN * CQ;

    // Stage operands: 512 rows x 128B (8 x cp16 per row)
    #pragma unroll
    for (int i = 0; i < 16; i++) {
        int idx = i * 256 + t;
        int row = idx >> 3, q = idx & 7;
        const __nv_bfloat16* src;
        uint32_t base;
        int grow;
        if (row < 128)      { src = qh; base = 0;         grow = n0 + row; }
        else if (row < 256) { src = ql; base = 18432;     grow = n0 + row - 128; }
        else if (row < 384) { src = qh; base = 36864;     grow = m0 + row - 256; }
        else                { src = ql; base = 55296;     grow = m0 + row - 384; }
        cp16(sb + base + (uint32_t)(row & 127) * 144 + q * 16,
             src + (size_t)grow * CQ + q * 8);
    }
    cp_commit();
    cp_wait<0>();
    __syncthreads();

    int wn = w & 1;    // n half (64)
    int wm = w >> 1;   // m quarter (32)

    // ldmatrix per-thread offsets
    const uint32_t A_thr = (uint32_t)(((l & 15) * GP + (l >> 4) * 8) * 2);
    const uint32_t B_thr = (uint32_t)((((l >> 4) * 8 + (l & 7)) * GP + ((l >> 3) & 1) * 8) * 2);
    const uint32_t aBaseH = sb + 0     + (uint32_t)(wn * 64) * 144 + A_thr;
    const uint32_t aBaseL = sb + 18432 + (uint32_t)(wn * 64) * 144 + A_thr;
    const uint32_t bBaseH = sb + 36864 + (uint32_t)(wm * 32) * 144 + B_thr;
    const uint32_t bBaseL = sb + 55296 + (uint32_t)(wm * 32) * 144 + B_thr;

    float acc[4][4][4] = {};

    #pragma unroll
    for (int kk = 0; kk < 4; kk++) {
        uint32_t koff = (uint32_t)(kk * 32);   // 16 bf16 = 32B
        #pragma unroll
        for (int term = 0; term < 3; term++) {
            uint32_t aB = (term == 2) ? aBaseL : aBaseH;
            uint32_t bB = (term == 1) ? bBaseL : bBaseH;
            uint32_t a[4][4];
            #pragma unroll
            for (int i = 0; i < 4; i++)
                ldm4(a[i], aB + (uint32_t)(i * 16) * 144 + koff);
            uint32_t bf[2][4];
            #pragma unroll
            for (int jj = 0; jj < 2; jj++)
                ldm4(bf[jj], bB + (uint32_t)(jj * 16) * 144 + koff);
            #pragma unroll
            for (int i = 0; i < 4; i++)
                #pragma unroll
                for (int j = 0; j < 4; j++)
                    mma16816(acc[i][j], a[i], bf[j >> 1][(j & 1) * 2], bf[j >> 1][(j & 1) * 2 + 1]);
        }
    }

    // Epilogue: exp on registers, bf16 hi/lo stores, rowsum via quad shuffle
    __nv_bfloat16* oh = g_ah + (size_t)b * NN2;
    __nv_bfloat16* ol = g_al + (size_t)b * NN2;
    int r0 = l >> 2;
    int cl = 2 * (l & 3);
    #pragma unroll
    for (int i = 0; i < 4; i++) {
        int nA = n0 + wn * 64 + i * 16 + r0;
        int nB = nA + 8;
        float rs0 = 0.f, rs1 = 0.f;
        #pragma unroll
        for (int j = 0; j < 4; j++) {
            int mcol = m0 + wm * 32 + j * 8 + cl;
            float e0 = __expf(acc[i][j][0]);
            float e1 = __expf(acc[i][j][1]);
            float e2 = __expf(acc[i][j][2]);
            float e3 = __expf(acc[i][j][3]);
            rs0 += e0 + e1; rs1 += e2 + e3;
            __nv_bfloat162 h01, l01, h23, l23;
            h01.x = __float2bfloat16(e0); h01.y = __float2bfloat16(e1);
            l01.x = __float2bfloat16(e0 - __bfloat162float(h01.x));
            l01.y = __float2bfloat16(e1 - __bfloat162float(h01.y));
            h23.x = __float2bfloat16(e2); h23.y = __float2bfloat16(e3);
            l23.x = __float2bfloat16(e2 - __bfloat162float(h23.x));
            l23.y = __float2bfloat16(e3 - __bfloat162float(h23.y));
            *reinterpret_cast<__nv_bfloat162*>(oh + (size_t)nA * NN + mcol) = h01;
            *reinterpret_cast<__nv_bfloat162*>(ol + (size_t)nA * NN + mcol) = l01;
            *reinterpret_cast<__nv_bfloat162*>(oh + (size_t)nB * NN + mcol) = h23;
            *reinterpret_cast<__nv_bfloat162*>(ol + (size_t)nB * NN + mcol) = l23;
        }
        rs0 += __shfl_xor_sync(0xffffffffu, rs0, 1);
        rs0 += __shfl_xor_sync(0xffffffffu, rs0, 2);
        rs1 += __shfl_xor_sync(0xffffffffu, rs1, 1);
        rs1 += __shfl_xor_sync(0xffffffffu, rs1, 2);
        if ((l & 3) == 0) {
            atomicAdd(&g_rowsum[b * NN + nA], rs0);
            atomicAdd(&g_rowsum[b * NN + nB], rs1);
        }
    }
}

// ---------------------------------------------------------------------------
// colsum[b,m] = sum_n (attn_hi + attn_lo)[n,m] / rowsum[n]
__global__ void __launch_bounds__(256) k_colsum() {
    __shared__ float inv[256];
    int b = blockIdx.z;
    int m = blockIdx.x * 256 + threadIdx.x;
    int nbase = blockIdx.y * 256;
    inv[threadIdx.x] = 1.0f / g_rowsum[b * NN + nbase + threadIdx.x];
    __syncthreads();
    const __nv_bfloat16* ah = g_ah + (size_t)b * NN2;
    const __nv_bfloat16* al = g_al + (size_t)b * NN2;
    float s = 0.f;
    #pragma unroll 4
    for (int i = 0; i < 256; i++) {
        size_t off = (size_t)(nbase + i) * NN + m;
        s += (__bfloat162float(ah[off]) + __bfloat162float(al[off])) * inv[i];
    }
    atomicAdd(&g_colsum[b * NN + m], s);
}

// ---------------------------------------------------------------------------
// vs = v/(1e-9+colsum[m]) -> bf16 hi/lo
__global__ void __launch_bounds__(256) k_splitv() {
    size_t i = (size_t)blockIdx.x * 256 + threadIdx.x;
    int m = (int)(i & (NN - 1));
    int b = (int)(i >> 20);
    float vs = g_v[i] / (1e-9f + g_colsum[b * NN + m]);
    __nv_bfloat16 h = __float2bfloat16(vs);
    g_vh[i] = h;
    g_vl[i] = __float2bfloat16(vs - __bfloat162float(h));
}

// ---------------------------------------------------------------------------
// x_r raw sums via raw mma bf16 3-term split.
// CTA 256c x 128n, 512 threads (warp 64c x 32n), BK=32, 2-stage cp.async.
// Stage rows: Vh(256) Vl(256) Ah(128) Al(128), pitch 40 bf16 (80B).
#define XP 40
#define XSTAGE (768 * XP * 2)       // 61440
#define XR_SMEM (2 * XSTAGE)        // 122880
__global__ void __launch_bounds__(512, 1) k_xr_mma() {
    extern __shared__ __align__(16) char smem[];
    const uint32_t sb = smem_u32(smem);
    int t = threadIdx.x, w = t >> 5, l = t & 31;
    int n0 = blockIdx.x * 128;
    int b = blockIdx.y;

    const __nv_bfloat16* vh = g_vh + (size_t)b * CC * NN;
    const __nv_bfloat16* vl = g_vl + (size_t)b * CC * NN;
    const __nv_bfloat16* ahp = g_ah + (size_t)b * NN2 + (size_t)n0 * NN;
    const __nv_bfloat16* alp = g_al + (size_t)b * NN2 + (size_t)n0 * NN;

    auto issue = [&](int kc) {
        uint32_t base = sb + (uint32_t)(kc & 1) * XSTAGE;
        int koff = kc * 32;
        #pragma unroll
        for (int i = 0; i < 6; i++) {
            int idx = i * 512 + t;
            int row = idx >> 2, q = idx & 3;
            const __nv_bfloat16* src;
            uint32_t rbase;
            int grow;
            if (row < 256)      { src = vh;  rbase = 0;     grow = row; }
            else if (row < 512) { src = vl;  rbase = 20480; grow = row - 256; }
            else if (row < 640) { src = ahp; rbase = 40960; grow = row - 512; }
            else                { src = alp; rbase = 51200; grow = row - 640; }
            cp16(base + rbase + (uint32_t)grow * 80 + q * 16,
                 src + (size_t)grow * NN + koff + q * 8);
        }
        cp_commit();
    };

    int wc = w >> 2;   // c quarter (64)
    int wn = w & 3;    // n quarter (32)

    const uint32_t A_thr = (uint32_t)(((l & 15) * XP + (l >> 4) * 8) * 2);
    const uint32_t B_thr = (uint32_t)((((l >> 4) * 8 + (l & 7)) * XP + ((l >> 3) & 1) * 8) * 2);
    const uint32_t aOffH = 0     + (uint32_t)(wc * 64) * 80 + A_thr;
    const uint32_t aOffL = 20480 + (uint32_t)(wc * 64) * 80 + A_thr;
    const uint32_t bOffH = 40960 + (uint32_t)(wn * 32) * 80 + B_thr;
    const uint32_t bOffL = 51200 + (uint32_t)(wn * 32) * 80 + B_thr;

    float acc[4][4][4] = {};

    issue(0); issue(1);

    for (int kc = 0; kc < 128; kc++) {
        if (kc < 127) cp_wait<1>(); else cp_wait<0>();
        __syncthreads();
        uint32_t stg = sb + (uint32_t)(kc & 1) * XSTAGE;
        #pragma unroll
        for (int ks = 0; ks < 2; ks++) {
            uint32_t koff = (uint32_t)(ks * 32);
            #pragma unroll
            for (int term = 0; term < 3; term++) {
                uint32_t aB = stg + ((term == 2) ? aOffL : aOffH);
                uint32_t bB = stg + ((term == 1) ? bOffL : bOffH);
                uint32_t a[4][4];
                #pragma unroll
                for (int i = 0; i < 4; i++)
                    ldm4(a[i], aB + (uint32_t)(i * 16) * 80 + koff);
                uint32_t bf[2][4];
                #pragma unroll
                for (int jj = 0; jj < 2; jj++)
                    ldm4(bf[jj], bB + (uint32_t)(jj * 16) * 80 + koff);
                #pragma unroll
                for (int i = 0; i < 4; i++)
                    #pragma unroll
                    for (int j = 0; j < 4; j++)
                        mma16816(acc[i][j], a[i], bf[j >> 1][(j & 1) * 2], bf[j >> 1][(j & 1) * 2 + 1]);
            }
        }
        __syncthreads();
        if (kc + 2 < 128) issue(kc + 2);
    }

    // Store raw sums (scaled by 1/rowsum later in k_final)
    int r0 = l >> 2;
    int cl = 2 * (l & 3);
    #pragma unroll
    for (int i = 0; i < 4; i++) {
        int cA = wc * 64 + i * 16 + r0;
        #pragma unroll
        for (int j = 0; j < 4; j++) {
            int ncol = n0 + wn * 32 + j * 8 + cl;
            float2 v01; v01.x = acc[i][j][0]; v01.y = acc[i][j][1];
            float2 v23; v23.x = acc[i][j][2]; v23.y = acc[i][j][3];
            *reinterpret_cast<float2*>(g_xr + ((size_t)b * CC + cA) * NN + ncol) = v01;
            *reinterpret_cast<float2*>(g_xr + ((size_t)b * CC + cA + 8) * NN + ncol) = v23;
        }
    }
}

// ---------------------------------------------------------------------------
// t = wt * (x - xr_raw/rowsum) + bt ; BN inference ; out = x + relu(bn)
__global__ void __launch_bounds__(256) k_final(
        const float* __restrict__ W, const float* __restrict__ bias,
        const float* __restrict__ x,
        const float* __restrict__ gamma, const float* __restrict__ beta,
        const float* __restrict__ mean,  const float* __restrict__ var,
        float* __restrict__ out) {
    __shared__ float As[16][64];
    __shared__ float Bs[16][64];
    __shared__ float invs[64];
    int b = blockIdx.z;
    int n0 = blockIdx.x * 64;
    int o0 = blockIdx.y * 64;
    const float* xb = x + (size_t)b * CC * NN;
    int t = threadIdx.x;
    int tx = t & 15, ty = t >> 4;
    if (t < 64) invs[t] = 1.0f / g_rowsum[b * NN + n0 + t];
    __syncthreads();
    float acc[4][4] = {};
    for (int c0 = 0; c0 < CC; c0 += 16) {
        {
            int o = t >> 2;
            int cq = (t & 3) << 2;
            float4 w4 = *reinterpret_cast<const float4*>(W + (o0 + o) * CC + c0 + cq);
            As[cq + 0][o] = w4.x; As[cq + 1][o] = w4.y;
            As[cq + 2][o] = w4.z; As[cq + 3][o] = w4.w;
            int c = t >> 4;
            int nq = (t & 15) << 2;
            float4 xv = *reinterpret_cast<const float4*>(xb + (size_t)(c0 + c) * NN + n0 + nq);
            float4 rv = *reinterpret_cast<const float4*>(g_xr + ((size_t)b * CC + c0 + c) * NN + n0 + nq);
            Bs[c][nq + 0] = xv.x - rv.x * invs[nq + 0];
            Bs[c][nq + 1] = xv.y - rv.y * invs[nq + 1];
            Bs[c][nq + 2] = xv.z - rv.z * invs[nq + 2];
            Bs[c][nq + 3] = xv.w - rv.w * invs[nq + 3];
        }
        __syncthreads();
        #pragma unroll
        for (int k = 0; k < 16; k++) {
            float a0 = As[k][ty * 4 + 0], a1 = As[k][ty * 4 + 1];
            float a2 = As[k][ty * 4 + 2], a3 = As[k][ty * 4 + 3];
            float b0 = Bs[k][tx * 4 + 0], b1 = Bs[k][tx * 4 + 1];
            float b2 = Bs[k][tx * 4 + 2], b3 = Bs[k][tx * 4 + 3];
            acc[0][0] += a0 * b0; acc[0][1] += a0 * b1; acc[0][2] += a0 * b2; acc[0][3] += a0 * b3;
            acc[1][0] += a1 * b0; acc[1][1] += a1 * b1; acc[1][2] += a1 * b2; acc[1][3] += a1 * b3;
            acc[2][0] += a2 * b0; acc[2][1] += a2 * b1; acc[2][2] += a2 * b2; acc[2][3] += a2 * b3;
            acc[3][0] += a3 * b0; acc[3][1] += a3 * b1; acc[3][2] += a3 * b2; acc[3][3] += a3 * b3;
        }
        __syncthreads();
    }
    #pragma unroll
    for (int i = 0; i < 4; i++) {
        int o = o0 + ty * 4 + i;
        float s  = gamma[o] * rsqrtf(var[o] + BN_EPSF);
        float sh = beta[o] - mean[o] * s;
        float bt = bias[o];
        size_t off = ((size_t)b * CC + o) * NN + n0 + tx * 4;
        float4 xv = *reinterpret_cast<const float4*>(xb + (size_t)o * NN + n0 + tx * 4);
        float4 r;
        r.x = xv.x + fmaxf((acc[i][0] + bt) * s + sh, 0.f);
        r.y = xv.y + fmaxf((acc[i][1] + bt) * s + sh, 0.f);
        r.z = xv.z + fmaxf((acc[i][2] + bt) * s + sh, 0.f);
        r.w = xv.w + fmaxf((acc[i][3] + bt) * s + sh, 0.f);
        *reinterpret_cast<float4*>(out + off) = r;
    }
}

// ---------------------------------------------------------------------------
extern "C" void kernel_launch(void* const* d_in, const int* in_sizes, int n_in,
                              void* d_out, int out_size) {
    const float* x     = (const float*)d_in[0];
    const float* wq    = (const float*)d_in[1];
    const float* wv    = (const float*)d_in[2];
    const float* bv    = (const float*)d_in[3];
    const float* wt    = (const float*)d_in[4];
    const float* bt    = (const float*)d_in[5];
    const float* gamma = (const float*)d_in[6];
    const float* beta  = (const float*)d_in[7];
    const float* rmean = (const float*)d_in[8];
    const float* rvar  = (const float*)d_in[9];
    float* out = (float*)d_out;

    float* v_p = nullptr;
    cudaGetSymbolAddress((void**)&v_p, g_v);

    cudaFuncSetAttribute(k_gram_mma, cudaFuncAttributeMaxDynamicSharedMemorySize, GRAM_SMEM);
    cudaFuncSetAttribute(k_xr_mma,   cudaFuncAttributeMaxDynamicSharedMemorySize, XR_SMEM);

    k_init<<<(BB * NN + 255) / 256, 256>>>();
    // qk projection -> bf16 hi/lo, transposed [b][n][64]
    k_convq<<<dim3(NN / 64, 1, BB), 256>>>(wq, x);
    // v = wv * x + bv (fp32)
    k_conv<<<dim3(NN / 64, CC / 64, BB), 256>>>(wv, bv, x, v_p, CC);
    // exp(energy) via raw mma bf16 split + rowsums
    k_gram_mma<<<dim3(NN / 128, NN / 128, BB), 256, GRAM_SMEM>>>();
    // colsums of normalized attn
    k_colsum<<<dim3(NN / 256, NN / 256, BB), 256>>>();
    // fold L1 renorm into v, split to bf16 hi/lo
    k_splitv<<<(BB * CC * NN) / 256, 256>>>();
    // raw x_r sums via raw mma bf16 split
    k_xr_mma<<<dim3(NN / 128, BB), 512, XR_SMEM>>>();
    // wt conv (x - x_r fused) + BN + relu + residual
    k_final<<<dim3(NN / 64, CC / 64, BB), 256>>>(wt, bt, x, gamma, beta, rmean, rvar, out);
}

// round 9
// speedup vs baseline: 2.7464x; 1.2464x over previous
#include <cuda_runtime.h>
#include <cuda_bf16.h>
#include <cstdint>
#include <math.h>

#define BB 4
#define CC 256
#define CQ 64
#define NN 4096
#define BN_EPSF 1e-5f

static constexpr size_t NN2 = (size_t)NN * NN;

// Scratch (device globals — no allocation allowed)
__device__ __nv_bfloat16 g_qkh[(size_t)BB * NN * CQ];   // 2 MB  qk hi  [b][n][o]
__device__ __nv_bfloat16 g_qkl[(size_t)BB * NN * CQ];   // 2 MB  qk lo
__device__ float         g_v[(size_t)BB * CC * NN];     // 16 MB v[b,c,n]
__device__ __nv_bfloat16 g_vh[(size_t)BB * CC * NN];    // 8 MB  vs hi [b][c][m]
__device__ __nv_bfloat16 g_vl[(size_t)BB * CC * NN];    // 8 MB  vs lo
__device__ __nv_bfloat16 g_ah[(size_t)BB * NN * NN];    // 134 MB exp(energy) bf16 [b][n][m]
__device__ float         g_rowsum[BB * NN];             // from ROUNDED exp (consistency)
__device__ float         g_colsum[BB * NN];
__device__ float         g_xr[(size_t)BB * CC * NN];    // 16 MB raw x_r sums

// ===========================================================================
__device__ __forceinline__ uint32_t smem_u32(const void* p) {
    uint32_t a;
    asm("{ .reg .u64 t; cvta.to.shared.u64 t, %1; cvt.u32.u64 %0, t; }" : "=r"(a) : "l"(p));
    return a;
}
__device__ __forceinline__ void cp16(uint32_t dst, const void* src) {
    asm volatile("cp.async.cg.shared.global [%0], [%1], 16;" :: "r"(dst), "l"(src) : "memory");
}
__device__ __forceinline__ void cp_commit() {
    asm volatile("cp.async.commit_group;" ::: "memory");
}
template <int N> __device__ __forceinline__ void cp_wait() {
    asm volatile("cp.async.wait_group %0;" :: "n"(N) : "memory");
}
__device__ __forceinline__ void ldm4(uint32_t* r, uint32_t a) {
    asm volatile("ldmatrix.sync.aligned.m8n8.x4.shared.b16 {%0,%1,%2,%3}, [%4];"
        : "=r"(r[0]), "=r"(r[1]), "=r"(r[2]), "=r"(r[3]) : "r"(a));
}
__device__ __forceinline__ void mma16816(float* c, const uint32_t* a, uint32_t b0, uint32_t b1) {
    asm volatile("mma.sync.aligned.m16n8k16.row.col.f32.bf16.bf16.f32 "
        "{%0,%1,%2,%3}, {%4,%5,%6,%7}, {%8,%9}, {%0,%1,%2,%3};"
        : "+f"(c[0]), "+f"(c[1]), "+f"(c[2]), "+f"(c[3])
        : "r"(a[0]), "r"(a[1]), "r"(a[2]), "r"(a[3]), "r"(b0), "r"(b1));
}

// ===========================================================================
__global__ void k_init() {
    int i = blockIdx.x * blockDim.x + threadIdx.x;
    if (i < BB * NN) { g_rowsum[i] = 0.f; g_colsum[i] = 0.f; }
}

// ---------------------------------------------------------------------------
// out[b,o,n] = sum_c W[o,c] * x[b,c,n] + bias[o]   (v projection, fp32 SIMT)
__global__ void __launch_bounds__(256) k_conv(
        const float* __restrict__ W, const float* __restrict__ bias,
        const float* __restrict__ x, float* __restrict__ out, int O) {
    __shared__ float As[16][64];
    __shared__ float Bs[16][64];
    int b = blockIdx.z;
    int n0 = blockIdx.x * 64;
    int o0 = blockIdx.y * 64;
    const float* xb = x + (size_t)b * CC * NN;
    int t = threadIdx.x;
    int tx = t & 15, ty = t >> 4;
    float acc[4][4] = {};
    for (int c0 = 0; c0 < CC; c0 += 16) {
        {
            int o = t >> 2;
            int cq = (t & 3) << 2;
            float4 w4 = *reinterpret_cast<const float4*>(W + (o0 + o) * CC + c0 + cq);
            As[cq + 0][o] = w4.x; As[cq + 1][o] = w4.y;
            As[cq + 2][o] = w4.z; As[cq + 3][o] = w4.w;
            int c = t >> 4;
            int nq = (t & 15) << 2;
            *reinterpret_cast<float4*>(&Bs[c][nq]) =
                *reinterpret_cast<const float4*>(xb + (size_t)(c0 + c) * NN + n0 + nq);
        }
        __syncthreads();
        #pragma unroll
        for (int k = 0; k < 16; k++) {
            float a0 = As[k][ty * 4 + 0], a1 = As[k][ty * 4 + 1];
            float a2 = As[k][ty * 4 + 2], a3 = As[k][ty * 4 + 3];
            float b0 = Bs[k][tx * 4 + 0], b1 = Bs[k][tx * 4 + 1];
            float b2 = Bs[k][tx * 4 + 2], b3 = Bs[k][tx * 4 + 3];
            acc[0][0] += a0 * b0; acc[0][1] += a0 * b1; acc[0][2] += a0 * b2; acc[0][3] += a0 * b3;
            acc[1][0] += a1 * b0; acc[1][1] += a1 * b1; acc[1][2] += a1 * b2; acc[1][3] += a1 * b3;
            acc[2][0] += a2 * b0; acc[2][1] += a2 * b1; acc[2][2] += a2 * b2; acc[2][3] += a2 * b3;
            acc[3][0] += a3 * b0; acc[3][1] += a3 * b1; acc[3][2] += a3 * b2; acc[3][3] += a3 * b3;
        }
        __syncthreads();
    }
    #pragma unroll
    for (int i = 0; i < 4; i++) {
        int o = o0 + ty * 4 + i;
        float bv = bias ? bias[o] : 0.f;
        float4 r;
        r.x = acc[i][0] + bv; r.y = acc[i][1] + bv;
        r.z = acc[i][2] + bv; r.w = acc[i][3] + bv;
        *reinterpret_cast<float4*>(out + ((size_t)b * O + o) * NN + n0 + tx * 4) = r;
    }
}

// ---------------------------------------------------------------------------
// qk projection, written TRANSPOSED [b][n][o] as bf16 hi + residual lo
__global__ void __launch_bounds__(256) k_convq(
        const float* __restrict__ W, const float* __restrict__ x) {
    __shared__ float As[16][64];
    __shared__ float Bs[16][64];
    int b = blockIdx.z;
    int n0 = blockIdx.x * 64;
    const float* xb = x + (size_t)b * CC * NN;
    int t = threadIdx.x;
    int tx = t & 15, ty = t >> 4;
    float acc[4][4] = {};
    for (int c0 = 0; c0 < CC; c0 += 16) {
        {
            int o = t >> 2;
            int cq = (t & 3) << 2;
            float4 w4 = *reinterpret_cast<const float4*>(W + o * CC + c0 + cq);
            As[cq + 0][o] = w4.x; As[cq + 1][o] = w4.y;
            As[cq + 2][o] = w4.z; As[cq + 3][o] = w4.w;
            int c = t >> 4;
            int nq = (t & 15) << 2;
            *reinterpret_cast<float4*>(&Bs[c][nq]) =
                *reinterpret_cast<const float4*>(xb + (size_t)(c0 + c) * NN + n0 + nq);
        }
        __syncthreads();
        #pragma unroll
        for (int k = 0; k < 16; k++) {
            float a0 = As[k][ty * 4 + 0], a1 = As[k][ty * 4 + 1];
            float a2 = As[k][ty * 4 + 2], a3 = As[k][ty * 4 + 3];
            float b0 = Bs[k][tx * 4 + 0], b1 = Bs[k][tx * 4 + 1];
            float b2 = Bs[k][tx * 4 + 2], b3 = Bs[k][tx * 4 + 3];
            acc[0][0] += a0 * b0; acc[0][1] += a0 * b1; acc[0][2] += a0 * b2; acc[0][3] += a0 * b3;
            acc[1][0] += a1 * b0; acc[1][1] += a1 * b1; acc[1][2] += a1 * b2; acc[1][3] += a1 * b3;
            acc[2][0] += a2 * b0; acc[2][1] += a2 * b1; acc[2][2] += a2 * b2; acc[2][3] += a2 * b3;
            acc[3][0] += a3 * b0; acc[3][1] += a3 * b1; acc[3][2] += a3 * b2; acc[3][3] += a3 * b3;
        }
        __syncthreads();
    }
    #pragma unroll
    for (int i = 0; i < 4; i++) {
        int o = ty * 4 + i;
        #pragma unroll
        for (int j = 0; j < 4; j++) {
            int n = n0 + tx * 4 + j;
            float v = acc[i][j];
            __nv_bfloat16 h = __float2bfloat16(v);
            size_t off = ((size_t)b * NN + n) * CQ + o;
            g_qkh[off] = h;
            g_qkl[off] = __float2bfloat16(v - __bfloat162float(h));
        }
    }
}

// ---------------------------------------------------------------------------
// Gram via raw mma bf16 3-term split: attn = exp(qk[n]·qk[m]).
// Stores bf16 hi ONLY; rowsum accumulated from the ROUNDED values so downstream
// normalization cancels the rounding of the dominant softmax terms.
// CTA 128n x 128m, 8 warps (warp 64n x 32m), K=64, 2 CTAs/SM.
// hi tiles in cp.async group0, lo tiles in group1 -> hi*hi term overlaps lo loads.
#define GP 72
#define GRAM_SMEM (4 * 128 * GP * 2)   // 73728
__global__ void __launch_bounds__(256, 2) k_gram_mma() {
    extern __shared__ __align__(16) char smem[];
    const uint32_t sb = smem_u32(smem);
    int t = threadIdx.x, w = t >> 5, l = t & 31;
    int m0 = blockIdx.x * 128;
    int n0 = blockIdx.y * 128;
    int b = blockIdx.z;
    const __nv_bfloat16* qh = g_qkh + (size_t)b * NN * CQ;
    const __nv_bfloat16* ql = g_qkl + (size_t)b * NN * CQ;

    // group 0: Ah (128 rows) + Bh (128 rows)
    #pragma unroll
    for (int i = 0; i < 8; i++) {
        int idx = i * 256 + t;
        int row = idx >> 3, q = idx & 7;
        if (row < 128)
            cp16(sb + 0 + (uint32_t)row * 144 + q * 16, qh + (size_t)(n0 + row) * CQ + q * 8);
        else
            cp16(sb + 36864 + (uint32_t)(row - 128) * 144 + q * 16, qh + (size_t)(m0 + row - 128) * CQ + q * 8);
    }
    cp_commit();
    // group 1: Al + Bl
    #pragma unroll
    for (int i = 0; i < 8; i++) {
        int idx = i * 256 + t;
        int row = idx >> 3, q = idx & 7;
        if (row < 128)
            cp16(sb + 18432 + (uint32_t)row * 144 + q * 16, ql + (size_t)(n0 + row) * CQ + q * 8);
        else
            cp16(sb + 55296 + (uint32_t)(row - 128) * 144 + q * 16, ql + (size_t)(m0 + row - 128) * CQ + q * 8);
    }
    cp_commit();

    int wn = w & 1;    // n half (64)
    int wm = w >> 1;   // m quarter (32)

    const uint32_t A_thr = (uint32_t)(((l & 15) * GP + (l >> 4) * 8) * 2);
    const uint32_t B_thr = (uint32_t)((((l >> 4) * 8 + (l & 7)) * GP + ((l >> 3) & 1) * 8) * 2);
    const uint32_t aBaseH = sb + 0     + (uint32_t)(wn * 64) * 144 + A_thr;
    const uint32_t aBaseL = sb + 18432 + (uint32_t)(wn * 64) * 144 + A_thr;
    const uint32_t bBaseH = sb + 36864 + (uint32_t)(wm * 32) * 144 + B_thr;
    const uint32_t bBaseL = sb + 55296 + (uint32_t)(wm * 32) * 144 + B_thr;

    float acc[4][4][4] = {};

    // Phase 1: hi*hi while lo tiles still loading
    cp_wait<1>();
    __syncthreads();
    #pragma unroll
    for (int kk = 0; kk < 4; kk++) {
        uint32_t koff = (uint32_t)(kk * 32);
        uint32_t a[4][4];
        #pragma unroll
        for (int i = 0; i < 4; i++)
            ldm4(a[i], aBaseH + (uint32_t)(i * 16) * 144 + koff);
        uint32_t bf[2][4];
        #pragma unroll
        for (int jj = 0; jj < 2; jj++)
            ldm4(bf[jj], bBaseH + (uint32_t)(jj * 16) * 144 + koff);
        #pragma unroll
        for (int i = 0; i < 4; i++)
            #pragma unroll
            for (int j = 0; j < 4; j++)
                mma16816(acc[i][j], a[i], bf[j >> 1][(j & 1) * 2], bf[j >> 1][(j & 1) * 2 + 1]);
    }
    // Phase 2: hi*lo + lo*hi
    cp_wait<0>();
    __syncthreads();
    #pragma unroll
    for (int kk = 0; kk < 4; kk++) {
        uint32_t koff = (uint32_t)(kk * 32);
        uint32_t ah[4][4], al[4][4];
        #pragma unroll
        for (int i = 0; i < 4; i++) {
            ldm4(ah[i], aBaseH + (uint32_t)(i * 16) * 144 + koff);
            ldm4(al[i], aBaseL + (uint32_t)(i * 16) * 144 + koff);
        }
        uint32_t bh[2][4], bl[2][4];
        #pragma unroll
        for (int jj = 0; jj < 2; jj++) {
            ldm4(bh[jj], bBaseH + (uint32_t)(jj * 16) * 144 + koff);
            ldm4(bl[jj], bBaseL + (uint32_t)(jj * 16) * 144 + koff);
        }
        #pragma unroll
        for (int i = 0; i < 4; i++)
            #pragma unroll
            for (int j = 0; j < 4; j++) {
                mma16816(acc[i][j], ah[i], bl[j >> 1][(j & 1) * 2], bl[j >> 1][(j & 1) * 2 + 1]);
                mma16816(acc[i][j], al[i], bh[j >> 1][(j & 1) * 2], bh[j >> 1][(j & 1) * 2 + 1]);
            }
    }

    // Epilogue: exp -> round to bf16 -> store hi; rowsum from ROUNDED values.
    __nv_bfloat16* oh = g_ah + (size_t)b * NN2;
    int r0 = l >> 2;
    int cl = 2 * (l & 3);
    #pragma unroll
    for (int i = 0; i < 4; i++) {
        int nA = n0 + wn * 64 + i * 16 + r0;
        int nB = nA + 8;
        float rs0 = 0.f, rs1 = 0.f;
        #pragma unroll
        for (int j = 0; j < 4; j++) {
            int mcol = m0 + wm * 32 + j * 8 + cl;
            __nv_bfloat162 h01, h23;
            h01.x = __float2bfloat16(__expf(acc[i][j][0]));
            h01.y = __float2bfloat16(__expf(acc[i][j][1]));
            h23.x = __float2bfloat16(__expf(acc[i][j][2]));
            h23.y = __float2bfloat16(__expf(acc[i][j][3]));
            rs0 += __bfloat162float(h01.x) + __bfloat162float(h01.y);
            rs1 += __bfloat162float(h23.x) + __bfloat162float(h23.y);
            *reinterpret_cast<__nv_bfloat162*>(oh + (size_t)nA * NN + mcol) = h01;
            *reinterpret_cast<__nv_bfloat162*>(oh + (size_t)nB * NN + mcol) = h23;
        }
        rs0 += __shfl_xor_sync(0xffffffffu, rs0, 1);
        rs0 += __shfl_xor_sync(0xffffffffu, rs0, 2);
        rs1 += __shfl_xor_sync(0xffffffffu, rs1, 1);
        rs1 += __shfl_xor_sync(0xffffffffu, rs1, 2);
        if ((l & 3) == 0) {
            atomicAdd(&g_rowsum[b * NN + nA], rs0);
            atomicAdd(&g_rowsum[b * NN + nB], rs1);
        }
    }
}

// ---------------------------------------------------------------------------
// colsum[b,m] = sum_n attn[n,m] / rowsum[n]   (bf162 loads, 2 cols/thread)
__global__ void __launch_bounds__(256) k_colsum() {
    __shared__ float inv[256];
    int b = blockIdx.z;
    int m = blockIdx.x * 512 + 2 * threadIdx.x;
    int nbase = blockIdx.y * 256;
    inv[threadIdx.x] = 1.0f / g_rowsum[b * NN + nbase + threadIdx.x];
    __syncthreads();
    const __nv_bfloat16* ah = g_ah + (size_t)b * NN2;
    float s0 = 0.f, s1 = 0.f;
    #pragma unroll 4
    for (int i = 0; i < 256; i++) {
        __nv_bfloat162 v = *reinterpret_cast<const __nv_bfloat162*>(ah + (size_t)(nbase + i) * NN + m);
        s0 += __bfloat162float(v.x) * inv[i];
        s1 += __bfloat162float(v.y) * inv[i];
    }
    atomicAdd(&g_colsum[b * NN + m], s0);
    atomicAdd(&g_colsum[b * NN + m + 1], s1);
}

// ---------------------------------------------------------------------------
// vs = v/(1e-9+colsum[m]) -> bf16 hi/lo
__global__ void __launch_bounds__(256) k_splitv() {
    size_t i = (size_t)blockIdx.x * 256 + threadIdx.x;
    int m = (int)(i & (NN - 1));
    int b = (int)(i >> 20);
    float vs = g_v[i] / (1e-9f + g_colsum[b * NN + m]);
    __nv_bfloat16 h = __float2bfloat16(vs);
    g_vh[i] = h;
    g_vl[i] = __float2bfloat16(vs - __bfloat162float(h));
}

// ---------------------------------------------------------------------------
// x_r raw sums via raw mma, 2-term (Vh*A + Vl*A), attn hi only.
// CTA 256c x 128n, 512 threads (warp 64c x 32n), BK=32, 3-stage cp.async.
// Stage rows: Vh(256) Vl(256) Ah(128), pitch 40 bf16 (80B). Stage 51200B.
#define XP 40
#define XSTAGE (640 * XP * 2)       // 51200
#define XR_SMEM (3 * XSTAGE)        // 153600
__global__ void __launch_bounds__(512, 1) k_xr_mma() {
    extern __shared__ __align__(16) char smem[];
    const uint32_t sb = smem_u32(smem);
    int t = threadIdx.x, w = t >> 5, l = t & 31;
    int n0 = blockIdx.x * 128;
    int b = blockIdx.y;

    const __nv_bfloat16* vh = g_vh + (size_t)b * CC * NN;
    const __nv_bfloat16* vl = g_vl + (size_t)b * CC * NN;
    const __nv_bfloat16* ahp = g_ah + (size_t)b * NN2 + (size_t)n0 * NN;

    auto issue = [&](int kc) {
        uint32_t base = sb + (uint32_t)(kc % 3) * XSTAGE;
        int koff = kc * 32;
        #pragma unroll
        for (int i = 0; i < 5; i++) {
            int idx = i * 512 + t;
            int row = idx >> 2, q = idx & 3;
            const __nv_bfloat16* src;
            uint32_t rbase;
            int grow;
            if (row < 256)      { src = vh;  rbase = 0;     grow = row; }
            else if (row < 512) { src = vl;  rbase = 20480; grow = row - 256; }
            else                { src = ahp; rbase = 40960; grow = row - 512; }
            cp16(base + rbase + (uint32_t)grow * 80 + q * 16,
                 src + (size_t)grow * NN + koff + q * 8);
        }
        cp_commit();
    };

    int wc = w >> 2;   // c quarter (64)
    int wn = w & 3;    // n quarter (32)

    const uint32_t A_thr = (uint32_t)(((l & 15) * XP + (l >> 4) * 8) * 2);
    const uint32_t B_thr = (uint32_t)((((l >> 4) * 8 + (l & 7)) * XP + ((l >> 3) & 1) * 8) * 2);
    const uint32_t aOffH = 0     + (uint32_t)(wc * 64) * 80 + A_thr;
    const uint32_t aOffL = 20480 + (uint32_t)(wc * 64) * 80 + A_thr;
    const uint32_t bOff  = 40960 + (uint32_t)(wn * 32) * 80 + B_thr;

    float acc[4][4][4] = {};

    issue(0); issue(1); issue(2);

    for (int kc = 0; kc < 128; kc++) {
        if (kc < 126) cp_wait<2>();
        else if (kc == 126) cp_wait<1>();
        else cp_wait<0>();
        __syncthreads();
        uint32_t stg = sb + (uint32_t)(kc % 3) * XSTAGE;
        #pragma unroll
        for (int ks = 0; ks < 2; ks++) {
            uint32_t koff = (uint32_t)(ks * 32);
            uint32_t bf[2][4];
            #pragma unroll
            for (int jj = 0; jj < 2; jj++)
                ldm4(bf[jj], stg + bOff + (uint32_t)(jj * 16) * 80 + koff);
            #pragma unroll
            for (int term = 0; term < 2; term++) {
                uint32_t aB = stg + (term ? aOffL : aOffH);
                uint32_t a[4][4];
                #pragma unroll
                for (int i = 0; i < 4; i++)
                    ldm4(a[i], aB + (uint32_t)(i * 16) * 80 + koff);
                #pragma unroll
                for (int i = 0; i < 4; i++)
                    #pragma unroll
                    for (int j = 0; j < 4; j++)
                        mma16816(acc[i][j], a[i], bf[j >> 1][(j & 1) * 2], bf[j >> 1][(j & 1) * 2 + 1]);
            }
        }
        __syncthreads();
        if (kc + 3 < 128) issue(kc + 3);
    }

    // Store raw sums (scaled by 1/rowsum later in k_final)
    int r0 = l >> 2;
    int cl = 2 * (l & 3);
    #pragma unroll
    for (int i = 0; i < 4; i++) {
        int cA = wc * 64 + i * 16 + r0;
        #pragma unroll
        for (int j = 0; j < 4; j++) {
            int ncol = n0 + wn * 32 + j * 8 + cl;
            float2 v01; v01.x = acc[i][j][0]; v01.y = acc[i][j][1];
            float2 v23; v23.x = acc[i][j][2]; v23.y = acc[i][j][3];
            *reinterpret_cast<float2*>(g_xr + ((size_t)b * CC + cA) * NN + ncol) = v01;
            *reinterpret_cast<float2*>(g_xr + ((size_t)b * CC + cA + 8) * NN + ncol) = v23;
        }
    }
}

// ---------------------------------------------------------------------------
// t = wt * (x - xr_raw/rowsum) + bt ; BN inference ; out = x + relu(bn)
__global__ void __launch_bounds__(256) k_final(
        const float* __restrict__ W, const float* __restrict__ bias,
        const float* __restrict__ x,
        const float* __restrict__ gamma, const float* __restrict__ beta,
        const float* __restrict__ mean,  const float* __restrict__ var,
        float* __restrict__ out) {
    __shared__ float As[16][64];
    __shared__ float Bs[16][64];
    __shared__ float invs[64];
    int b = blockIdx.z;
    int n0 = blockIdx.x * 64;
    int o0 = blockIdx.y * 64;
    const float* xb = x + (size_t)b * CC * NN;
    int t = threadIdx.x;
    int tx = t & 15, ty = t >> 4;
    if (t < 64) invs[t] = 1.0f / g_rowsum[b * NN + n0 + t];
    __syncthreads();
    float acc[4][4] = {};
    for (int c0 = 0; c0 < CC; c0 += 16) {
        {
            int o = t >> 2;
            int cq = (t & 3) << 2;
            float4 w4 = *reinterpret_cast<const float4*>(W + (o0 + o) * CC + c0 + cq);
            As[cq + 0][o] = w4.x; As[cq + 1][o] = w4.y;
            As[cq + 2][o] = w4.z; As[cq + 3][o] = w4.w;
            int c = t >> 4;
            int nq = (t & 15) << 2;
            float4 xv = *reinterpret_cast<const float4*>(xb + (size_t)(c0 + c) * NN + n0 + nq);
            float4 rv = *reinterpret_cast<const float4*>(g_xr + ((size_t)b * CC + c0 + c) * NN + n0 + nq);
            Bs[c][nq + 0] = xv.x - rv.x * invs[nq + 0];
            Bs[c][nq + 1] = xv.y - rv.y * invs[nq + 1];
            Bs[c][nq + 2] = xv.z - rv.z * invs[nq + 2];
            Bs[c][nq + 3] = xv.w - rv.w * invs[nq + 3];
        }
        __syncthreads();
        #pragma unroll
        for (int k = 0; k < 16; k++) {
            float a0 = As[k][ty * 4 + 0], a1 = As[k][ty * 4 + 1];
            float a2 = As[k][ty * 4 + 2], a3 = As[k][ty * 4 + 3];
            float b0 = Bs[k][tx * 4 + 0], b1 = Bs[k][tx * 4 + 1];
            float b2 = Bs[k][tx * 4 + 2], b3 = Bs[k][tx * 4 + 3];
            acc[0][0] += a0 * b0; acc[0][1] += a0 * b1; acc[0][2] += a0 * b2; acc[0][3] += a0 * b3;
            acc[1][0] += a1 * b0; acc[1][1] += a1 * b1; acc[1][2] += a1 * b2; acc[1][3] += a1 * b3;
            acc[2][0] += a2 * b0; acc[2][1] += a2 * b1; acc[2][2] += a2 * b2; acc[2][3] += a2 * b3;
            acc[3][0] += a3 * b0; acc[3][1] += a3 * b1; acc[3][2] += a3 * b2; acc[3][3] += a3 * b3;
        }
        __syncthreads();
    }
    #pragma unroll
    for (int i = 0; i < 4; i++) {
        int o = o0 + ty * 4 + i;
        float s  = gamma[o] * rsqrtf(var[o] + BN_EPSF);
        float sh = beta[o] - mean[o] * s;
        float bt = bias[o];
        size_t off = ((size_t)b * CC + o) * NN + n0 + tx * 4;
        float4 xv = *reinterpret_cast<const float4*>(xb + (size_t)o * NN + n0 + tx * 4);
        float4 r;
        r.x = xv.x + fmaxf((acc[i][0] + bt) * s + sh, 0.f);
        r.y = xv.y + fmaxf((acc[i][1] + bt) * s + sh, 0.f);
        r.z = xv.z + fmaxf((acc[i][2] + bt) * s + sh, 0.f);
        r.w = xv.w + fmaxf((acc[i][3] + bt) * s + sh, 0.f);
        *reinterpret_cast<float4*>(out + off) = r;
    }
}

// ---------------------------------------------------------------------------
extern "C" void kernel_launch(void* const* d_in, const int* in_sizes, int n_in,
                              void* d_out, int out_size) {
    const float* x     = (const float*)d_in[0];
    const float* wq    = (const float*)d_in[1];
    const float* wv    = (const float*)d_in[2];
    const float* bv    = (const float*)d_in[3];
    const float* wt    = (const float*)d_in[4];
    const float* bt    = (const float*)d_in[5];
    const float* gamma = (const float*)d_in[6];
    const float* beta  = (const float*)d_in[7];
    const float* rmean = (const float*)d_in[8];
    const float* rvar  = (const float*)d_in[9];
    float* out = (float*)d_out;

    float* v_p = nullptr;
    cudaGetSymbolAddress((void**)&v_p, g_v);

    cudaFuncSetAttribute(k_gram_mma, cudaFuncAttributeMaxDynamicSharedMemorySize, GRAM_SMEM);
    cudaFuncSetAttribute(k_xr_mma,   cudaFuncAttributeMaxDynamicSharedMemorySize, XR_SMEM);

    k_init<<<(BB * NN + 255) / 256, 256>>>();
    // qk projection -> bf16 hi/lo, transposed [b][n][64]
    k_convq<<<dim3(NN / 64, 1, BB), 256>>>(wq, x);
    // v = wv * x + bv (fp32)
    k_conv<<<dim3(NN / 64, CC / 64, BB), 256>>>(wv, bv, x, v_p, CC);
    // exp(energy) via raw mma bf16 split; store rounded bf16; rowsum from rounded
    k_gram_mma<<<dim3(NN / 128, NN / 128, BB), 256, GRAM_SMEM>>>();
    // colsums of normalized attn
    k_colsum<<<dim3(NN / 512, NN / 256, BB), 256>>>();
    // fold L1 renorm into v, split to bf16 hi/lo
    k_splitv<<<(BB * CC * NN) / 256, 256>>>();
    // raw x_r sums via raw mma, 2-term
    k_xr_mma<<<dim3(NN / 128, BB), 512, XR_SMEM>>>();
    // wt conv (x - x_r fused) + BN + relu + residual
    k_final<<<dim3(NN / 64, CC / 64, BB), 256>>>(wt, bt, x, gamma, beta, rmean, rvar, out);
}

// round 11
// speedup vs baseline: 3.0351x; 1.1051x over previous
#include <cuda_runtime.h>
#include <cuda_bf16.h>
#include <cstdint>
#include <math.h>

#define BB 4
#define CC 256
#define CQ 64
#define NN 4096
#define BN_EPSF 1e-5f

static constexpr size_t NN2 = (size_t)NN * NN;

// Scratch (device globals — no allocation allowed)
__device__ __nv_bfloat16 g_qkh[(size_t)BB * NN * CQ];   // 2 MB  qk hi  [b][n][o]
__device__ __nv_bfloat16 g_qkl[(size_t)BB * NN * CQ];   // 2 MB  qk lo
__device__ float         g_v[(size_t)BB * CC * NN];     // 16 MB v[b,c,n]
__device__ __nv_bfloat16 g_vh[(size_t)BB * CC * NN];    // 8 MB  vs hi [b][c][m]
__device__ __nv_bfloat16 g_vl[(size_t)BB * CC * NN];    // 8 MB  vs lo
__device__ __nv_bfloat16 g_ah[(size_t)BB * NN * NN];    // 134 MB exp(energy) bf16 [b][n][m]
__device__ float         g_rowsum[BB * NN];             // from ROUNDED exp (consistency)
__device__ float         g_colsum[BB * NN];
__device__ float         g_xr[(size_t)BB * CC * NN];    // 16 MB raw x_r sums

// ===========================================================================
__device__ __forceinline__ uint32_t smem_u32(const void* p) {
    uint32_t a;
    asm("{ .reg .u64 t; cvta.to.shared.u64 t, %1; cvt.u32.u64 %0, t; }" : "=r"(a) : "l"(p));
    return a;
}
__device__ __forceinline__ void cp16(uint32_t dst, const void* src) {
    asm volatile("cp.async.cg.shared.global [%0], [%1], 16;" :: "r"(dst), "l"(src) : "memory");
}
__device__ __forceinline__ void cp_commit() {
    asm volatile("cp.async.commit_group;" ::: "memory");
}
template <int N> __device__ __forceinline__ void cp_wait() {
    asm volatile("cp.async.wait_group %0;" :: "n"(N) : "memory");
}
__device__ __forceinline__ void ldm4(uint32_t* r, uint32_t a) {
    asm volatile("ldmatrix.sync.aligned.m8n8.x4.shared.b16 {%0,%1,%2,%3}, [%4];"
        : "=r"(r[0]), "=r"(r[1]), "=r"(r[2]), "=r"(r[3]) : "r"(a));
}
__device__ __forceinline__ void mma16816(float* c, const uint32_t* a, uint32_t b0, uint32_t b1) {
    asm volatile("mma.sync.aligned.m16n8k16.row.col.f32.bf16.bf16.f32 "
        "{%0,%1,%2,%3}, {%4,%5,%6,%7}, {%8,%9}, {%0,%1,%2,%3};"
        : "+f"(c[0]), "+f"(c[1]), "+f"(c[2]), "+f"(c[3])
        : "r"(a[0]), "r"(a[1]), "r"(a[2]), "r"(a[3]), "r"(b0), "r"(b1));
}

// ===========================================================================
__global__ void k_init() {
    int i = blockIdx.x * blockDim.x + threadIdx.x;
    if (i < BB * NN) { g_rowsum[i] = 0.f; g_colsum[i] = 0.f; }
}

// ---------------------------------------------------------------------------
// out[b,o,n] = sum_c W[o,c] * x[b,c,n] + bias[o]   (v projection, fp32 SIMT)
__global__ void __launch_bounds__(256) k_conv(
        const float* __restrict__ W, const float* __restrict__ bias,
        const float* __restrict__ x, float* __restrict__ out, int O) {
    __shared__ float As[16][64];
    __shared__ float Bs[16][64];
    int b = blockIdx.z;
    int n0 = blockIdx.x * 64;
    int o0 = blockIdx.y * 64;
    const float* xb = x + (size_t)b * CC * NN;
    int t = threadIdx.x;
    int tx = t & 15, ty = t >> 4;
    float acc[4][4] = {};
    for (int c0 = 0; c0 < CC; c0 += 16) {
        {
            int o = t >> 2;
            int cq = (t & 3) << 2;
            float4 w4 = *reinterpret_cast<const float4*>(W + (o0 + o) * CC + c0 + cq);
            As[cq + 0][o] = w4.x; As[cq + 1][o] = w4.y;
            As[cq + 2][o] = w4.z; As[cq + 3][o] = w4.w;
            int c = t >> 4;
            int nq = (t & 15) << 2;
            *reinterpret_cast<float4*>(&Bs[c][nq]) =
                *reinterpret_cast<const float4*>(xb + (size_t)(c0 + c) * NN + n0 + nq);
        }
        __syncthreads();
        #pragma unroll
        for (int k = 0; k < 16; k++) {
            float a0 = As[k][ty * 4 + 0], a1 = As[k][ty * 4 + 1];
            float a2 = As[k][ty * 4 + 2], a3 = As[k][ty * 4 + 3];
            float b0 = Bs[k][tx * 4 + 0], b1 = Bs[k][tx * 4 + 1];
            float b2 = Bs[k][tx * 4 + 2], b3 = Bs[k][tx * 4 + 3];
            acc[0][0] += a0 * b0; acc[0][1] += a0 * b1; acc[0][2] += a0 * b2; acc[0][3] += a0 * b3;
            acc[1][0] += a1 * b0; acc[1][1] += a1 * b1; acc[1][2] += a1 * b2; acc[1][3] += a1 * b3;
            acc[2][0] += a2 * b0; acc[2][1] += a2 * b1; acc[2][2] += a2 * b2; acc[2][3] += a2 * b3;
            acc[3][0] += a3 * b0; acc[3][1] += a3 * b1; acc[3][2] += a3 * b2; acc[3][3] += a3 * b3;
        }
        __syncthreads();
    }
    #pragma unroll
    for (int i = 0; i < 4; i++) {
        int o = o0 + ty * 4 + i;
        float bv = bias ? bias[o] : 0.f;
        float4 r;
        r.x = acc[i][0] + bv; r.y = acc[i][1] + bv;
        r.z = acc[i][2] + bv; r.w = acc[i][3] + bv;
        *reinterpret_cast<float4*>(out + ((size_t)b * O + o) * NN + n0 + tx * 4) = r;
    }
}

// ---------------------------------------------------------------------------
// qk projection, written TRANSPOSED [b][n][o] as bf16 hi + residual lo
__global__ void __launch_bounds__(256) k_convq(
        const float* __restrict__ W, const float* __restrict__ x) {
    __shared__ float As[16][64];
    __shared__ float Bs[16][64];
    int b = blockIdx.z;
    int n0 = blockIdx.x * 64;
    const float* xb = x + (size_t)b * CC * NN;
    int t = threadIdx.x;
    int tx = t & 15, ty = t >> 4;
    float acc[4][4] = {};
    for (int c0 = 0; c0 < CC; c0 += 16) {
        {
            int o = t >> 2;
            int cq = (t & 3) << 2;
            float4 w4 = *reinterpret_cast<const float4*>(W + o * CC + c0 + cq);
            As[cq + 0][o] = w4.x; As[cq + 1][o] = w4.y;
            As[cq + 2][o] = w4.z; As[cq + 3][o] = w4.w;
            int c = t >> 4;
            int nq = (t & 15) << 2;
            *reinterpret_cast<float4*>(&Bs[c][nq]) =
                *reinterpret_cast<const float4*>(xb + (size_t)(c0 + c) * NN + n0 + nq);
        }
        __syncthreads();
        #pragma unroll
        for (int k = 0; k < 16; k++) {
            float a0 = As[k][ty * 4 + 0], a1 = As[k][ty * 4 + 1];
            float a2 = As[k][ty * 4 + 2], a3 = As[k][ty * 4 + 3];
            float b0 = Bs[k][tx * 4 + 0], b1 = Bs[k][tx * 4 + 1];
            float b2 = Bs[k][tx * 4 + 2], b3 = Bs[k][tx * 4 + 3];
            acc[0][0] += a0 * b0; acc[0][1] += a0 * b1; acc[0][2] += a0 * b2; acc[0][3] += a0 * b3;
            acc[1][0] += a1 * b0; acc[1][1] += a1 * b1; acc[1][2] += a1 * b2; acc[1][3] += a1 * b3;
            acc[2][0] += a2 * b0; acc[2][1] += a2 * b1; acc[2][2] += a2 * b2; acc[2][3] += a2 * b3;
            acc[3][0] += a3 * b0; acc[3][1] += a3 * b1; acc[3][2] += a3 * b2; acc[3][3] += a3 * b3;
        }
        __syncthreads();
    }
    #pragma unroll
    for (int i = 0; i < 4; i++) {
        int o = ty * 4 + i;
        #pragma unroll
        for (int j = 0; j < 4; j++) {
            int n = n0 + tx * 4 + j;
            float v = acc[i][j];
            __nv_bfloat16 h = __float2bfloat16(v);
            size_t off = ((size_t)b * NN + n) * CQ + o;
            g_qkh[off] = h;
            g_qkl[off] = __float2bfloat16(v - __bfloat162float(h));
        }
    }
}

// ---------------------------------------------------------------------------
// Gram via raw mma bf16 3-term split, SYMMETRIC: only upper-triangle block
// pairs are computed; off-diagonal tiles are stored twice (direct + transposed
// via smem), and rowsum gets row-sums (-> rowsum[n]) and col-sums (-> rowsum[m]).
// CTA 128n x 128m, 8 warps (warp 64n x 32m), K=64, 2 CTAs/SM.
#define GP 72
#define TP 136
#define GRAM_SMEM (4 * 128 * GP * 2)   // 73728 (>= transpose buffer 128*TP*2 = 34816)
__global__ void __launch_bounds__(256, 2) k_gram_mma() {
    extern __shared__ __align__(16) char smem[];
    const uint32_t sb = smem_u32(smem);
    int t = threadIdx.x, w = t >> 5, l = t & 31;
    // decode upper-triangle pair (bi <= bj) from blockIdx.x in [0, 528)
    int bi = 0, rem = blockIdx.x;
    while (rem >= 32 - bi) { rem -= 32 - bi; bi++; }
    int bj = bi + rem;
    int n0 = bi * 128;
    int m0 = bj * 128;
    bool mirror = (bi != bj);
    int b = blockIdx.y;
    const __nv_bfloat16* qh = g_qkh + (size_t)b * NN * CQ;
    const __nv_bfloat16* ql = g_qkl + (size_t)b * NN * CQ;

    // group 0: Ah (128 rows) + Bh (128 rows)
    #pragma unroll
    for (int i = 0; i < 8; i++) {
        int idx = i * 256 + t;
        int row = idx >> 3, q = idx & 7;
        if (row < 128)
            cp16(sb + 0 + (uint32_t)row * 144 + q * 16, qh + (size_t)(n0 + row) * CQ + q * 8);
        else
            cp16(sb + 36864 + (uint32_t)(row - 128) * 144 + q * 16, qh + (size_t)(m0 + row - 128) * CQ + q * 8);
    }
    cp_commit();
    // group 1: Al + Bl
    #pragma unroll
    for (int i = 0; i < 8; i++) {
        int idx = i * 256 + t;
        int row = idx >> 3, q = idx & 7;
        if (row < 128)
            cp16(sb + 18432 + (uint32_t)row * 144 + q * 16, ql + (size_t)(n0 + row) * CQ + q * 8);
        else
            cp16(sb + 55296 + (uint32_t)(row - 128) * 144 + q * 16, ql + (size_t)(m0 + row - 128) * CQ + q * 8);
    }
    cp_commit();

    int wn = w & 1;    // n half (64)
    int wm = w >> 1;   // m quarter (32)

    const uint32_t A_thr = (uint32_t)(((l & 15) * GP + (l >> 4) * 8) * 2);
    const uint32_t B_thr = (uint32_t)((((l >> 4) * 8 + (l & 7)) * GP + ((l >> 3) & 1) * 8) * 2);
    const uint32_t aBaseH = sb + 0     + (uint32_t)(wn * 64) * 144 + A_thr;
    const uint32_t aBaseL = sb + 18432 + (uint32_t)(wn * 64) * 144 + A_thr;
    const uint32_t bBaseH = sb + 36864 + (uint32_t)(wm * 32) * 144 + B_thr;
    const uint32_t bBaseL = sb + 55296 + (uint32_t)(wm * 32) * 144 + B_thr;

    float acc[4][4][4] = {};

    // Phase 1: hi*hi while lo tiles still loading
    cp_wait<1>();
    __syncthreads();
    #pragma unroll
    for (int kk = 0; kk < 4; kk++) {
        uint32_t koff = (uint32_t)(kk * 32);
        uint32_t a[4][4];
        #pragma unroll
        for (int i = 0; i < 4; i++)
            ldm4(a[i], aBaseH + (uint32_t)(i * 16) * 144 + koff);
        uint32_t bf[2][4];
        #pragma unroll
        for (int jj = 0; jj < 2; jj++)
            ldm4(bf[jj], bBaseH + (uint32_t)(jj * 16) * 144 + koff);
        #pragma unroll
        for (int i = 0; i < 4; i++)
            #pragma unroll
            for (int j = 0; j < 4; j++)
                mma16816(acc[i][j], a[i], bf[j >> 1][(j & 1) * 2], bf[j >> 1][(j & 1) * 2 + 1]);
    }
    // Phase 2: hi*lo + lo*hi
    cp_wait<0>();
    __syncthreads();
    #pragma unroll
    for (int kk = 0; kk < 4; kk++) {
        uint32_t koff = (uint32_t)(kk * 32);
        uint32_t ah[4][4], al[4][4];
        #pragma unroll
        for (int i = 0; i < 4; i++) {
            ldm4(ah[i], aBaseH + (uint32_t)(i * 16) * 144 + koff);
            ldm4(al[i], aBaseL + (uint32_t)(i * 16) * 144 + koff);
        }
        uint32_t bh[2][4], bl[2][4];
        #pragma unroll
        for (int jj = 0; jj < 2; jj++) {
            ldm4(bh[jj], bBaseH + (uint32_t)(jj * 16) * 144 + koff);
            ldm4(bl[jj], bBaseL + (uint32_t)(jj * 16) * 144 + koff);
        }
        #pragma unroll
        for (int i = 0; i < 4; i++)
            #pragma unroll
            for (int j = 0; j < 4; j++) {
                mma16816(acc[i][j], ah[i], bl[j >> 1][(j & 1) * 2], bl[j >> 1][(j & 1) * 2 + 1]);
                mma16816(acc[i][j], al[i], bh[j >> 1][(j & 1) * 2], bh[j >> 1][(j & 1) * 2 + 1]);
            }
    }
    __syncthreads();   // operands dead; smem reusable for transpose staging

    // Epilogue: exp -> round to bf16 -> store (n,m); rowsum from ROUNDED values.
    // If mirror: scatter rounded values transposed into smem, track column sums.
    __nv_bfloat16* oh = g_ah + (size_t)b * NN2;
    __nv_bfloat16* smT = reinterpret_cast<__nv_bfloat16*>(smem);
    int r0 = l >> 2;
    int cl = 2 * (l & 3);
    float cs[4][2] = {};
    #pragma unroll
    for (int i = 0; i < 4; i++) {
        int lnA = wn * 64 + i * 16 + r0;
        int lnB = lnA + 8;
        int nA = n0 + lnA;
        int nB = n0 + lnB;
        float rs0 = 0.f, rs1 = 0.f;
        #pragma unroll
        for (int j = 0; j < 4; j++) {
            int ml = wm * 32 + j * 8 + cl;
            int mcol = m0 + ml;
            __nv_bfloat162 h01, h23;
            h01.x = __float2bfloat16(__expf(acc[i][j][0]));
            h01.y = __float2bfloat16(__expf(acc[i][j][1]));
            h23.x = __float2bfloat16(__expf(acc[i][j][2]));
            h23.y = __float2bfloat16(__expf(acc[i][j][3]));
            float f0 = __bfloat162float(h01.x), f1 = __bfloat162float(h01.y);
            float f2 = __bfloat162float(h23.x), f3 = __bfloat162float(h23.y);
            rs0 += f0 + f1;
            rs1 += f2 + f3;
            cs[j][0] += f0 + f2;
            cs[j][1] += f1 + f3;
            *reinterpret_cast<__nv_bfloat162*>(oh + (size_t)nA * NN + mcol) = h01;
            *reinterpret_cast<__nv_bfloat162*>(oh + (size_t)nB * NN + mcol) = h23;
            if (mirror) {
                smT[(uint32_t)ml * TP + lnA]       = h01.x;
                smT[(uint32_t)(ml + 1) * TP + lnA] = h01.y;
                smT[(uint32_t)ml * TP + lnB]       = h23.x;
                smT[(uint32_t)(ml + 1) * TP + lnB] = h23.y;
            }
        }
        rs0 += __shfl_xor_sync(0xffffffffu, rs0, 1);
        rs0 += __shfl_xor_sync(0xffffffffu, rs0, 2);
        rs1 += __shfl_xor_sync(0xffffffffu, rs1, 1);
        rs1 += __shfl_xor_sync(0xffffffffu, rs1, 2);
        if ((l & 3) == 0) {
            atomicAdd(&g_rowsum[b * NN + nA], rs0);
            atomicAdd(&g_rowsum[b * NN + nB], rs1);
        }
    }
    if (mirror) {
        // column sums -> rowsum[m] (reduce over lanes with same l&3)
        #pragma unroll
        for (int j = 0; j < 4; j++) {
            #pragma unroll
            for (int h = 0; h < 2; h++) {
                float v = cs[j][h];
                v += __shfl_xor_sync(0xffffffffu, v, 4);
                v += __shfl_xor_sync(0xffffffffu, v, 8);
                v += __shfl_xor_sync(0xffffffffu, v, 16);
                if (l < 4)
                    atomicAdd(&g_rowsum[b * NN + m0 + wm * 32 + j * 8 + cl + h], v);
            }
        }
        __syncthreads();
        // coalesced copy-out of transposed tile: rows m0..m0+128, cols n0..n0+128
        int mr = t >> 1, hf = t & 1;
        const float4* srow = reinterpret_cast<const float4*>(smT + (uint32_t)mr * TP + hf * 64);
        float4* drow = reinterpret_cast<float4*>(oh + (size_t)(m0 + mr) * NN + n0 + hf * 64);
        #pragma unroll
        for (int q = 0; q < 8; q++) drow[q] = srow[q];
    }
}

// ---------------------------------------------------------------------------
// colsum[b,m] = sum_n attn[n,m] / rowsum[n]   (bf162 loads, 2 cols/thread)
__global__ void __launch_bounds__(256) k_colsum() {
    __shared__ float inv[256];
    int b = blockIdx.z;
    int m = blockIdx.x * 512 + 2 * threadIdx.x;
    int nbase = blockIdx.y * 256;
    inv[threadIdx.x] = 1.0f / g_rowsum[b * NN + nbase + threadIdx.x];
    __syncthreads();
    const __nv_bfloat16* ah = g_ah + (size_t)b * NN2;
    float s0 = 0.f, s1 = 0.f;
    #pragma unroll 4
    for (int i = 0; i < 256; i++) {
        __nv_bfloat162 v = *reinterpret_cast<const __nv_bfloat162*>(ah + (size_t)(nbase + i) * NN + m);
        s0 += __bfloat162float(v.x) * inv[i];
        s1 += __bfloat162float(v.y) * inv[i];
    }
    atomicAdd(&g_colsum[b * NN + m], s0);
    atomicAdd(&g_colsum[b * NN + m + 1], s1);
}

// ---------------------------------------------------------------------------
// vs = v/(1e-9+colsum[m]) -> bf16 hi/lo
__global__ void __launch_bounds__(256) k_splitv() {
    size_t i = (size_t)blockIdx.x * 256 + threadIdx.x;
    int m = (int)(i & (NN - 1));
    int b = (int)(i >> 20);
    float vs = g_v[i] / (1e-9f + g_colsum[b * NN + m]);
    __nv_bfloat16 h = __float2bfloat16(vs);
    g_vh[i] = h;
    g_vl[i] = __float2bfloat16(vs - __bfloat162float(h));
}

// ---------------------------------------------------------------------------
// x_r raw sums via raw mma, 2-term (Vh*A + Vl*A), attn hi only.
// CTA 256c x 128n, 512 threads (warp 64c x 32n), BK=64, 2-stage cp.async.
// Stage rows: Vh(256) Vl(256) Ah(128), pitch 72 bf16 (144B). Stage 92160B.
#define XP 72
#define XSTAGE (640 * XP * 2)       // 92160
#define XR_SMEM (2 * XSTAGE)        // 184320
__global__ void __launch_bounds__(512, 1) k_xr_mma() {
    extern __shared__ __align__(16) char smem[];
    const uint32_t sb = smem_u32(smem);
    int t = threadIdx.x, w = t >> 5, l = t & 31;
    int n0 = blockIdx.x * 128;
    int b = blockIdx.y;

    const __nv_bfloat16* vh = g_vh + (size_t)b * CC * NN;
    const __nv_bfloat16* vl = g_vl + (size_t)b * CC * NN;
    const __nv_bfloat16* ahp = g_ah + (size_t)b * NN2 + (size_t)n0 * NN;

    auto issue = [&](int kc) {
        uint32_t base = sb + (uint32_t)(kc & 1) * XSTAGE;
        int koff = kc * 64;
        #pragma unroll
        for (int i = 0; i < 10; i++) {
            int idx = i * 512 + t;
            int row = idx >> 3, q = idx & 7;
            const __nv_bfloat16* src;
            uint32_t rbase;
            int grow;
            if (row < 256)      { src = vh;  rbase = 0;     grow = row; }
            else if (row < 512) { src = vl;  rbase = 36864; grow = row - 256; }
            else                { src = ahp; rbase = 73728; grow = row - 512; }
            cp16(base + rbase + (uint32_t)grow * 144 + q * 16,
                 src + (size_t)grow * NN + koff + q * 8);
        }
        cp_commit();
    };

    int wc = w >> 2;   // c quarter (64)
    int wn = w & 3;    // n quarter (32)

    const uint32_t A_thr = (uint32_t)(((l & 15) * XP + (l >> 4) * 8) * 2);
    const uint32_t B_thr = (uint32_t)((((l >> 4) * 8 + (l & 7)) * XP + ((l >> 3) & 1) * 8) * 2);
    const uint32_t aOffH = 0     + (uint32_t)(wc * 64) * 144 + A_thr;
    const uint32_t aOffL = 36864 + (uint32_t)(wc * 64) * 144 + A_thr;
    const uint32_t bOff  = 73728 + (uint32_t)(wn * 32) * 144 + B_thr;

    float acc[4][4][4] = {};

    issue(0); issue(1);

    for (int kc = 0; kc < 64; kc++) {
        if (kc < 63) cp_wait<1>(); else cp_wait<0>();
        __syncthreads();
        uint32_t stg = sb + (uint32_t)(kc & 1) * XSTAGE;
        #pragma unroll
        for (int ks = 0; ks < 4; ks++) {
            uint32_t koff = (uint32_t)(ks * 32);
            uint32_t bf[2][4];
            #pragma unroll
            for (int jj = 0; jj < 2; jj++)
                ldm4(bf[jj], stg + bOff + (uint32_t)(jj * 16) * 144 + koff);
            #pragma unroll
            for (int term = 0; term < 2; term++) {
                uint32_t aB = stg + (term ? aOffL : aOffH);
                uint32_t a[4][4];
                #pragma unroll
                for (int i = 0; i < 4; i++)
                    ldm4(a[i], aB + (uint32_t)(i * 16) * 144 + koff);
                #pragma unroll
                for (int i = 0; i < 4; i++)
                    #pragma unroll
                    for (int j = 0; j < 4; j++)
                        mma16816(acc[i][j], a[i], bf[j >> 1][(j & 1) * 2], bf[j >> 1][(j & 1) * 2 + 1]);
            }
        }
        __syncthreads();
        if (kc + 2 < 64) issue(kc + 2);
    }

    // Store raw sums (scaled by 1/rowsum later in k_final)
    int r0 = l >> 2;
    int cl = 2 * (l & 3);
    #pragma unroll
    for (int i = 0; i < 4; i++) {
        int cA = wc * 64 + i * 16 + r0;
        #pragma unroll
        for (int j = 0; j < 4; j++) {
            int ncol = n0 + wn * 32 + j * 8 + cl;
            float2 v01; v01.x = acc[i][j][0]; v01.y = acc[i][j][1];
            float2 v23; v23.x = acc[i][j][2]; v23.y = acc[i][j][3];
            *reinterpret_cast<float2*>(g_xr + ((size_t)b * CC + cA) * NN + ncol) = v01;
            *reinterpret_cast<float2*>(g_xr + ((size_t)b * CC + cA + 8) * NN + ncol) = v23;
        }
    }
}

// ---------------------------------------------------------------------------
// t = wt * (x - xr_raw/rowsum) + bt ; BN inference ; out = x + relu(bn)
__global__ void __launch_bounds__(256) k_final(
        const float* __restrict__ W, const float* __restrict__ bias,
        const float* __restrict__ x,
        const float* __restrict__ gamma, const float* __restrict__ beta,
        const float* __restrict__ mean,  const float* __restrict__ var,
        float* __restrict__ out) {
    __shared__ float As[16][64];
    __shared__ float Bs[16][64];
    __shared__ float invs[64];
    int b = blockIdx.z;
    int n0 = blockIdx.x * 64;
    int o0 = blockIdx.y * 64;
    const float* xb = x + (size_t)b * CC * NN;
    int t = threadIdx.x;
    int tx = t & 15, ty = t >> 4;
    if (t < 64) invs[t] = 1.0f / g_rowsum[b * NN + n0 + t];
    __syncthreads();
    float acc[4][4] = {};
    for (int c0 = 0; c0 < CC; c0 += 16) {
        {
            int o = t >> 2;
            int cq = (t & 3) << 2;
            float4 w4 = *reinterpret_cast<const float4*>(W + (o0 + o) * CC + c0 + cq);
            As[cq + 0][o] = w4.x; As[cq + 1][o] = w4.y;
            As[cq + 2][o] = w4.z; As[cq + 3][o] = w4.w;
            int c = t >> 4;
            int nq = (t & 15) << 2;
            float4 xv = *reinterpret_cast<const float4*>(xb + (size_t)(c0 + c) * NN + n0 + nq);
            float4 rv = *reinterpret_cast<const float4*>(g_xr + ((size_t)b * CC + c0 + c) * NN + n0 + nq);
            Bs[c][nq + 0] = xv.x - rv.x * invs[nq + 0];
            Bs[c][nq + 1] = xv.y - rv.y * invs[nq + 1];
            Bs[c][nq + 2] = xv.z - rv.z * invs[nq + 2];
            Bs[c][nq + 3] = xv.w - rv.w * invs[nq + 3];
        }
        __syncthreads();
        #pragma unroll
        for (int k = 0; k < 16; k++) {
            float a0 = As[k][ty * 4 + 0], a1 = As[k][ty * 4 + 1];
            float a2 = As[k][ty * 4 + 2], a3 = As[k][ty * 4 + 3];
            float b0 = Bs[k][tx * 4 + 0], b1 = Bs[k][tx * 4 + 1];
            float b2 = Bs[k][tx * 4 + 2], b3 = Bs[k][tx * 4 + 3];
            acc[0][0] += a0 * b0; acc[0][1] += a0 * b1; acc[0][2] += a0 * b2; acc[0][3] += a0 * b3;
            acc[1][0] += a1 * b0; acc[1][1] += a1 * b1; acc[1][2] += a1 * b2; acc[1][3] += a1 * b3;
            acc[2][0] += a2 * b0; acc[2][1] += a2 * b1; acc[2][2] += a2 * b2; acc[2][3] += a2 * b3;
            acc[3][0] += a3 * b0; acc[3][1] += a3 * b1; acc[3][2] += a3 * b2; acc[3][3] += a3 * b3;
        }
        __syncthreads();
    }
    #pragma unroll
    for (int i = 0; i < 4; i++) {
        int o = o0 + ty * 4 + i;
        float s  = gamma[o] * rsqrtf(var[o] + BN_EPSF);
        float sh = beta[o] - mean[o] * s;
        float bt = bias[o];
        size_t off = ((size_t)b * CC + o) * NN + n0 + tx * 4;
        float4 xv = *reinterpret_cast<const float4*>(xb + (size_t)o * NN + n0 + tx * 4);
        float4 r;
        r.x = xv.x + fmaxf((acc[i][0] + bt) * s + sh, 0.f);
        r.y = xv.y + fmaxf((acc[i][1] + bt) * s + sh, 0.f);
        r.z = xv.z + fmaxf((acc[i][2] + bt) * s + sh, 0.f);
        r.w = xv.w + fmaxf((acc[i][3] + bt) * s + sh, 0.f);
        *reinterpret_cast<float4*>(out + off) = r;
    }
}

// ---------------------------------------------------------------------------
extern "C" void kernel_launch(void* const* d_in, const int* in_sizes, int n_in,
                              void* d_out, int out_size) {
    const float* x     = (const float*)d_in[0];
    const float* wq    = (const float*)d_in[1];
    const float* wv    = (const float*)d_in[2];
    const float* bv    = (const float*)d_in[3];
    const float* wt    = (const float*)d_in[4];
    const float* bt    = (const float*)d_in[5];
    const float* gamma = (const float*)d_in[6];
    const float* beta  = (const float*)d_in[7];
    const float* rmean = (const float*)d_in[8];
    const float* rvar  = (const float*)d_in[9];
    float* out = (float*)d_out;

    float* v_p = nullptr;
    cudaGetSymbolAddress((void**)&v_p, g_v);

    cudaFuncSetAttribute(k_gram_mma, cudaFuncAttributeMaxDynamicSharedMemorySize, GRAM_SMEM);
    cudaFuncSetAttribute(k_xr_mma,   cudaFuncAttributeMaxDynamicSharedMemorySize, XR_SMEM);

    k_init<<<(BB * NN + 255) / 256, 256>>>();
    // qk projection -> bf16 hi/lo, transposed [b][n][64]
    k_convq<<<dim3(NN / 64, 1, BB), 256>>>(wq, x);
    // v = wv * x + bv (fp32)
    k_conv<<<dim3(NN / 64, CC / 64, BB), 256>>>(wv, bv, x, v_p, CC);
    // exp(energy) via raw mma bf16 split, symmetric upper-triangle grid
    k_gram_mma<<<dim3(528, BB), 256, GRAM_SMEM>>>();
    // colsums of normalized attn
    k_colsum<<<dim3(NN / 512, NN / 256, BB), 256>>>();
    // fold L1 renorm into v, split to bf16 hi/lo
    k_splitv<<<(BB * CC * NN) / 256, 256>>>();
    // raw x_r sums via raw mma, 2-term, BK=64
    k_xr_mma<<<dim3(NN / 128, BB), 512, XR_SMEM>>>();
    // wt conv (x - x_r fused) + BN + relu + residual
    k_final<<<dim3(NN / 64, CC / 64, BB), 256>>>(wt, bt, x, gamma, beta, rmean, rvar, out);
}

// round 12
// speedup vs baseline: 3.5642x; 1.1744x over previous
#include <cuda_runtime.h>
#include <cuda_bf16.h>
#include <cuda_fp16.h>
#include <cstdint>
#include <math.h>

#define BB 4
#define CC 256
#define CQ 64
#define NN 4096
#define BN_EPSF 1e-5f

static constexpr size_t NN2 = (size_t)NN * NN;

// Scratch (device globals — no allocation allowed)
__device__ __nv_bfloat16 g_qkh[(size_t)BB * NN * CQ];   // 2 MB  qk hi  [b][n][o]
__device__ __nv_bfloat16 g_qkl[(size_t)BB * NN * CQ];   // 2 MB  qk lo
__device__ float         g_v[(size_t)BB * CC * NN];     // 16 MB v[b,c,n]
__device__ __half        g_vh[(size_t)BB * CC * NN];    // 8 MB  vs fp16 [b][c][m]
__device__ __half        g_ah[(size_t)BB * NN * NN];    // 134 MB exp(E - D[n]) fp16 [b][n][m]
__device__ float         g_diag[BB * NN];               // exact |qk_n|^2 (per-row shift)
__device__ float         g_rowsum[BB * NN];             // from ROUNDED exp (consistency)
__device__ float         g_colsum[BB * NN];
__device__ float         g_xr[(size_t)BB * CC * NN];    // 16 MB raw x_r sums

// ===========================================================================
__device__ __forceinline__ uint32_t smem_u32(const void* p) {
    uint32_t a;
    asm("{ .reg .u64 t; cvta.to.shared.u64 t, %1; cvt.u32.u64 %0, t; }" : "=r"(a) : "l"(p));
    return a;
}
__device__ __forceinline__ void cp16(uint32_t dst, const void* src) {
    asm volatile("cp.async.cg.shared.global [%0], [%1], 16;" :: "r"(dst), "l"(src) : "memory");
}
__device__ __forceinline__ void cp_commit() {
    asm volatile("cp.async.commit_group;" ::: "memory");
}
template <int N> __device__ __forceinline__ void cp_wait() {
    asm volatile("cp.async.wait_group %0;" :: "n"(N) : "memory");
}
__device__ __forceinline__ void ldm4(uint32_t* r, uint32_t a) {
    asm volatile("ldmatrix.sync.aligned.m8n8.x4.shared.b16 {%0,%1,%2,%3}, [%4];"
        : "=r"(r[0]), "=r"(r[1]), "=r"(r[2]), "=r"(r[3]) : "r"(a));
}
__device__ __forceinline__ void mma16816(float* c, const uint32_t* a, uint32_t b0, uint32_t b1) {
    asm volatile("mma.sync.aligned.m16n8k16.row.col.f32.bf16.bf16.f32 "
        "{%0,%1,%2,%3}, {%4,%5,%6,%7}, {%8,%9}, {%0,%1,%2,%3};"
        : "+f"(c[0]), "+f"(c[1]), "+f"(c[2]), "+f"(c[3])
        : "r"(a[0]), "r"(a[1]), "r"(a[2]), "r"(a[3]), "r"(b0), "r"(b1));
}
__device__ __forceinline__ void mma16816h(float* c, const uint32_t* a, uint32_t b0, uint32_t b1) {
    asm volatile("mma.sync.aligned.m16n8k16.row.col.f32.f16.f16.f32 "
        "{%0,%1,%2,%3}, {%4,%5,%6,%7}, {%8,%9}, {%0,%1,%2,%3};"
        : "+f"(c[0]), "+f"(c[1]), "+f"(c[2]), "+f"(c[3])
        : "r"(a[0]), "r"(a[1]), "r"(a[2]), "r"(a[3]), "r"(b0), "r"(b1));
}

// ===========================================================================
__global__ void k_init() {
    int i = blockIdx.x * blockDim.x + threadIdx.x;
    if (i < BB * NN) { g_rowsum[i] = 0.f; g_colsum[i] = 0.f; g_diag[i] = 0.f; }
}

// ---------------------------------------------------------------------------
// out[b,o,n] = sum_c W[o,c] * x[b,c,n] + bias[o]   (v projection, fp32 SIMT)
__global__ void __launch_bounds__(256) k_conv(
        const float* __restrict__ W, const float* __restrict__ bias,
        const float* __restrict__ x, float* __restrict__ out, int O) {
    __shared__ float As[16][64];
    __shared__ float Bs[16][64];
    int b = blockIdx.z;
    int n0 = blockIdx.x * 64;
    int o0 = blockIdx.y * 64;
    const float* xb = x + (size_t)b * CC * NN;
    int t = threadIdx.x;
    int tx = t & 15, ty = t >> 4;
    float acc[4][4] = {};
    for (int c0 = 0; c0 < CC; c0 += 16) {
        {
            int o = t >> 2;
            int cq = (t & 3) << 2;
            float4 w4 = *reinterpret_cast<const float4*>(W + (o0 + o) * CC + c0 + cq);
            As[cq + 0][o] = w4.x; As[cq + 1][o] = w4.y;
            As[cq + 2][o] = w4.z; As[cq + 3][o] = w4.w;
            int c = t >> 4;
            int nq = (t & 15) << 2;
            *reinterpret_cast<float4*>(&Bs[c][nq]) =
                *reinterpret_cast<const float4*>(xb + (size_t)(c0 + c) * NN + n0 + nq);
        }
        __syncthreads();
        #pragma unroll
        for (int k = 0; k < 16; k++) {
            float a0 = As[k][ty * 4 + 0], a1 = As[k][ty * 4 + 1];
            float a2 = As[k][ty * 4 + 2], a3 = As[k][ty * 4 + 3];
            float b0 = Bs[k][tx * 4 + 0], b1 = Bs[k][tx * 4 + 1];
            float b2 = Bs[k][tx * 4 + 2], b3 = Bs[k][tx * 4 + 3];
            acc[0][0] += a0 * b0; acc[0][1] += a0 * b1; acc[0][2] += a0 * b2; acc[0][3] += a0 * b3;
            acc[1][0] += a1 * b0; acc[1][1] += a1 * b1; acc[1][2] += a1 * b2; acc[1][3] += a1 * b3;
            acc[2][0] += a2 * b0; acc[2][1] += a2 * b1; acc[2][2] += a2 * b2; acc[2][3] += a2 * b3;
            acc[3][0] += a3 * b0; acc[3][1] += a3 * b1; acc[3][2] += a3 * b2; acc[3][3] += a3 * b3;
        }
        __syncthreads();
    }
    #pragma unroll
    for (int i = 0; i < 4; i++) {
        int o = o0 + ty * 4 + i;
        float bv = bias ? bias[o] : 0.f;
        float4 r;
        r.x = acc[i][0] + bv; r.y = acc[i][1] + bv;
        r.z = acc[i][2] + bv; r.w = acc[i][3] + bv;
        *reinterpret_cast<float4*>(out + ((size_t)b * O + o) * NN + n0 + tx * 4) = r;
    }
}

// ---------------------------------------------------------------------------
// qk projection, written TRANSPOSED [b][n][o] as bf16 hi + residual lo.
// Also accumulates the exact diagonal D[n] = sum_o qk[n,o]^2 (per-row shift).
__global__ void __launch_bounds__(256) k_convq(
        const float* __restrict__ W, const float* __restrict__ x) {
    __shared__ float As[16][64];
    __shared__ float Bs[16][64];
    int b = blockIdx.z;
    int n0 = blockIdx.x * 64;
    const float* xb = x + (size_t)b * CC * NN;
    int t = threadIdx.x;
    int tx = t & 15, ty = t >> 4;
    float acc[4][4] = {};
    for (int c0 = 0; c0 < CC; c0 += 16) {
        {
            int o = t >> 2;
            int cq = (t & 3) << 2;
            float4 w4 = *reinterpret_cast<const float4*>(W + o * CC + c0 + cq);
            As[cq + 0][o] = w4.x; As[cq + 1][o] = w4.y;
            As[cq + 2][o] = w4.z; As[cq + 3][o] = w4.w;
            int c = t >> 4;
            int nq = (t & 15) << 2;
            *reinterpret_cast<float4*>(&Bs[c][nq]) =
                *reinterpret_cast<const float4*>(xb + (size_t)(c0 + c) * NN + n0 + nq);
        }
        __syncthreads();
        #pragma unroll
        for (int k = 0; k < 16; k++) {
            float a0 = As[k][ty * 4 + 0], a1 = As[k][ty * 4 + 1];
            float a2 = As[k][ty * 4 + 2], a3 = As[k][ty * 4 + 3];
            float b0 = Bs[k][tx * 4 + 0], b1 = Bs[k][tx * 4 + 1];
            float b2 = Bs[k][tx * 4 + 2], b3 = Bs[k][tx * 4 + 3];
            acc[0][0] += a0 * b0; acc[0][1] += a0 * b1; acc[0][2] += a0 * b2; acc[0][3] += a0 * b3;
            acc[1][0] += a1 * b0; acc[1][1] += a1 * b1; acc[1][2] += a1 * b2; acc[1][3] += a1 * b3;
            acc[2][0] += a2 * b0; acc[2][1] += a2 * b1; acc[2][2] += a2 * b2; acc[2][3] += a2 * b3;
            acc[3][0] += a3 * b0; acc[3][1] += a3 * b1; acc[3][2] += a3 * b2; acc[3][3] += a3 * b3;
        }
        __syncthreads();
    }
    float sq[4] = {0.f, 0.f, 0.f, 0.f};
    #pragma unroll
    for (int i = 0; i < 4; i++) {
        int o = ty * 4 + i;
        #pragma unroll
        for (int j = 0; j < 4; j++) {
            int n = n0 + tx * 4 + j;
            float v = acc[i][j];
            sq[j] += v * v;
            __nv_bfloat16 h = __float2bfloat16(v);
            size_t off = ((size_t)b * NN + n) * CQ + o;
            g_qkh[off] = h;
            g_qkl[off] = __float2bfloat16(v - __bfloat162float(h));
        }
    }
    #pragma unroll
    for (int j = 0; j < 4; j++)
        atomicAdd(&g_diag[b * NN + n0 + tx * 4 + j], sq[j]);
}

// ---------------------------------------------------------------------------
// Gram via raw mma bf16 3-term split, SYMMETRIC upper-triangle grid.
// Stores fp16 exp(E - D[row]) — per-row shift keeps fp16 in range; all
// downstream normalization is shift-invariant. Off-diagonal CTAs also store
// the transposed tile with the COLUMN's shift (second expf) via smem staging.
// rowsum accumulated from the ROUNDED fp16 values (consistency).
#define GP 72
#define TP 136
#define GRAM_SMEM (4 * 128 * GP * 2 + 1024)   // operands 73728 + D arrays
__global__ void __launch_bounds__(256, 2) k_gram_mma() {
    extern __shared__ __align__(16) char smem[];
    const uint32_t sb = smem_u32(smem);
    int t = threadIdx.x, w = t >> 5, l = t & 31;
    // decode upper-triangle pair (bi <= bj) from blockIdx.x in [0, 528)
    int bi = 0, rem = blockIdx.x;
    while (rem >= 32 - bi) { rem -= 32 - bi; bi++; }
    int bj = bi + rem;
    int n0 = bi * 128;
    int m0 = bj * 128;
    bool mirror = (bi != bj);
    int b = blockIdx.y;
    const __nv_bfloat16* qh = g_qkh + (size_t)b * NN * CQ;
    const __nv_bfloat16* ql = g_qkl + (size_t)b * NN * CQ;
    float* sD = reinterpret_cast<float*>(smem + 73728);   // [0..128) D[n], [128..256) D[m]

    // group 0: Ah (128 rows) + Bh (128 rows)
    #pragma unroll
    for (int i = 0; i < 8; i++) {
        int idx = i * 256 + t;
        int row = idx >> 3, q = idx & 7;
        if (row < 128)
            cp16(sb + 0 + (uint32_t)row * 144 + q * 16, qh + (size_t)(n0 + row) * CQ + q * 8);
        else
            cp16(sb + 36864 + (uint32_t)(row - 128) * 144 + q * 16, qh + (size_t)(m0 + row - 128) * CQ + q * 8);
    }
    cp_commit();
    // group 1: Al + Bl
    #pragma unroll
    for (int i = 0; i < 8; i++) {
        int idx = i * 256 + t;
        int row = idx >> 3, q = idx & 7;
        if (row < 128)
            cp16(sb + 18432 + (uint32_t)row * 144 + q * 16, ql + (size_t)(n0 + row) * CQ + q * 8);
        else
            cp16(sb + 55296 + (uint32_t)(row - 128) * 144 + q * 16, ql + (size_t)(m0 + row - 128) * CQ + q * 8);
    }
    cp_commit();
    // stage diagonal shifts
    if (t < 128) sD[t] = g_diag[b * NN + n0 + t];
    else         sD[t] = g_diag[b * NN + m0 + (t - 128)];

    int wn = w & 1;    // n half (64)
    int wm = w >> 1;   // m quarter (32)

    const uint32_t A_thr = (uint32_t)(((l & 15) * GP + (l >> 4) * 8) * 2);
    const uint32_t B_thr = (uint32_t)((((l >> 4) * 8 + (l & 7)) * GP + ((l >> 3) & 1) * 8) * 2);
    const uint32_t aBaseH = sb + 0     + (uint32_t)(wn * 64) * 144 + A_thr;
    const uint32_t aBaseL = sb + 18432 + (uint32_t)(wn * 64) * 144 + A_thr;
    const uint32_t bBaseH = sb + 36864 + (uint32_t)(wm * 32) * 144 + B_thr;
    const uint32_t bBaseL = sb + 55296 + (uint32_t)(wm * 32) * 144 + B_thr;

    float acc[4][4][4] = {};

    // Phase 1: hi*hi while lo tiles still loading
    cp_wait<1>();
    __syncthreads();
    #pragma unroll
    for (int kk = 0; kk < 4; kk++) {
        uint32_t koff = (uint32_t)(kk * 32);
        uint32_t a[4][4];
        #pragma unroll
        for (int i = 0; i < 4; i++)
            ldm4(a[i], aBaseH + (uint32_t)(i * 16) * 144 + koff);
        uint32_t bf[2][4];
        #pragma unroll
        for (int jj = 0; jj < 2; jj++)
            ldm4(bf[jj], bBaseH + (uint32_t)(jj * 16) * 144 + koff);
        #pragma unroll
        for (int i = 0; i < 4; i++)
            #pragma unroll
            for (int j = 0; j < 4; j++)
                mma16816(acc[i][j], a[i], bf[j >> 1][(j & 1) * 2], bf[j >> 1][(j & 1) * 2 + 1]);
    }
    // Phase 2: hi*lo + lo*hi
    cp_wait<0>();
    __syncthreads();
    #pragma unroll
    for (int kk = 0; kk < 4; kk++) {
        uint32_t koff = (uint32_t)(kk * 32);
        uint32_t ah[4][4], al[4][4];
        #pragma unroll
        for (int i = 0; i < 4; i++) {
            ldm4(ah[i], aBaseH + (uint32_t)(i * 16) * 144 + koff);
            ldm4(al[i], aBaseL + (uint32_t)(i * 16) * 144 + koff);
        }
        uint32_t bh[2][4], bl[2][4];
        #pragma unroll
        for (int jj = 0; jj < 2; jj++) {
            ldm4(bh[jj], bBaseH + (uint32_t)(jj * 16) * 144 + koff);
            ldm4(bl[jj], bBaseL + (uint32_t)(jj * 16) * 144 + koff);
        }
        #pragma unroll
        for (int i = 0; i < 4; i++)
            #pragma unroll
            for (int j = 0; j < 4; j++) {
                mma16816(acc[i][j], ah[i], bl[j >> 1][(j & 1) * 2], bl[j >> 1][(j & 1) * 2 + 1]);
                mma16816(acc[i][j], al[i], bh[j >> 1][(j & 1) * 2], bh[j >> 1][(j & 1) * 2 + 1]);
            }
    }
    __syncthreads();   // operands dead; smem reusable for transpose staging

    // Epilogue
    __half* oh = g_ah + (size_t)b * NN2;
    __half* smT = reinterpret_cast<__half*>(smem);
    int r0 = l >> 2;
    int cl = 2 * (l & 3);
    float cs[4][2] = {};
    #pragma unroll
    for (int i = 0; i < 4; i++) {
        int lnA = wn * 64 + i * 16 + r0;
        int lnB = lnA + 8;
        int nA = n0 + lnA;
        int nB = n0 + lnB;
        float DnA = sD[lnA], DnB = sD[lnB];
        float rs0 = 0.f, rs1 = 0.f;
        #pragma unroll
        for (int j = 0; j < 4; j++) {
            int ml = wm * 32 + j * 8 + cl;
            int mcol = m0 + ml;
            __half2 h01, h23;
            h01.x = __float2half(__expf(acc[i][j][0] - DnA));
            h01.y = __float2half(__expf(acc[i][j][1] - DnA));
            h23.x = __float2half(__expf(acc[i][j][2] - DnB));
            h23.y = __float2half(__expf(acc[i][j][3] - DnB));
            rs0 += __half2float(h01.x) + __half2float(h01.y);
            rs1 += __half2float(h23.x) + __half2float(h23.y);
            *reinterpret_cast<__half2*>(oh + (size_t)nA * NN + mcol) = h01;
            *reinterpret_cast<__half2*>(oh + (size_t)nB * NN + mcol) = h23;
            if (mirror) {
                float DmA = sD[128 + ml], DmB = sD[128 + ml + 1];
                __half m00 = __float2half(__expf(acc[i][j][0] - DmA));
                __half m01 = __float2half(__expf(acc[i][j][1] - DmB));
                __half m10 = __float2half(__expf(acc[i][j][2] - DmA));
                __half m11 = __float2half(__expf(acc[i][j][3] - DmB));
                cs[j][0] += __half2float(m00) + __half2float(m10);
                cs[j][1] += __half2float(m01) + __half2float(m11);
                smT[(uint32_t)ml * TP + lnA]       = m00;
                smT[(uint32_t)(ml + 1) * TP + lnA] = m01;
                smT[(uint32_t)ml * TP + lnB]       = m10;
                smT[(uint32_t)(ml + 1) * TP + lnB] = m11;
            }
        }
        rs0 += __shfl_xor_sync(0xffffffffu, rs0, 1);
        rs0 += __shfl_xor_sync(0xffffffffu, rs0, 2);
        rs1 += __shfl_xor_sync(0xffffffffu, rs1, 1);
        rs1 += __shfl_xor_sync(0xffffffffu, rs1, 2);
        if ((l & 3) == 0) {
            atomicAdd(&g_rowsum[b * NN + nA], rs0);
            atomicAdd(&g_rowsum[b * NN + nB], rs1);
        }
    }
    if (mirror) {
        // column sums of the COLUMN-shifted values -> rowsum[m]
        #pragma unroll
        for (int j = 0; j < 4; j++) {
            #pragma unroll
            for (int h = 0; h < 2; h++) {
                float v = cs[j][h];
                v += __shfl_xor_sync(0xffffffffu, v, 4);
                v += __shfl_xor_sync(0xffffffffu, v, 8);
                v += __shfl_xor_sync(0xffffffffu, v, 16);
                if (l < 4)
                    atomicAdd(&g_rowsum[b * NN + m0 + wm * 32 + j * 8 + cl + h], v);
            }
        }
        __syncthreads();
        // coalesced copy-out of transposed tile
        int mr = t >> 1, hf = t & 1;
        const float4* srow = reinterpret_cast<const float4*>(smT + (uint32_t)mr * TP + hf * 64);
        float4* drow = reinterpret_cast<float4*>(oh + (size_t)(m0 + mr) * NN + n0 + hf * 64);
        #pragma unroll
        for (int q = 0; q < 8; q++) drow[q] = srow[q];
    }
}

// ---------------------------------------------------------------------------
// colsum[b,m] = sum_n attn[n,m] / rowsum[n]   (half2 loads, 2 cols/thread)
__global__ void __launch_bounds__(256) k_colsum() {
    __shared__ float inv[256];
    int b = blockIdx.z;
    int m = blockIdx.x * 512 + 2 * threadIdx.x;
    int nbase = blockIdx.y * 256;
    inv[threadIdx.x] = 1.0f / g_rowsum[b * NN + nbase + threadIdx.x];
    __syncthreads();
    const __half* ah = g_ah + (size_t)b * NN2;
    float s0 = 0.f, s1 = 0.f;
    #pragma unroll 4
    for (int i = 0; i < 256; i++) {
        __half2 v = *reinterpret_cast<const __half2*>(ah + (size_t)(nbase + i) * NN + m);
        s0 += __half2float(v.x) * inv[i];
        s1 += __half2float(v.y) * inv[i];
    }
    atomicAdd(&g_colsum[b * NN + m], s0);
    atomicAdd(&g_colsum[b * NN + m + 1], s1);
}

// ---------------------------------------------------------------------------
// vs = v/(1e-9+colsum[m]) -> fp16 (single precision term)
__global__ void __launch_bounds__(256) k_splitv() {
    size_t i = (size_t)blockIdx.x * 256 + threadIdx.x;
    int m = (int)(i & (NN - 1));
    int b = (int)(i >> 20);
    float vs = g_v[i] / (1e-9f + g_colsum[b * NN + m]);
    g_vh[i] = __float2half(vs);
}

// ---------------------------------------------------------------------------
// x_r raw sums via raw mma fp16, SINGLE term.
// CTA 128c x 256n, 256 threads (8 warps of 64c x 64n), BK=64, 3-stage cp.async.
// Stage rows: Vh(128) Ah(256), pitch 72 halfs (144B). Stage 55296B.
#define XP 72
#define XSTAGE (384 * XP * 2)       // 55296
#define XR_SMEM (3 * XSTAGE)        // 165888
__global__ void __launch_bounds__(256, 1) k_xr_mma() {
    extern __shared__ __align__(16) char smem[];
    const uint32_t sb = smem_u32(smem);
    int t = threadIdx.x, w = t >> 5, l = t & 31;
    int n0 = blockIdx.x * 256;
    int c0 = blockIdx.y * 128;
    int b = blockIdx.z;

    const __half* vh = g_vh + (size_t)b * CC * NN + (size_t)c0 * NN;
    const __half* ahp = g_ah + (size_t)b * NN2 + (size_t)n0 * NN;

    auto issue = [&](int kc) {
        uint32_t base = sb + (uint32_t)(kc % 3) * XSTAGE;
        int koff = kc * 64;
        #pragma unroll
        for (int i = 0; i < 12; i++) {
            int idx = i * 256 + t;
            int row = idx >> 3, q = idx & 7;
            if (row < 128)
                cp16(base + (uint32_t)row * 144 + q * 16,
                     vh + (size_t)row * NN + koff + q * 8);
            else
                cp16(base + 18432 + (uint32_t)(row - 128) * 144 + q * 16,
                     ahp + (size_t)(row - 128) * NN + koff + q * 8);
        }
        cp_commit();
    };

    int wc = w >> 2;   // c half (64)
    int wn = w & 3;    // n quarter (64)

    const uint32_t A_thr = (uint32_t)(((l & 15) * XP + (l >> 4) * 8) * 2);
    const uint32_t B_thr = (uint32_t)((((l >> 4) * 8 + (l & 7)) * XP + ((l >> 3) & 1) * 8) * 2);
    const uint32_t aOff = 0     + (uint32_t)(wc * 64) * 144 + A_thr;
    const uint32_t bOff = 18432 + (uint32_t)(wn * 64) * 144 + B_thr;

    float acc[4][8][4] = {};

    issue(0); issue(1); issue(2);

    for (int kc = 0; kc < 64; kc++) {
        if (kc < 62) cp_wait<2>();
        else if (kc == 62) cp_wait<1>();
        else cp_wait<0>();
        __syncthreads();
        uint32_t stg = sb + (uint32_t)(kc % 3) * XSTAGE;
        #pragma unroll
        for (int ks = 0; ks < 4; ks++) {
            uint32_t koff = (uint32_t)(ks * 32);
            uint32_t bf[4][4];
            #pragma unroll
            for (int jj = 0; jj < 4; jj++)
                ldm4(bf[jj], stg + bOff + (uint32_t)(jj * 16) * 144 + koff);
            uint32_t a[4][4];
            #pragma unroll
            for (int i = 0; i < 4; i++)
                ldm4(a[i], stg + aOff + (uint32_t)(i * 16) * 144 + koff);
            #pragma unroll
            for (int i = 0; i < 4; i++)
                #pragma unroll
                for (int j = 0; j < 8; j++)
                    mma16816h(acc[i][j], a[i], bf[j >> 1][(j & 1) * 2], bf[j >> 1][(j & 1) * 2 + 1]);
        }
        __syncthreads();
        if (kc + 3 < 64) issue(kc + 3);
    }

    // Store raw sums (scaled by 1/rowsum later in k_final)
    int r0 = l >> 2;
    int cl = 2 * (l & 3);
    #pragma unroll
    for (int i = 0; i < 4; i++) {
        int cA = c0 + wc * 64 + i * 16 + r0;
        #pragma unroll
        for (int j = 0; j < 8; j++) {
            int ncol = n0 + wn * 64 + j * 8 + cl;
            float2 v01; v01.x = acc[i][j][0]; v01.y = acc[i][j][1];
            float2 v23; v23.x = acc[i][j][2]; v23.y = acc[i][j][3];
            *reinterpret_cast<float2*>(g_xr + ((size_t)b * CC + cA) * NN + ncol) = v01;
            *reinterpret_cast<float2*>(g_xr + ((size_t)b * CC + cA + 8) * NN + ncol) = v23;
        }
    }
}

// ---------------------------------------------------------------------------
// t = wt * (x - xr_raw/rowsum) + bt ; BN inference ; out = x + relu(bn)
__global__ void __launch_bounds__(256) k_final(
        const float* __restrict__ W, const float* __restrict__ bias,
        const float* __restrict__ x,
        const float* __restrict__ gamma, const float* __restrict__ beta,
        const float* __restrict__ mean,  const float* __restrict__ var,
        float* __restrict__ out) {
    __shared__ float As[16][64];
    __shared__ float Bs[16][64];
    __shared__ float invs[64];
    int b = blockIdx.z;
    int n0 = blockIdx.x * 64;
    int o0 = blockIdx.y * 64;
    const float* xb = x + (size_t)b * CC * NN;
    int t = threadIdx.x;
    int tx = t & 15, ty = t >> 4;
    if (t < 64) invs[t] = 1.0f / g_rowsum[b * NN + n0 + t];
    __syncthreads();
    float acc[4][4] = {};
    for (int c0 = 0; c0 < CC; c0 += 16) {
        {
            int o = t >> 2;
            int cq = (t & 3) << 2;
            float4 w4 = *reinterpret_cast<const float4*>(W + (o0 + o) * CC + c0 + cq);
            As[cq + 0][o] = w4.x; As[cq + 1][o] = w4.y;
            As[cq + 2][o] = w4.z; As[cq + 3][o] = w4.w;
            int c = t >> 4;
            int nq = (t & 15) << 2;
            float4 xv = *reinterpret_cast<const float4*>(xb + (size_t)(c0 + c) * NN + n0 + nq);
            float4 rv = *reinterpret_cast<const float4*>(g_xr + ((size_t)b * CC + c0 + c) * NN + n0 + nq);
            Bs[c][nq + 0] = xv.x - rv.x * invs[nq + 0];
            Bs[c][nq + 1] = xv.y - rv.y * invs[nq + 1];
            Bs[c][nq + 2] = xv.z - rv.z * invs[nq + 2];
            Bs[c][nq + 3] = xv.w - rv.w * invs[nq + 3];
        }
        __syncthreads();
        #pragma unroll
        for (int k = 0; k < 16; k++) {
            float a0 = As[k][ty * 4 + 0], a1 = As[k][ty * 4 + 1];
            float a2 = As[k][ty * 4 + 2], a3 = As[k][ty * 4 + 3];
            float b0 = Bs[k][tx * 4 + 0], b1 = Bs[k][tx * 4 + 1];
            float b2 = Bs[k][tx * 4 + 2], b3 = Bs[k][tx * 4 + 3];
            acc[0][0] += a0 * b0; acc[0][1] += a0 * b1; acc[0][2] += a0 * b2; acc[0][3] += a0 * b3;
            acc[1][0] += a1 * b0; acc[1][1] += a1 * b1; acc[1][2] += a1 * b2; acc[1][3] += a1 * b3;
            acc[2][0] += a2 * b0; acc[2][1] += a2 * b1; acc[2][2] += a2 * b2; acc[2][3] += a2 * b3;
            acc[3][0] += a3 * b0; acc[3][1] += a3 * b1; acc[3][2] += a3 * b2; acc[3][3] += a3 * b3;
        }
        __syncthreads();
    }
    #pragma unroll
    for (int i = 0; i < 4; i++) {
        int o = o0 + ty * 4 + i;
        float s  = gamma[o] * rsqrtf(var[o] + BN_EPSF);
        float sh = beta[o] - mean[o] * s;
        float bt = bias[o];
        size_t off = ((size_t)b * CC + o) * NN + n0 + tx * 4;
        float4 xv = *reinterpret_cast<const float4*>(xb + (size_t)o * NN + n0 + tx * 4);
        float4 r;
        r.x = xv.x + fmaxf((acc[i][0] + bt) * s + sh, 0.f);
        r.y = xv.y + fmaxf((acc[i][1] + bt) * s + sh, 0.f);
        r.z = xv.z + fmaxf((acc[i][2] + bt) * s + sh, 0.f);
        r.w = xv.w + fmaxf((acc[i][3] + bt) * s + sh, 0.f);
        *reinterpret_cast<float4*>(out + off) = r;
    }
}

// ---------------------------------------------------------------------------
extern "C" void kernel_launch(void* const* d_in, const int* in_sizes, int n_in,
                              void* d_out, int out_size) {
    const float* x     = (const float*)d_in[0];
    const float* wq    = (const float*)d_in[1];
    const float* wv    = (const float*)d_in[2];
    const float* bv    = (const float*)d_in[3];
    const float* wt    = (const float*)d_in[4];
    const float* bt    = (const float*)d_in[5];
    const float* gamma = (const float*)d_in[6];
    const float* beta  = (const float*)d_in[7];
    const float* rmean = (const float*)d_in[8];
    const float* rvar  = (const float*)d_in[9];
    float* out = (float*)d_out;

    float* v_p = nullptr;
    cudaGetSymbolAddress((void**)&v_p, g_v);

    cudaFuncSetAttribute(k_gram_mma, cudaFuncAttributeMaxDynamicSharedMemorySize, GRAM_SMEM);
    cudaFuncSetAttribute(k_xr_mma,   cudaFuncAttributeMaxDynamicSharedMemorySize, XR_SMEM);

    k_init<<<(BB * NN + 255) / 256, 256>>>();
    // qk projection -> bf16 hi/lo + exact diagonal shift D[n]
    k_convq<<<dim3(NN / 64, 1, BB), 256>>>(wq, x);
    // v = wv * x + bv (fp32)
    k_conv<<<dim3(NN / 64, CC / 64, BB), 256>>>(wv, bv, x, v_p, CC);
    // exp(E - D[row]) fp16, symmetric upper-triangle grid
    k_gram_mma<<<dim3(528, BB), 256, GRAM_SMEM>>>();
    // colsums of normalized attn
    k_colsum<<<dim3(NN / 512, NN / 256, BB), 256>>>();
    // fold L1 renorm into v -> fp16
    k_splitv<<<(BB * CC * NN) / 256, 256>>>();
    // raw x_r sums via fp16 mma, single term
    k_xr_mma<<<dim3(NN / 256, CC / 128, BB), 256, XR_SMEM>>>();
    // wt conv (x - x_r fused) + BN + relu + residual
    k_final<<<dim3(NN / 64, CC / 64, BB), 256>>>(wt, bt, x, gamma, beta, rmean, rvar, out);
}

// round 13
// speedup vs baseline: 3.8248x; 1.0731x over previous
#include <cuda_runtime.h>
#include <cuda.h>
#include <cuda_bf16.h>
#include <cuda_fp16.h>
#include <cstdint>
#include <math.h>

#define BB 4
#define CC 256
#define CQ 64
#define NN 4096
#define BN_EPSF 1e-5f

static constexpr size_t NN2 = (size_t)NN * NN;

// Scratch (device globals — no allocation allowed)
__device__ __nv_bfloat16 g_qkh[(size_t)BB * NN * CQ];   // 2 MB  qk hi  [b][n][o]
__device__ __nv_bfloat16 g_qkl[(size_t)BB * NN * CQ];   // 2 MB  qk lo
__device__ float         g_v[(size_t)BB * CC * NN];     // 16 MB v[b,c,n]
__device__ __half        g_vh[(size_t)BB * CC * NN];    // 8 MB  vs fp16 [b][c][m]
__device__ __half        g_ah[(size_t)BB * NN * NN];    // 134 MB exp(E - D[n]) fp16 [b][n][m]
__device__ float         g_diag[BB * NN];               // exact |qk_n|^2 (per-row shift)
__device__ float         g_rowsum[BB * NN];             // from ROUNDED exp (consistency)
__device__ float         g_colsum[BB * NN];
__device__ float         g_xr[(size_t)BB * CC * NN];    // 16 MB raw x_r sums

// ===========================================================================
__device__ __forceinline__ uint32_t smem_u32(const void* p) {
    uint32_t a;
    asm("{ .reg .u64 t; cvta.to.shared.u64 t, %1; cvt.u32.u64 %0, t; }" : "=r"(a) : "l"(p));
    return a;
}
__device__ __forceinline__ void ldm4(uint32_t* r, uint32_t a) {
    asm volatile("ldmatrix.sync.aligned.m8n8.x4.shared.b16 {%0,%1,%2,%3}, [%4];"
        : "=r"(r[0]), "=r"(r[1]), "=r"(r[2]), "=r"(r[3]) : "r"(a));
}
__device__ __forceinline__ void mma16816(float* c, const uint32_t* a, uint32_t b0, uint32_t b1) {
    asm volatile("mma.sync.aligned.m16n8k16.row.col.f32.bf16.bf16.f32 "
        "{%0,%1,%2,%3}, {%4,%5,%6,%7}, {%8,%9}, {%0,%1,%2,%3};"
        : "+f"(c[0]), "+f"(c[1]), "+f"(c[2]), "+f"(c[3])
        : "r"(a[0]), "r"(a[1]), "r"(a[2]), "r"(a[3]), "r"(b0), "r"(b1));
}
__device__ __forceinline__ void mma16816h(float* c, const uint32_t* a, uint32_t b0, uint32_t b1) {
    asm volatile("mma.sync.aligned.m16n8k16.row.col.f32.f16.f16.f32 "
        "{%0,%1,%2,%3}, {%4,%5,%6,%7}, {%8,%9}, {%0,%1,%2,%3};"
        : "+f"(c[0]), "+f"(c[1]), "+f"(c[2]), "+f"(c[3])
        : "r"(a[0]), "r"(a[1]), "r"(a[2]), "r"(a[3]), "r"(b0), "r"(b1));
}
__device__ __forceinline__ void mbar_init(uint32_t a, uint32_t cnt) {
    asm volatile("mbarrier.init.shared.b64 [%0], %1;" :: "r"(a), "r"(cnt) : "memory");
}
__device__ __forceinline__ void mbar_expect(uint32_t a, uint32_t bytes) {
    asm volatile("mbarrier.arrive.expect_tx.shared.b64 _, [%0], %1;"
        :: "r"(a), "r"(bytes) : "memory");
}
__device__ __forceinline__ void mbar_wait(uint32_t a, uint32_t par) {
    asm volatile(
        "{\n\t.reg .pred P1;\n\t"
        "WL%=:\n\t"
        "mbarrier.try_wait.parity.acquire.cta.shared::cta.b64 P1, [%0], %1, 0x989680;\n\t"
        "@P1 bra.uni WD%=;\n\t"
        "bra.uni WL%=;\n\t"
        "WD%=:\n\t}"
        :: "r"(a), "r"(par) : "memory");
}
__device__ __forceinline__ void tma3d(uint32_t smem_addr, const CUtensorMap* tm,
                                      int cx, int cy, int cz, uint32_t mbar) {
    asm volatile(
        "cp.async.bulk.tensor.3d.shared::cta.global.tile.mbarrier::complete_tx::bytes "
        "[%0], [%1, {%2, %3, %4}], [%5];"
        :: "r"(smem_addr), "l"(tm), "r"(cx), "r"(cy), "r"(cz), "r"(mbar) : "memory");
}

// ===========================================================================
__global__ void k_init() {
    int i = blockIdx.x * blockDim.x + threadIdx.x;
    if (i < BB * NN) { g_rowsum[i] = 0.f; g_colsum[i] = 0.f; g_diag[i] = 0.f; }
}

// ---------------------------------------------------------------------------
// out[b,o,n] = sum_c W[o,c] * x[b,c,n] + bias[o]   (v projection, fp32 SIMT)
__global__ void __launch_bounds__(256) k_conv(
        const float* __restrict__ W, const float* __restrict__ bias,
        const float* __restrict__ x, float* __restrict__ out, int O) {
    __shared__ float As[16][64];
    __shared__ float Bs[16][64];
    int b = blockIdx.z;
    int n0 = blockIdx.x * 64;
    int o0 = blockIdx.y * 64;
    const float* xb = x + (size_t)b * CC * NN;
    int t = threadIdx.x;
    int tx = t & 15, ty = t >> 4;
    float acc[4][4] = {};
    for (int c0 = 0; c0 < CC; c0 += 16) {
        {
            int o = t >> 2;
            int cq = (t & 3) << 2;
            float4 w4 = *reinterpret_cast<const float4*>(W + (o0 + o) * CC + c0 + cq);
            As[cq + 0][o] = w4.x; As[cq + 1][o] = w4.y;
            As[cq + 2][o] = w4.z; As[cq + 3][o] = w4.w;
            int c = t >> 4;
            int nq = (t & 15) << 2;
            *reinterpret_cast<float4*>(&Bs[c][nq]) =
                *reinterpret_cast<const float4*>(xb + (size_t)(c0 + c) * NN + n0 + nq);
        }
        __syncthreads();
        #pragma unroll
        for (int k = 0; k < 16; k++) {
            float a0 = As[k][ty * 4 + 0], a1 = As[k][ty * 4 + 1];
            float a2 = As[k][ty * 4 + 2], a3 = As[k][ty * 4 + 3];
            float b0 = Bs[k][tx * 4 + 0], b1 = Bs[k][tx * 4 + 1];
            float b2 = Bs[k][tx * 4 + 2], b3 = Bs[k][tx * 4 + 3];
            acc[0][0] += a0 * b0; acc[0][1] += a0 * b1; acc[0][2] += a0 * b2; acc[0][3] += a0 * b3;
            acc[1][0] += a1 * b0; acc[1][1] += a1 * b1; acc[1][2] += a1 * b2; acc[1][3] += a1 * b3;
            acc[2][0] += a2 * b0; acc[2][1] += a2 * b1; acc[2][2] += a2 * b2; acc[2][3] += a2 * b3;
            acc[3][0] += a3 * b0; acc[3][1] += a3 * b1; acc[3][2] += a3 * b2; acc[3][3] += a3 * b3;
        }
        __syncthreads();
    }
    #pragma unroll
    for (int i = 0; i < 4; i++) {
        int o = o0 + ty * 4 + i;
        float bv = bias ? bias[o] : 0.f;
        float4 r;
        r.x = acc[i][0] + bv; r.y = acc[i][1] + bv;
        r.z = acc[i][2] + bv; r.w = acc[i][3] + bv;
        *reinterpret_cast<float4*>(out + ((size_t)b * O + o) * NN + n0 + tx * 4) = r;
    }
}

// ---------------------------------------------------------------------------
// qk projection, written TRANSPOSED [b][n][o] as bf16 hi + residual lo.
// Also accumulates the exact diagonal D[n] = sum_o qk[n,o]^2 (per-row shift).
__global__ void __launch_bounds__(256) k_convq(
        const float* __restrict__ W, const float* __restrict__ x) {
    __shared__ float As[16][64];
    __shared__ float Bs[16][64];
    int b = blockIdx.z;
    int n0 = blockIdx.x * 64;
    const float* xb = x + (size_t)b * CC * NN;
    int t = threadIdx.x;
    int tx = t & 15, ty = t >> 4;
    float acc[4][4] = {};
    for (int c0 = 0; c0 < CC; c0 += 16) {
        {
            int o = t >> 2;
            int cq = (t & 3) << 2;
            float4 w4 = *reinterpret_cast<const float4*>(W + o * CC + c0 + cq);
            As[cq + 0][o] = w4.x; As[cq + 1][o] = w4.y;
            As[cq + 2][o] = w4.z; As[cq + 3][o] = w4.w;
            int c = t >> 4;
            int nq = (t & 15) << 2;
            *reinterpret_cast<float4*>(&Bs[c][nq]) =
                *reinterpret_cast<const float4*>(xb + (size_t)(c0 + c) * NN + n0 + nq);
        }
        __syncthreads();
        #pragma unroll
        for (int k = 0; k < 16; k++) {
            float a0 = As[k][ty * 4 + 0], a1 = As[k][ty * 4 + 1];
            float a2 = As[k][ty * 4 + 2], a3 = As[k][ty * 4 + 3];
            float b0 = Bs[k][tx * 4 + 0], b1 = Bs[k][tx * 4 + 1];
            float b2 = Bs[k][tx * 4 + 2], b3 = Bs[k][tx * 4 + 3];
            acc[0][0] += a0 * b0; acc[0][1] += a0 * b1; acc[0][2] += a0 * b2; acc[0][3] += a0 * b3;
            acc[1][0] += a1 * b0; acc[1][1] += a1 * b1; acc[1][2] += a1 * b2; acc[1][3] += a1 * b3;
            acc[2][0] += a2 * b0; acc[2][1] += a2 * b1; acc[2][2] += a2 * b2; acc[2][3] += a2 * b3;
            acc[3][0] += a3 * b0; acc[3][1] += a3 * b1; acc[3][2] += a3 * b2; acc[3][3] += a3 * b3;
        }
        __syncthreads();
    }
    float sq[4] = {0.f, 0.f, 0.f, 0.f};
    #pragma unroll
    for (int i = 0; i < 4; i++) {
        int o = ty * 4 + i;
        #pragma unroll
        for (int j = 0; j < 4; j++) {
            int n = n0 + tx * 4 + j;
            float v = acc[i][j];
            sq[j] += v * v;
            __nv_bfloat16 h = __float2bfloat16(v);
            size_t off = ((size_t)b * NN + n) * CQ + o;
            g_qkh[off] = h;
            g_qkl[off] = __float2bfloat16(v - __bfloat162float(h));
        }
    }
    #pragma unroll
    for (int j = 0; j < 4; j++)
        atomicAdd(&g_diag[b * NN + n0 + tx * 4 + j], sq[j]);
}

// ---------------------------------------------------------------------------
// Gram via raw mma bf16 3-term split, SYMMETRIC upper-triangle grid, TMA loads.
// Stores fp16 exp(E - D[row]); mirror tiles get the COLUMN shift.
// Tiles (TMA SW128, pitch 128B): Ah@0 Al@16384 Bh@32768 Bl@49152; sD@65536; mbar@66560
#define TP 136
#define GRAM_SMEM 66624
__global__ void __launch_bounds__(256, 2) k_gram_mma(
        const __grid_constant__ CUtensorMap tmQh,
        const __grid_constant__ CUtensorMap tmQl) {
    extern __shared__ __align__(16) char smem[];
    const uint32_t sb = smem_u32(smem);
    int t = threadIdx.x, w = t >> 5, l = t & 31;
    // decode upper-triangle pair (bi <= bj) from blockIdx.x in [0, 528)
    int bi = 0, rem = blockIdx.x;
    while (rem >= 32 - bi) { rem -= 32 - bi; bi++; }
    int bj = bi + rem;
    int n0 = bi * 128;
    int m0 = bj * 128;
    bool mirror = (bi != bj);
    int b = blockIdx.y;
    float* sD = reinterpret_cast<float*>(smem + 65536);   // [0..128) D[n], [128..256) D[m]
    const uint32_t mb0 = sb + 66560, mb1 = sb + 66568;

    if (t == 0) { mbar_init(mb0, 1); mbar_init(mb1, 1); }
    __syncthreads();
    if (t == 0) {
        mbar_expect(mb0, 32768);
        tma3d(sb + 0,     &tmQh, 0, n0, b, mb0);
        tma3d(sb + 32768, &tmQh, 0, m0, b, mb0);
        mbar_expect(mb1, 32768);
        tma3d(sb + 16384, &tmQl, 0, n0, b, mb1);
        tma3d(sb + 49152, &tmQl, 0, m0, b, mb1);
    }
    // stage diagonal shifts
    if (t < 128) sD[t] = g_diag[b * NN + n0 + t];
    else         sD[t] = g_diag[b * NN + m0 + (t - 128)];

    int wn = w & 1;    // n half (64)
    int wm = w >> 1;   // m quarter (32)

    // fragment row/chunk decomposition (pitch 128B, TMA 128B swizzle)
    const int rA = wn * 64 + (l & 15);            // + i*16
    const int u0A = l >> 4;
    const int r7A = rA & 7;
    const int rB = wm * 32 + (l >> 4) * 8 + (l & 7);  // + jj*16
    const int u0B = (l >> 3) & 1;
    const int r7B = rB & 7;
    const uint32_t aRowH = sb + 0     + (uint32_t)rA * 128;
    const uint32_t aRowL = sb + 16384 + (uint32_t)rA * 128;
    const uint32_t bRowH = sb + 32768 + (uint32_t)rB * 128;
    const uint32_t bRowL = sb + 49152 + (uint32_t)rB * 128;

    float acc[4][4][4] = {};

    // Phase 1: hi*hi while lo tiles still loading
    mbar_wait(mb0, 0);
    #pragma unroll
    for (int kk = 0; kk < 4; kk++) {
        uint32_t cA = (uint32_t)(((kk * 2 + u0A) ^ r7A) << 4);
        uint32_t cB = (uint32_t)(((kk * 2 + u0B) ^ r7B) << 4);
        uint32_t a[4][4];
        #pragma unroll
        for (int i = 0; i < 4; i++)
            ldm4(a[i], aRowH + (uint32_t)(i * 2048) + cA);
        uint32_t bf[2][4];
        #pragma unroll
        for (int jj = 0; jj < 2; jj++)
            ldm4(bf[jj], bRowH + (uint32_t)(jj * 2048) + cB);
        #pragma unroll
        for (int i = 0; i < 4; i++)
            #pragma unroll
            for (int j = 0; j < 4; j++)
                mma16816(acc[i][j], a[i], bf[j >> 1][(j & 1) * 2], bf[j >> 1][(j & 1) * 2 + 1]);
    }
    // Phase 2: hi*lo + lo*hi
    mbar_wait(mb1, 0);
    #pragma unroll
    for (int kk = 0; kk < 4; kk++) {
        uint32_t cA = (uint32_t)(((kk * 2 + u0A) ^ r7A) << 4);
        uint32_t cB = (uint32_t)(((kk * 2 + u0B) ^ r7B) << 4);
        uint32_t ah[4][4], al[4][4];
        #pragma unroll
        for (int i = 0; i < 4; i++) {
            ldm4(ah[i], aRowH + (uint32_t)(i * 2048) + cA);
            ldm4(al[i], aRowL + (uint32_t)(i * 2048) + cA);
        }
        uint32_t bh[2][4], bl[2][4];
        #pragma unroll
        for (int jj = 0; jj < 2; jj++) {
            ldm4(bh[jj], bRowH + (uint32_t)(jj * 2048) + cB);
            ldm4(bl[jj], bRowL + (uint32_t)(jj * 2048) + cB);
        }
        #pragma unroll
        for (int i = 0; i < 4; i++)
            #pragma unroll
            for (int j = 0; j < 4; j++) {
                mma16816(acc[i][j], ah[i], bl[j >> 1][(j & 1) * 2], bl[j >> 1][(j & 1) * 2 + 1]);
                mma16816(acc[i][j], al[i], bh[j >> 1][(j & 1) * 2], bh[j >> 1][(j & 1) * 2 + 1]);
            }
    }
    __syncthreads();   // operands dead; smem reusable for transpose staging

    // Epilogue
    __half* oh = g_ah + (size_t)b * NN2;
    __half* smT = reinterpret_cast<__half*>(smem);
    int r0 = l >> 2;
    int cl = 2 * (l & 3);
    float cs[4][2] = {};
    #pragma unroll
    for (int i = 0; i < 4; i++) {
        int lnA = wn * 64 + i * 16 + r0;
        int lnB = lnA + 8;
        int nA = n0 + lnA;
        int nB = n0 + lnB;
        float DnA = sD[lnA], DnB = sD[lnB];
        float rs0 = 0.f, rs1 = 0.f;
        #pragma unroll
        for (int j = 0; j < 4; j++) {
            int ml = wm * 32 + j * 8 + cl;
            int mcol = m0 + ml;
            __half2 h01, h23;
            h01.x = __float2half(__expf(acc[i][j][0] - DnA));
            h01.y = __float2half(__expf(acc[i][j][1] - DnA));
            h23.x = __float2half(__expf(acc[i][j][2] - DnB));
            h23.y = __float2half(__expf(acc[i][j][3] - DnB));
            rs0 += __half2float(h01.x) + __half2float(h01.y);
            rs1 += __half2float(h23.x) + __half2float(h23.y);
            *reinterpret_cast<__half2*>(oh + (size_t)nA * NN + mcol) = h01;
            *reinterpret_cast<__half2*>(oh + (size_t)nB * NN + mcol) = h23;
            if (mirror) {
                float DmA = sD[128 + ml], DmB = sD[128 + ml + 1];
                __half m00 = __float2half(__expf(acc[i][j][0] - DmA));
                __half m01 = __float2half(__expf(acc[i][j][1] - DmB));
                __half m10 = __float2half(__expf(acc[i][j][2] - DmA));
                __half m11 = __float2half(__expf(acc[i][j][3] - DmB));
                cs[j][0] += __half2float(m00) + __half2float(m10);
                cs[j][1] += __half2float(m01) + __half2float(m11);
                smT[(uint32_t)ml * TP + lnA]       = m00;
                smT[(uint32_t)(ml + 1) * TP + lnA] = m01;
                smT[(uint32_t)ml * TP + lnB]       = m10;
                smT[(uint32_t)(ml + 1) * TP + lnB] = m11;
            }
        }
        rs0 += __shfl_xor_sync(0xffffffffu, rs0, 1);
        rs0 += __shfl_xor_sync(0xffffffffu, rs0, 2);
        rs1 += __shfl_xor_sync(0xffffffffu, rs1, 1);
        rs1 += __shfl_xor_sync(0xffffffffu, rs1, 2);
        if ((l & 3) == 0) {
            atomicAdd(&g_rowsum[b * NN + nA], rs0);
            atomicAdd(&g_rowsum[b * NN + nB], rs1);
        }
    }
    if (mirror) {
        // column sums of the COLUMN-shifted values -> rowsum[m]
        #pragma unroll
        for (int j = 0; j < 4; j++) {
            #pragma unroll
            for (int h = 0; h < 2; h++) {
                float v = cs[j][h];
                v += __shfl_xor_sync(0xffffffffu, v, 4);
                v += __shfl_xor_sync(0xffffffffu, v, 8);
                v += __shfl_xor_sync(0xffffffffu, v, 16);
                if (l < 4)
                    atomicAdd(&g_rowsum[b * NN + m0 + wm * 32 + j * 8 + cl + h], v);
            }
        }
        __syncthreads();
        // coalesced copy-out of transposed tile
        int mr = t >> 1, hf = t & 1;
        const float4* srow = reinterpret_cast<const float4*>(smT + (uint32_t)mr * TP + hf * 64);
        float4* drow = reinterpret_cast<float4*>(oh + (size_t)(m0 + mr) * NN + n0 + hf * 64);
        #pragma unroll
        for (int q = 0; q < 8; q++) drow[q] = srow[q];
    }
}

// ---------------------------------------------------------------------------
// colsum[b,m] = sum_n attn[n,m] / rowsum[n]   (half2 loads, 2 cols/thread)
__global__ void __launch_bounds__(256) k_colsum() {
    __shared__ float inv[256];
    int b = blockIdx.z;
    int m = blockIdx.x * 512 + 2 * threadIdx.x;
    int nbase = blockIdx.y * 256;
    inv[threadIdx.x] = 1.0f / g_rowsum[b * NN + nbase + threadIdx.x];
    __syncthreads();
    const __half* ah = g_ah + (size_t)b * NN2;
    float s0 = 0.f, s1 = 0.f;
    #pragma unroll 4
    for (int i = 0; i < 256; i++) {
        __half2 v = *reinterpret_cast<const __half2*>(ah + (size_t)(nbase + i) * NN + m);
        s0 += __half2float(v.x) * inv[i];
        s1 += __half2float(v.y) * inv[i];
    }
    atomicAdd(&g_colsum[b * NN + m], s0);
    atomicAdd(&g_colsum[b * NN + m + 1], s1);
}

// ---------------------------------------------------------------------------
// vs = v/(1e-9+colsum[m]) -> fp16
__global__ void __launch_bounds__(256) k_splitv() {
    size_t i = (size_t)blockIdx.x * 256 + threadIdx.x;
    int m = (int)(i & (NN - 1));
    int b = (int)(i >> 20);
    float vs = g_v[i] / (1e-9f + g_colsum[b * NN + m]);
    g_vh[i] = __float2half(vs);
}

// ---------------------------------------------------------------------------
// x_r raw sums via raw mma fp16, SINGLE term, TMA-staged.
// CTA 128c x 256n, 256 threads (8 warps of 64c x 64n), BK=64, 3-stage pipeline.
// Stage: vs 128 rows @ +0 (16KB), attn 256 rows @ +16384 (32KB) = 49152 B.
#define XSTAGE 49152
#define XR_SMEM (3 * XSTAGE + 64)    // + mbarriers
__global__ void __launch_bounds__(256, 1) k_xr_mma(
        const __grid_constant__ CUtensorMap tmV,
        const __grid_constant__ CUtensorMap tmA) {
    extern __shared__ __align__(16) char smem[];
    const uint32_t sb = smem_u32(smem);
    int t = threadIdx.x, w = t >> 5, l = t & 31;
    int n0 = blockIdx.x * 256;
    int c0 = blockIdx.y * 128;
    int b = blockIdx.z;
    const uint32_t MB = sb + 3 * XSTAGE;

    if (t == 0) { mbar_init(MB, 1); mbar_init(MB + 8, 1); mbar_init(MB + 16, 1); }
    __syncthreads();

    auto issue = [&](int kc) {
        int s = kc % 3;
        uint32_t base = sb + (uint32_t)s * XSTAGE;
        mbar_expect(MB + s * 8, XSTAGE);
        tma3d(base,         &tmV, kc * 64, c0, b, MB + s * 8);
        tma3d(base + 16384, &tmA, kc * 64, n0, b, MB + s * 8);
    };
    if (t == 0) { issue(0); issue(1); issue(2); }

    int wc = w >> 2;   // c half (64)
    int wn = w & 3;    // n quarter (64)

    const int rA = wc * 64 + (l & 15);                // + i*16
    const int u0A = l >> 4;
    const int r7A = rA & 7;
    const int rB = wn * 64 + (l >> 4) * 8 + (l & 7);  // + jj*16
    const int u0B = (l >> 3) & 1;
    const int r7B = rB & 7;
    const uint32_t aRow = (uint32_t)rA * 128;
    const uint32_t bRow = 16384u + (uint32_t)rB * 128;

    float acc[4][8][4] = {};

    for (int kc = 0; kc < 64; kc++) {
        int s = kc % 3;
        mbar_wait(MB + s * 8, (uint32_t)((kc / 3) & 1));
        uint32_t stg = sb + (uint32_t)s * XSTAGE;
        #pragma unroll
        for (int ks = 0; ks < 4; ks++) {
            uint32_t cA = (uint32_t)(((ks * 2 + u0A) ^ r7A) << 4);
            uint32_t cB = (uint32_t)(((ks * 2 + u0B) ^ r7B) << 4);
            uint32_t bf[4][4];
            #pragma unroll
            for (int jj = 0; jj < 4; jj++)
                ldm4(bf[jj], stg + bRow + (uint32_t)(jj * 2048) + cB);
            uint32_t a[4][4];
            #pragma unroll
            for (int i = 0; i < 4; i++)
                ldm4(a[i], stg + aRow + (uint32_t)(i * 2048) + cA);
            #pragma unroll
            for (int i = 0; i < 4; i++)
                #pragma unroll
                for (int j = 0; j < 8; j++)
                    mma16816h(acc[i][j], a[i], bf[j >> 1][(j & 1) * 2], bf[j >> 1][(j & 1) * 2 + 1]);
        }
        __syncthreads();
        if (t == 0 && kc + 3 < 64) issue(kc + 3);
    }

    // Store raw sums (scaled by 1/rowsum later in k_final)
    int r0 = l >> 2;
    int cl = 2 * (l & 3);
    #pragma unroll
    for (int i = 0; i < 4; i++) {
        int cA = c0 + wc * 64 + i * 16 + r0;
        #pragma unroll
        for (int j = 0; j < 8; j++) {
            int ncol = n0 + wn * 64 + j * 8 + cl;
            float2 v01; v01.x = acc[i][j][0]; v01.y = acc[i][j][1];
            float2 v23; v23.x = acc[i][j][2]; v23.y = acc[i][j][3];
            *reinterpret_cast<float2*>(g_xr + ((size_t)b * CC + cA) * NN + ncol) = v01;
            *reinterpret_cast<float2*>(g_xr + ((size_t)b * CC + cA + 8) * NN + ncol) = v23;
        }
    }
}

// ---------------------------------------------------------------------------
// t = wt * (x - xr_raw/rowsum) + bt ; BN inference ; out = x + relu(bn)
__global__ void __launch_bounds__(256) k_final(
        const float* __restrict__ W, const float* __restrict__ bias,
        const float* __restrict__ x,
        const float* __restrict__ gamma, const float* __restrict__ beta,
        const float* __restrict__ mean,  const float* __restrict__ var,
        float* __restrict__ out) {
    __shared__ float As[16][64];
    __shared__ float Bs[16][64];
    __shared__ float invs[64];
    int b = blockIdx.z;
    int n0 = blockIdx.x * 64;
    int o0 = blockIdx.y * 64;
    const float* xb = x + (size_t)b * CC * NN;
    int t = threadIdx.x;
    int tx = t & 15, ty = t >> 4;
    if (t < 64) invs[t] = 1.0f / g_rowsum[b * NN + n0 + t];
    __syncthreads();
    float acc[4][4] = {};
    for (int c0 = 0; c0 < CC; c0 += 16) {
        {
            int o = t >> 2;
            int cq = (t & 3) << 2;
            float4 w4 = *reinterpret_cast<const float4*>(W + (o0 + o) * CC + c0 + cq);
            As[cq + 0][o] = w4.x; As[cq + 1][o] = w4.y;
            As[cq + 2][o] = w4.z; As[cq + 3][o] = w4.w;
            int c = t >> 4;
            int nq = (t & 15) << 2;
            float4 xv = *reinterpret_cast<const float4*>(xb + (size_t)(c0 + c) * NN + n0 + nq);
            float4 rv = *reinterpret_cast<const float4*>(g_xr + ((size_t)b * CC + c0 + c) * NN + n0 + nq);
            Bs[c][nq + 0] = xv.x - rv.x * invs[nq + 0];
            Bs[c][nq + 1] = xv.y - rv.y * invs[nq + 1];
            Bs[c][nq + 2] = xv.z - rv.z * invs[nq + 2];
            Bs[c][nq + 3] = xv.w - rv.w * invs[nq + 3];
        }
        __syncthreads();
        #pragma unroll
        for (int k = 0; k < 16; k++) {
            float a0 = As[k][ty * 4 + 0], a1 = As[k][ty * 4 + 1];
            float a2 = As[k][ty * 4 + 2], a3 = As[k][ty * 4 + 3];
            float b0 = Bs[k][tx * 4 + 0], b1 = Bs[k][tx * 4 + 1];
            float b2 = Bs[k][tx * 4 + 2], b3 = Bs[k][tx * 4 + 3];
            acc[0][0] += a0 * b0; acc[0][1] += a0 * b1; acc[0][2] += a0 * b2; acc[0][3] += a0 * b3;
            acc[1][0] += a1 * b0; acc[1][1] += a1 * b1; acc[1][2] += a1 * b2; acc[1][3] += a1 * b3;
            acc[2][0] += a2 * b0; acc[2][1] += a2 * b1; acc[2][2] += a2 * b2; acc[2][3] += a2 * b3;
            acc[3][0] += a3 * b0; acc[3][1] += a3 * b1; acc[3][2] += a3 * b2; acc[3][3] += a3 * b3;
        }
        __syncthreads();
    }
    #pragma unroll
    for (int i = 0; i < 4; i++) {
        int o = o0 + ty * 4 + i;
        float s  = gamma[o] * rsqrtf(var[o] + BN_EPSF);
        float sh = beta[o] - mean[o] * s;
        float bt = bias[o];
        size_t off = ((size_t)b * CC + o) * NN + n0 + tx * 4;
        float4 xv = *reinterpret_cast<const float4*>(xb + (size_t)o * NN + n0 + tx * 4);
        float4 r;
        r.x = xv.x + fmaxf((acc[i][0] + bt) * s + sh, 0.f);
        r.y = xv.y + fmaxf((acc[i][1] + bt) * s + sh, 0.f);
        r.z = xv.z + fmaxf((acc[i][2] + bt) * s + sh, 0.f);
        r.w = xv.w + fmaxf((acc[i][3] + bt) * s + sh, 0.f);
        *reinterpret_cast<float4*>(out + off) = r;
    }
}

// ---------------------------------------------------------------------------
typedef CUresult (*PFN_tme_v12)(
    CUtensorMap*, CUtensorMapDataType, cuuint32_t, void*,
    const cuuint64_t*, const cuuint64_t*, const cuuint32_t*, const cuuint32_t*,
    CUtensorMapInterleave, CUtensorMapSwizzle, CUtensorMapL2promotion,
    CUtensorMapFloatOOBfill);

static void make_tm(PFN_tme_v12 enc, CUtensorMap* tm, void* ptr,
                    CUtensorMapDataType dt,
                    uint64_t d0, uint64_t d1, uint64_t d2,
                    uint64_t s1, uint64_t s2,
                    uint32_t b0, uint32_t b1) {
    cuuint64_t dims[3] = {d0, d1, d2};
    cuuint64_t strides[2] = {s1, s2};
    cuuint32_t box[3] = {b0, b1, 1};
    cuuint32_t es[3] = {1, 1, 1};
    enc(tm, dt, 3, ptr, dims, strides, box, es,
        CU_TENSOR_MAP_INTERLEAVE_NONE, CU_TENSOR_MAP_SWIZZLE_128B,
        CU_TENSOR_MAP_L2_PROMOTION_L2_128B, CU_TENSOR_MAP_FLOAT_OOB_FILL_NONE);
}

extern "C" void kernel_launch(void* const* d_in, const int* in_sizes, int n_in,
                              void* d_out, int out_size) {
    const float* x     = (const float*)d_in[0];
    const float* wq    = (const float*)d_in[1];
    const float* wv    = (const float*)d_in[2];
    const float* bv    = (const float*)d_in[3];
    const float* wt    = (const float*)d_in[4];
    const float* bt    = (const float*)d_in[5];
    const float* gamma = (const float*)d_in[6];
    const float* beta  = (const float*)d_in[7];
    const float* rmean = (const float*)d_in[8];
    const float* rvar  = (const float*)d_in[9];
    float* out = (float*)d_out;

    float* v_p = nullptr;
    void *qkh_p = nullptr, *qkl_p = nullptr, *vh_p = nullptr, *ah_p = nullptr;
    cudaGetSymbolAddress((void**)&v_p, g_v);
    cudaGetSymbolAddress(&qkh_p, g_qkh);
    cudaGetSymbolAddress(&qkl_p, g_qkl);
    cudaGetSymbolAddress(&vh_p, g_vh);
    cudaGetSymbolAddress(&ah_p, g_ah);

    PFN_tme_v12 enc = nullptr;
    cudaDriverEntryPointQueryResult qr;
    cudaGetDriverEntryPointByVersion("cuTensorMapEncodeTiled", (void**)&enc, 12000,
                                     cudaEnableDefault, &qr);

    CUtensorMap tmQh, tmQl, tmV, tmA;
    make_tm(enc, &tmQh, qkh_p, CU_TENSOR_MAP_DATA_TYPE_BFLOAT16,
            CQ, NN, BB, CQ * 2, (uint64_t)NN * CQ * 2, 64, 128);
    make_tm(enc, &tmQl, qkl_p, CU_TENSOR_MAP_DATA_TYPE_BFLOAT16,
            CQ, NN, BB, CQ * 2, (uint64_t)NN * CQ * 2, 64, 128);
    make_tm(enc, &tmV, vh_p, CU_TENSOR_MAP_DATA_TYPE_FLOAT16,
            NN, CC, BB, NN * 2, (uint64_t)CC * NN * 2, 64, 128);
    make_tm(enc, &tmA, ah_p, CU_TENSOR_MAP_DATA_TYPE_FLOAT16,
            NN, NN, BB, NN * 2, (uint64_t)NN * NN * 2, 64, 256);

    cudaFuncSetAttribute(k_gram_mma, cudaFuncAttributeMaxDynamicSharedMemorySize, GRAM_SMEM);
    cudaFuncSetAttribute(k_xr_mma,   cudaFuncAttributeMaxDynamicSharedMemorySize, XR_SMEM);

    k_init<<<(BB * NN + 255) / 256, 256>>>();
    // qk projection -> bf16 hi/lo + exact diagonal shift D[n]
    k_convq<<<dim3(NN / 64, 1, BB), 256>>>(wq, x);
    // v = wv * x + bv (fp32)
    k_conv<<<dim3(NN / 64, CC / 64, BB), 256>>>(wv, bv, x, v_p, CC);
    // exp(E - D[row]) fp16, symmetric upper-triangle grid, TMA-staged
    k_gram_mma<<<dim3(528, BB), 256, GRAM_SMEM>>>(tmQh, tmQl);
    // colsums of normalized attn
    k_colsum<<<dim3(NN / 512, NN / 256, BB), 256>>>();
    // fold L1 renorm into v -> fp16
    k_splitv<<<(BB * CC * NN) / 256, 256>>>();
    // raw x_r sums via fp16 mma, single term, TMA 3-stage pipeline
    k_xr_mma<<<dim3(NN / 256, CC / 128, BB), 256, XR_SMEM>>>(tmV, tmA);
    // wt conv (x - x_r fused) + BN + relu + residual
    k_final<<<dim3(NN / 64, CC / 64, BB), 256>>>(wt, bt, x, gamma, beta, rmean, rvar, out);
}

// round 17
// speedup vs baseline: 3.8804x; 1.0145x over previous
#include <cuda_runtime.h>
#include <cuda.h>
#include <cuda_bf16.h>
#include <cuda_fp16.h>
#include <cstdint>
#include <math.h>

#define BB 4
#define CC 256
#define CQ 64
#define NN 4096
#define BN_EPSF 1e-5f

static constexpr size_t NN2 = (size_t)NN * NN;

// Scratch (device globals — no allocation allowed)
__device__ __half        g_qk[(size_t)BB * NN * CQ];    // 2 MB  qk fp16 [b][n][o]
__device__ float         g_v[(size_t)BB * CC * NN];     // 16 MB v[b,c,n]
__device__ __half        g_vh[(size_t)BB * CC * NN];    // 8 MB  vs fp16 [b][c][m]
__device__ __half        g_ah[(size_t)BB * NN * NN];    // 134 MB exp(E - D[n]) fp16 [b][n][m]
__device__ float         g_diag[BB * NN];               // exact |qk_n|^2 (per-row shift)
__device__ float         g_rowsum[BB * NN];             // from ROUNDED exp (consistency)
__device__ float         g_colsum[BB * NN];
__device__ float         g_xr[(size_t)BB * CC * NN];    // 16 MB raw x_r sums

// ===========================================================================
__device__ __forceinline__ uint32_t smem_u32(const void* p) {
    uint32_t a;
    asm("{ .reg .u64 t; cvta.to.shared.u64 t, %1; cvt.u32.u64 %0, t; }" : "=r"(a) : "l"(p));
    return a;
}
__device__ __forceinline__ void ldm4(uint32_t* r, uint32_t a) {
    asm volatile("ldmatrix.sync.aligned.m8n8.x4.shared.b16 {%0,%1,%2,%3}, [%4];"
        : "=r"(r[0]), "=r"(r[1]), "=r"(r[2]), "=r"(r[3]) : "r"(a));
}
__device__ __forceinline__ void mma16816h(float* c, const uint32_t* a, uint32_t b0, uint32_t b1) {
    asm volatile("mma.sync.aligned.m16n8k16.row.col.f32.f16.f16.f32 "
        "{%0,%1,%2,%3}, {%4,%5,%6,%7}, {%8,%9}, {%0,%1,%2,%3};"
        : "+f"(c[0]), "+f"(c[1]), "+f"(c[2]), "+f"(c[3])
        : "r"(a[0]), "r"(a[1]), "r"(a[2]), "r"(a[3]), "r"(b0), "r"(b1));
}
__device__ __forceinline__ void mbar_init(uint32_t a, uint32_t cnt) {
    asm volatile("mbarrier.init.shared.b64 [%0], %1;" :: "r"(a), "r"(cnt) : "memory");
}
__device__ __forceinline__ void mbar_expect(uint32_t a, uint32_t bytes) {
    asm volatile("mbarrier.arrive.expect_tx.shared.b64 _, [%0], %1;"
        :: "r"(a), "r"(bytes) : "memory");
}
__device__ __forceinline__ void mbar_wait(uint32_t a, uint32_t par) {
    asm volatile(
        "{\n\t.reg .pred P1;\n\t"
        "WL%=:\n\t"
        "mbarrier.try_wait.parity.acquire.cta.shared::cta.b64 P1, [%0], %1, 0x989680;\n\t"
        "@P1 bra.uni WD%=;\n\t"
        "bra.uni WL%=;\n\t"
        "WD%=:\n\t}"
        :: "r"(a), "r"(par) : "memory");
}
__device__ __forceinline__ void tma3d(uint32_t smem_addr, const CUtensorMap* tm,
                                      int cx, int cy, int cz, uint32_t mbar) {
    asm volatile(
        "cp.async.bulk.tensor.3d.shared::cta.global.tile.mbarrier::complete_tx::bytes "
        "[%0], [%1, {%2, %3, %4}], [%5];"
        :: "r"(smem_addr), "l"(tm), "r"(cx), "r"(cy), "r"(cz), "r"(mbar) : "memory");
}

// ===========================================================================
__global__ void k_init() {
    int i = blockIdx.x * blockDim.x + threadIdx.x;
    if (i < BB * NN) { g_rowsum[i] = 0.f; g_colsum[i] = 0.f; g_diag[i] = 0.f; }
}

// ---------------------------------------------------------------------------
// out[b,o,n] = sum_c W[o,c] * x[b,c,n] + bias[o]   (v projection, fp32 SIMT)
__global__ void __launch_bounds__(256) k_conv(
        const float* __restrict__ W, const float* __restrict__ bias,
        const float* __restrict__ x, float* __restrict__ out, int O) {
    __shared__ float As[16][64];
    __shared__ float Bs[16][64];
    int b = blockIdx.z;
    int n0 = blockIdx.x * 64;
    int o0 = blockIdx.y * 64;
    const float* xb = x + (size_t)b * CC * NN;
    int t = threadIdx.x;
    int tx = t & 15, ty = t >> 4;
    float acc[4][4] = {};
    for (int c0 = 0; c0 < CC; c0 += 16) {
        {
            int o = t >> 2;
            int cq = (t & 3) << 2;
            float4 w4 = *reinterpret_cast<const float4*>(W + (o0 + o) * CC + c0 + cq);
            As[cq + 0][o] = w4.x; As[cq + 1][o] = w4.y;
            As[cq + 2][o] = w4.z; As[cq + 3][o] = w4.w;
            int c = t >> 4;
            int nq = (t & 15) << 2;
            *reinterpret_cast<float4*>(&Bs[c][nq]) =
                *reinterpret_cast<const float4*>(xb + (size_t)(c0 + c) * NN + n0 + nq);
        }
        __syncthreads();
        #pragma unroll
        for (int k = 0; k < 16; k++) {
            float a0 = As[k][ty * 4 + 0], a1 = As[k][ty * 4 + 1];
            float a2 = As[k][ty * 4 + 2], a3 = As[k][ty * 4 + 3];
            float b0 = Bs[k][tx * 4 + 0], b1 = Bs[k][tx * 4 + 1];
            float b2 = Bs[k][tx * 4 + 2], b3 = Bs[k][tx * 4 + 3];
            acc[0][0] += a0 * b0; acc[0][1] += a0 * b1; acc[0][2] += a0 * b2; acc[0][3] += a0 * b3;
            acc[1][0] += a1 * b0; acc[1][1] += a1 * b1; acc[1][2] += a1 * b2; acc[1][3] += a1 * b3;
            acc[2][0] += a2 * b0; acc[2][1] += a2 * b1; acc[2][2] += a2 * b2; acc[2][3] += a2 * b3;
            acc[3][0] += a3 * b0; acc[3][1] += a3 * b1; acc[3][2] += a3 * b2; acc[3][3] += a3 * b3;
        }
        __syncthreads();
    }
    #pragma unroll
    for (int i = 0; i < 4; i++) {
        int o = o0 + ty * 4 + i;
        float bv = bias ? bias[o] : 0.f;
        float4 r;
        r.x = acc[i][0] + bv; r.y = acc[i][1] + bv;
        r.z = acc[i][2] + bv; r.w = acc[i][3] + bv;
        *reinterpret_cast<float4*>(out + ((size_t)b * O + o) * NN + n0 + tx * 4) = r;
    }
}

// ---------------------------------------------------------------------------
// qk projection, written TRANSPOSED [b][n][o] as fp16 (single term).
// Also accumulates the exact diagonal D[n] = sum_o qk[n,o]^2 (per-row shift).
__global__ void __launch_bounds__(256) k_convq(
        const float* __restrict__ W, const float* __restrict__ x) {
    __shared__ float As[16][64];
    __shared__ float Bs[16][64];
    int b = blockIdx.z;
    int n0 = blockIdx.x * 64;
    const float* xb = x + (size_t)b * CC * NN;
    int t = threadIdx.x;
    int tx = t & 15, ty = t >> 4;
    float acc[4][4] = {};
    for (int c0 = 0; c0 < CC; c0 += 16) {
        {
            int o = t >> 2;
            int cq = (t & 3) << 2;
            float4 w4 = *reinterpret_cast<const float4*>(W + o * CC + c0 + cq);
            As[cq + 0][o] = w4.x; As[cq + 1][o] = w4.y;
            As[cq + 2][o] = w4.z; As[cq + 3][o] = w4.w;
            int c = t >> 4;
            int nq = (t & 15) << 2;
            *reinterpret_cast<float4*>(&Bs[c][nq]) =
                *reinterpret_cast<const float4*>(xb + (size_t)(c0 + c) * NN + n0 + nq);
        }
        __syncthreads();
        #pragma unroll
        for (int k = 0; k < 16; k++) {
            float a0 = As[k][ty * 4 + 0], a1 = As[k][ty * 4 + 1];
            float a2 = As[k][ty * 4 + 2], a3 = As[k][ty * 4 + 3];
            float b0 = Bs[k][tx * 4 + 0], b1 = Bs[k][tx * 4 + 1];
            float b2 = Bs[k][tx * 4 + 2], b3 = Bs[k][tx * 4 + 3];
            acc[0][0] += a0 * b0; acc[0][1] += a0 * b1; acc[0][2] += a0 * b2; acc[0][3] += a0 * b3;
            acc[1][0] += a1 * b0; acc[1][1] += a1 * b1; acc[1][2] += a1 * b2; acc[1][3] += a1 * b3;
            acc[2][0] += a2 * b0; acc[2][1] += a2 * b1; acc[2][2] += a2 * b2; acc[2][3] += a2 * b3;
            acc[3][0] += a3 * b0; acc[3][1] += a3 * b1; acc[3][2] += a3 * b2; acc[3][3] += a3 * b3;
        }
        __syncthreads();
    }
    float sq[4] = {0.f, 0.f, 0.f, 0.f};
    #pragma unroll
    for (int i = 0; i < 4; i++) {
        int o = ty * 4 + i;
        #pragma unroll
        for (int j = 0; j < 4; j++) {
            int n = n0 + tx * 4 + j;
            float v = acc[i][j];
            sq[j] += v * v;
            g_qk[((size_t)b * NN + n) * CQ + o] = __float2half(v);
        }
    }
    #pragma unroll
    for (int j = 0; j < 4; j++)
        atomicAdd(&g_diag[b * NN + n0 + tx * 4 + j], sq[j]);
}

// ---------------------------------------------------------------------------
// Gram via single fp16 mma, SYMMETRIC upper-triangle grid, TMA loads.
// Stores fp16 exp(E - D[row]); mirror tiles get the COLUMN shift via factored
// ratio exps: exp(E-Dm) = exp(E-Dn) * exp(Dn-41) * exp(41-Dm).
// smem: A@0 (16KB) B@16384 (16KB) | smT reuse @0 (34816) | sD@34816 | mbar@35840
#define TP 136
#define GRAM_SMEM 35904
__global__ void __launch_bounds__(256, 2) k_gram_mma(
        const __grid_constant__ CUtensorMap tmQ) {
    extern __shared__ __align__(16) char smem[];
    const uint32_t sb = smem_u32(smem);
    int t = threadIdx.x, w = t >> 5, l = t & 31;
    // decode upper-triangle pair (bi <= bj) from blockIdx.x in [0, 528)
    int bi = 0, rem = blockIdx.x;
    while (rem >= 32 - bi) { rem -= 32 - bi; bi++; }
    int bj = bi + rem;
    int n0 = bi * 128;
    int m0 = bj * 128;
    bool mirror = (bi != bj);
    int b = blockIdx.y;
    float* sD = reinterpret_cast<float*>(smem + 34816);   // [0..128) D[n], [128..256) D[m]
    const uint32_t mb0 = sb + 35840;

    if (t == 0) mbar_init(mb0, 1);
    __syncthreads();
    if (t == 0) {
        mbar_expect(mb0, 32768);
        tma3d(sb + 0,     &tmQ, 0, n0, b, mb0);
        tma3d(sb + 16384, &tmQ, 0, m0, b, mb0);
    }
    // stage diagonal shifts
    if (t < 128) sD[t] = g_diag[b * NN + n0 + t];
    else         sD[t] = g_diag[b * NN + m0 + (t - 128)];

    int wn = w & 1;    // n half (64)
    int wm = w >> 1;   // m quarter (32)

    // fragment row/chunk decomposition (pitch 128B, TMA 128B swizzle)
    const int rA = wn * 64 + (l & 15);
    const int u0A = l >> 4;
    const int r7A = rA & 7;
    const int rB = wm * 32 + (l >> 4) * 8 + (l & 7);
    const int u0B = (l >> 3) & 1;
    const int r7B = rB & 7;
    const uint32_t aRow = sb + 0     + (uint32_t)rA * 128;
    const uint32_t bRow = sb + 16384 + (uint32_t)rB * 128;

    float acc[4][4][4] = {};

    mbar_wait(mb0, 0);
    #pragma unroll
    for (int kk = 0; kk < 4; kk++) {
        uint32_t cA = (uint32_t)(((kk * 2 + u0A) ^ r7A) << 4);
        uint32_t cB = (uint32_t)(((kk * 2 + u0B) ^ r7B) << 4);
        uint32_t a[4][4];
        #pragma unroll
        for (int i = 0; i < 4; i++)
            ldm4(a[i], aRow + (uint32_t)(i * 2048) + cA);
        uint32_t bf[2][4];
        #pragma unroll
        for (int jj = 0; jj < 2; jj++)
            ldm4(bf[jj], bRow + (uint32_t)(jj * 2048) + cB);
        #pragma unroll
        for (int i = 0; i < 4; i++)
            #pragma unroll
            for (int j = 0; j < 4; j++)
                mma16816h(acc[i][j], a[i], bf[j >> 1][(j & 1) * 2], bf[j >> 1][(j & 1) * 2 + 1]);
    }
    __syncthreads();   // operands dead; smem reusable for transpose staging; sD coherent

    // Epilogue
    __half* oh = g_ah + (size_t)b * NN2;
    __half* smT = reinterpret_cast<__half*>(smem);
    int r0 = l >> 2;
    int cl = 2 * (l & 3);
    float pn[4][2], pmi[4][2];
    if (mirror) {
        #pragma unroll
        for (int i = 0; i < 4; i++) {
            int lnA = wn * 64 + i * 16 + r0;
            pn[i][0] = __expf(sD[lnA] - 41.0f);
            pn[i][1] = __expf(sD[lnA + 8] - 41.0f);
        }
        #pragma unroll
        for (int j = 0; j < 4; j++) {
            int ml = wm * 32 + j * 8 + cl;
            pmi[j][0] = __expf(41.0f - sD[128 + ml]);
            pmi[j][1] = __expf(41.0f - sD[128 + ml + 1]);
        }
    }
    float cs[4][2] = {};
    #pragma unroll
    for (int i = 0; i < 4; i++) {
        int lnA = wn * 64 + i * 16 + r0;
        int lnB = lnA + 8;
        int nA = n0 + lnA;
        int nB = n0 + lnB;
        float DnA = sD[lnA], DnB = sD[lnB];
        float rs0 = 0.f, rs1 = 0.f;
        #pragma unroll
        for (int j = 0; j < 4; j++) {
            int ml = wm * 32 + j * 8 + cl;
            int mcol = m0 + ml;
            float e0 = __expf(acc[i][j][0] - DnA);
            float e1 = __expf(acc[i][j][1] - DnA);
            float e2 = __expf(acc[i][j][2] - DnB);
            float e3 = __expf(acc[i][j][3] - DnB);
            __half2 h01, h23;
            h01.x = __float2half(e0); h01.y = __float2half(e1);
            h23.x = __float2half(e2); h23.y = __float2half(e3);
            rs0 += __half2float(h01.x) + __half2float(h01.y);
            rs1 += __half2float(h23.x) + __half2float(h23.y);
            *reinterpret_cast<__half2*>(oh + (size_t)nA * NN + mcol) = h01;
            *reinterpret_cast<__half2*>(oh + (size_t)nB * NN + mcol) = h23;
            if (mirror) {
                __half m00 = __float2half(e0 * pn[i][0] * pmi[j][0]);
                __half m01 = __float2half(e1 * pn[i][0] * pmi[j][1]);
                __half m10 = __float2half(e2 * pn[i][1] * pmi[j][0]);
                __half m11 = __float2half(e3 * pn[i][1] * pmi[j][1]);
                cs[j][0] += __half2float(m00) + __half2float(m10);
                cs[j][1] += __half2float(m01) + __half2float(m11);
                smT[(uint32_t)ml * TP + lnA]       = m00;
                smT[(uint32_t)(ml + 1) * TP + lnA] = m01;
                smT[(uint32_t)ml * TP + lnB]       = m10;
                smT[(uint32_t)(ml + 1) * TP + lnB] = m11;
            }
        }
        rs0 += __shfl_xor_sync(0xffffffffu, rs0, 1);
        rs0 += __shfl_xor_sync(0xffffffffu, rs0, 2);
        rs1 += __shfl_xor_sync(0xffffffffu, rs1, 1);
        rs1 += __shfl_xor_sync(0xffffffffu, rs1, 2);
        if ((l & 3) == 0) {
            atomicAdd(&g_rowsum[b * NN + nA], rs0);
            atomicAdd(&g_rowsum[b * NN + nB], rs1);
        }
    }
    if (mirror) {
        // column sums of the COLUMN-shifted rounded values -> rowsum[m]
        #pragma unroll
        for (int j = 0; j < 4; j++) {
            #pragma unroll
            for (int h = 0; h < 2; h++) {
                float v = cs[j][h];
                v += __shfl_xor_sync(0xffffffffu, v, 4);
                v += __shfl_xor_sync(0xffffffffu, v, 8);
                v += __shfl_xor_sync(0xffffffffu, v, 16);
                if (l < 4)
                    atomicAdd(&g_rowsum[b * NN + m0 + wm * 32 + j * 8 + cl + h], v);
            }
        }
        __syncthreads();
        // coalesced copy-out of transposed tile
        int mr = t >> 1, hf = t & 1;
        const float4* srow = reinterpret_cast<const float4*>(smT + (uint32_t)mr * TP + hf * 64);
        float4* drow = reinterpret_cast<float4*>(oh + (size_t)(m0 + mr) * NN + n0 + hf * 64);
        #pragma unroll
        for (int q = 0; q < 8; q++) drow[q] = srow[q];
    }
}

// ---------------------------------------------------------------------------
// colsum[b,m] = sum_n attn[n,m] / rowsum[n]   (float4 = 8 cols/thread)
__global__ void __launch_bounds__(256) k_colsum() {
    __shared__ float inv[256];
    int b = blockIdx.z;
    int m0 = blockIdx.x * 2048 + threadIdx.x * 8;
    int nbase = blockIdx.y * 256;
    inv[threadIdx.x] = 1.0f / g_rowsum[b * NN + nbase + threadIdx.x];
    __syncthreads();
    const __half* ah = g_ah + (size_t)b * NN2 + (size_t)nbase * NN + m0;
    float s[8] = {};
    #pragma unroll 8
    for (int i = 0; i < 256; i++) {
        float4 v4 = *reinterpret_cast<const float4*>(ah + (size_t)i * NN);
        __half2 p0 = *reinterpret_cast<__half2*>(&v4.x);
        __half2 p1 = *reinterpret_cast<__half2*>(&v4.y);
        __half2 p2 = *reinterpret_cast<__half2*>(&v4.z);
        __half2 p3 = *reinterpret_cast<__half2*>(&v4.w);
        float wgt = inv[i];
        s[0] += __half2float(p0.x) * wgt; s[1] += __half2float(p0.y) * wgt;
        s[2] += __half2float(p1.x) * wgt; s[3] += __half2float(p1.y) * wgt;
        s[4] += __half2float(p2.x) * wgt; s[5] += __half2float(p2.y) * wgt;
        s[6] += __half2float(p3.x) * wgt; s[7] += __half2float(p3.y) * wgt;
    }
    #pragma unroll
    for (int k = 0; k < 8; k++)
        atomicAdd(&g_colsum[b * NN + m0 + k], s[k]);
}

// ---------------------------------------------------------------------------
// vs = v/(1e-9+colsum[m]) -> fp16
__global__ void __launch_bounds__(256) k_splitv() {
    size_t i = (size_t)blockIdx.x * 256 + threadIdx.x;
    int m = (int)(i & (NN - 1));
    int b = (int)(i >> 20);
    float vs = g_v[i] / (1e-9f + g_colsum[b * NN + m]);
    g_vh[i] = __float2half(vs);
}

// ---------------------------------------------------------------------------
// x_r raw sums via raw mma fp16, SINGLE term, TMA-staged, 4-stage pipeline.
// CTA 128c x 256n, 256 threads (8 warps of 64c x 64n), BK=64.
// Stage: vs 128 rows @ +0 (16KB), attn 256 rows @ +16384 (32KB) = 49152 B.
#define XSTAGE 49152
#define XR_SMEM (4 * XSTAGE + 64)    // + mbarriers
__global__ void __launch_bounds__(256, 1) k_xr_mma(
        const __grid_constant__ CUtensorMap tmV,
        const __grid_constant__ CUtensorMap tmA) {
    extern __shared__ __align__(16) char smem[];
    const uint32_t sb = smem_u32(smem);
    int t = threadIdx.x, w = t >> 5, l = t & 31;
    int n0 = blockIdx.x * 256;
    int c0 = blockIdx.y * 128;
    int b = blockIdx.z;
    const uint32_t MB = sb + 4 * XSTAGE;

    if (t == 0) {
        mbar_init(MB, 1); mbar_init(MB + 8, 1);
        mbar_init(MB + 16, 1); mbar_init(MB + 24, 1);
    }
    __syncthreads();

    auto issue = [&](int kc) {
        int s = kc & 3;
        uint32_t base = sb + (uint32_t)s * XSTAGE;
        mbar_expect(MB + s * 8, XSTAGE);
        tma3d(base,         &tmV, kc * 64, c0, b, MB + s * 8);
        tma3d(base + 16384, &tmA, kc * 64, n0, b, MB + s * 8);
    };
    if (t == 0) { issue(0); issue(1); issue(2); issue(3); }

    int wc = w >> 2;   // c half (64)
    int wn = w & 3;    // n quarter (64)

    const int rA = wc * 64 + (l & 15);
    const int u0A = l >> 4;
    const int r7A = rA & 7;
    const int rB = wn * 64 + (l >> 4) * 8 + (l & 7);
    const int u0B = (l >> 3) & 1;
    const int r7B = rB & 7;
    const uint32_t aRow = (uint32_t)rA * 128;
    const uint32_t bRow = 16384u + (uint32_t)rB * 128;

    float acc[4][8][4] = {};

    for (int kc = 0; kc < 64; kc++) {
        int s = kc & 3;
        mbar_wait(MB + s * 8, (uint32_t)((kc >> 2) & 1));
        uint32_t stg = sb + (uint32_t)s * XSTAGE;
        #pragma unroll
        for (int ks = 0; ks < 4; ks++) {
            uint32_t cA = (uint32_t)(((ks * 2 + u0A) ^ r7A) << 4);
            uint32_t cB = (uint32_t)(((ks * 2 + u0B) ^ r7B) << 4);
            uint32_t bf[4][4];
            #pragma unroll
            for (int jj = 0; jj < 4; jj++)
                ldm4(bf[jj], stg + bRow + (uint32_t)(jj * 2048) + cB);
            uint32_t a[4][4];
            #pragma unroll
            for (int i = 0; i < 4; i++)
                ldm4(a[i], stg + aRow + (uint32_t)(i * 2048) + cA);
            #pragma unroll
            for (int i = 0; i < 4; i++)
                #pragma unroll
                for (int j = 0; j < 8; j++)
                    mma16816h(acc[i][j], a[i], bf[j >> 1][(j & 1) * 2], bf[j >> 1][(j & 1) * 2 + 1]);
        }
        __syncthreads();
        if (t == 0 && kc + 4 < 64) issue(kc + 4);
    }

    // Store raw sums (scaled by 1/rowsum later in k_final)
    int r0 = l >> 2;
    int cl = 2 * (l & 3);
    #pragma unroll
    for (int i = 0; i < 4; i++) {
        int cA = c0 + wc * 64 + i * 16 + r0;
        #pragma unroll
        for (int j = 0; j < 8; j++) {
            int ncol = n0 + wn * 64 + j * 8 + cl;
            float2 v01; v01.x = acc[i][j][0]; v01.y = acc[i][j][1];
            float2 v23; v23.x = acc[i][j][2]; v23.y = acc[i][j][3];
            *reinterpret_cast<float2*>(g_xr + ((size_t)b * CC + cA) * NN + ncol) = v01;
            *reinterpret_cast<float2*>(g_xr + ((size_t)b * CC + cA + 8) * NN + ncol) = v23;
        }
    }
}

// ---------------------------------------------------------------------------
// t = wt * (x - xr_raw/rowsum) + bt ; BN inference ; out = x + relu(bn)
__global__ void __launch_bounds__(256) k_final(
        const float* __restrict__ W, const float* __restrict__ bias,
        const float* __restrict__ x,
        const float* __restrict__ gamma, const float* __restrict__ beta,
        const float* __restrict__ mean,  const float* __restrict__ var,
        float* __restrict__ out) {
    __shared__ float As[16][64];
    __shared__ float Bs[16][64];
    __shared__ float invs[64];
    int b = blockIdx.z;
    int n0 = blockIdx.x * 64;
    int o0 = blockIdx.y * 64;
    const float* xb = x + (size_t)b * CC * NN;
    int t = threadIdx.x;
    int tx = t & 15, ty = t >> 4;
    if (t < 64) invs[t] = 1.0f / g_rowsum[b * NN + n0 + t];
    __syncthreads();
    float acc[4][4] = {};
    for (int c0 = 0; c0 < CC; c0 += 16) {
        {
            int o = t >> 2;
            int cq = (t & 3) << 2;
            float4 w4 = *reinterpret_cast<const float4*>(W + (o0 + o) * CC + c0 + cq);
            As[cq + 0][o] = w4.x; As[cq + 1][o] = w4.y;
            As[cq + 2][o] = w4.z; As[cq + 3][o] = w4.w;
            int c = t >> 4;
            int nq = (t & 15) << 2;
            float4 xv = *reinterpret_cast<const float4*>(xb + (size_t)(c0 + c) * NN + n0 + nq);
            float4 rv = *reinterpret_cast<const float4*>(g_xr + ((size_t)b * CC + c0 + c) * NN + n0 + nq);
            Bs[c][nq + 0] = xv.x - rv.x * invs[nq + 0];
            Bs[c][nq + 1] = xv.y - rv.y * invs[nq + 1];
            Bs[c][nq + 2] = xv.z - rv.z * invs[nq + 2];
            Bs[c][nq + 3] = xv.w - rv.w * invs[nq + 3];
        }
        __syncthreads();
        #pragma unroll
        for (int k = 0; k < 16; k++) {
            float a0 = As[k][ty * 4 + 0], a1 = As[k][ty * 4 + 1];
            float a2 = As[k][ty * 4 + 2], a3 = As[k][ty * 4 + 3];
            float b0 = Bs[k][tx * 4 + 0], b1 = Bs[k][tx * 4 + 1];
            float b2 = Bs[k][tx * 4 + 2], b3 = Bs[k][tx * 4 + 3];
            acc[0][0] += a0 * b0; acc[0][1] += a0 * b1; acc[0][2] += a0 * b2; acc[0][3] += a0 * b3;
            acc[1][0] += a1 * b0; acc[1][1] += a1 * b1; acc[1][2] += a1 * b2; acc[1][3] += a1 * b3;
            acc[2][0] += a2 * b0; acc[2][1] += a2 * b1; acc[2][2] += a2 * b2; acc[2][3] += a2 * b3;
            acc[3][0] += a3 * b0; acc[3][1] += a3 * b1; acc[3][2] += a3 * b2; acc[3][3] += a3 * b3;
        }
        __syncthreads();
    }
    #pragma unroll
    for (int i = 0; i < 4; i++) {
        int o = o0 + ty * 4 + i;
        float s  = gamma[o] * rsqrtf(var[o] + BN_EPSF);
        float sh = beta[o] - mean[o] * s;
        float bt = bias[o];
        size_t off = ((size_t)b * CC + o) * NN + n0 + tx * 4;
        float4 xv = *reinterpret_cast<const float4*>(xb + (size_t)o * NN + n0 + tx * 4);
        float4 r;
        r.x = xv.x + fmaxf((acc[i][0] + bt) * s + sh, 0.f);
        r.y = xv.y + fmaxf((acc[i][1] + bt) * s + sh, 0.f);
        r.z = xv.z + fmaxf((acc[i][2] + bt) * s + sh, 0.f);
        r.w = xv.w + fmaxf((acc[i][3] + bt) * s + sh, 0.f);
        *reinterpret_cast<float4*>(out + off) = r;
    }
}

// ---------------------------------------------------------------------------
typedef CUresult (*PFN_tme_v12)(
    CUtensorMap*, CUtensorMapDataType, cuuint32_t, void*,
    const cuuint64_t*, const cuuint64_t*, const cuuint32_t*, const cuuint32_t*,
    CUtensorMapInterleave, CUtensorMapSwizzle, CUtensorMapL2promotion,
    CUtensorMapFloatOOBfill);

static void make_tm(PFN_tme_v12 enc, CUtensorMap* tm, void* ptr,
                    CUtensorMapDataType dt,
                    uint64_t d0, uint64_t d1, uint64_t d2,
                    uint64_t s1, uint64_t s2,
                    uint32_t b0, uint32_t b1) {
    cuuint64_t dims[3] = {d0, d1, d2};
    cuuint64_t strides[2] = {s1, s2};
    cuuint32_t box[3] = {b0, b1, 1};
    cuuint32_t es[3] = {1, 1, 1};
    enc(tm, dt, 3, ptr, dims, strides, box, es,
        CU_TENSOR_MAP_INTERLEAVE_NONE, CU_TENSOR_MAP_SWIZZLE_128B,
        CU_TENSOR_MAP_L2_PROMOTION_L2_128B, CU_TENSOR_MAP_FLOAT_OOB_FILL_NONE);
}

extern "C" void kernel_launch(void* const* d_in, const int* in_sizes, int n_in,
                              void* d_out, int out_size) {
    const float* x     = (const float*)d_in[0];
    const float* wq    = (const float*)d_in[1];
    const float* wv    = (const float*)d_in[2];
    const float* bv    = (const float*)d_in[3];
    const float* wt    = (const float*)d_in[4];
    const float* bt    = (const float*)d_in[5];
    const float* gamma = (const float*)d_in[6];
    const float* beta  = (const float*)d_in[7];
    const float* rmean = (const float*)d_in[8];
    const float* rvar  = (const float*)d_in[9];
    float* out = (float*)d_out;

    float* v_p = nullptr;
    void *qk_p = nullptr, *vh_p = nullptr, *ah_p = nullptr;
    cudaGetSymbolAddress((void**)&v_p, g_v);
    cudaGetSymbolAddress(&qk_p, g_qk);
    cudaGetSymbolAddress(&vh_p, g_vh);
    cudaGetSymbolAddress(&ah_p, g_ah);

    PFN_tme_v12 enc = nullptr;
    cudaDriverEntryPointQueryResult qr;
    cudaGetDriverEntryPointByVersion("cuTensorMapEncodeTiled", (void**)&enc, 12000,
                                     cudaEnableDefault, &qr);

    CUtensorMap tmQ, tmV, tmA;
    make_tm(enc, &tmQ, qk_p, CU_TENSOR_MAP_DATA_TYPE_FLOAT16,
            CQ, NN, BB, CQ * 2, (uint64_t)NN * CQ * 2, 64, 128);
    make_tm(enc, &tmV, vh_p, CU_TENSOR_MAP_DATA_TYPE_FLOAT16,
            NN, CC, BB, NN * 2, (uint64_t)CC * NN * 2, 64, 128);
    make_tm(enc, &tmA, ah_p, CU_TENSOR_MAP_DATA_TYPE_FLOAT16,
            NN, NN, BB, NN * 2, (uint64_t)NN * NN * 2, 64, 256);

    cudaFuncSetAttribute(k_gram_mma, cudaFuncAttributeMaxDynamicSharedMemorySize, GRAM_SMEM);
    cudaFuncSetAttribute(k_xr_mma,   cudaFuncAttributeMaxDynamicSharedMemorySize, XR_SMEM);

    k_init<<<(BB * NN + 255) / 256, 256>>>();
    // qk projection -> fp16 + exact diagonal shift D[n]
    k_convq<<<dim3(NN / 64, 1, BB), 256>>>(wq, x);
    // v = wv * x + bv (fp32)
    k_conv<<<dim3(NN / 64, CC / 64, BB), 256>>>(wv, bv, x, v_p, CC);
    // exp(E - D[row]) fp16, single-term fp16 mma, symmetric grid, TMA
    k_gram_mma<<<dim3(528, BB), 256, GRAM_SMEM>>>(tmQ);
    // colsums of normalized attn (8 cols/thread)
    k_colsum<<<dim3(2, 16, BB), 256>>>();
    // fold L1 renorm into v -> fp16
    k_splitv<<<(BB * CC * NN) / 256, 256>>>();
    // raw x_r sums via fp16 mma, single term, TMA 4-stage pipeline
    k_xr_mma<<<dim3(NN / 256, CC / 128, BB), 256, XR_SMEM>>>(tmV, tmA);
    // wt conv (x - x_r fused) + BN + relu + residual
    k_final<<<dim3(NN / 64, CC / 64, BB), 256>>>(wt, bt, x, gamma, beta, rmean, rvar, out);
}